// round 12
// baseline (speedup 1.0000x reference)
#include <cuda_runtime.h>
#include <cuda_bf16.h>
#include <math.h>

#define CDIV(a,b) (((a)+(b)-1)/(b))

// ---------------- problem dims ----------------
constexpr int kBS = 16, kN = 64;
constexpr int kB1 = kBS * kN;              // 1024 sequences
constexpr int kTC = 72, kBP = kBS * kTC;   // 1152 graph batches

// ---------------- scratch ----------------
__device__ __align__(16) uint2 g_xi [(size_t)kB1 * 256 * 32];   // [bn][s][p<32]
__device__ float g_c1[(size_t)kB1 * 256 * 256];
__device__ __align__(16) uint2 g_p1i[(size_t)kB1 * 129 * 128];
__device__ float g_c2[(size_t)kB1 * 131 * 128];
__device__ __align__(16) uint2 g_p2i[(size_t)kB1 * 66 * 64];
__device__ float g_c3[(size_t)kB1 * 70 * 256];
__device__ __align__(16) uint2 g_p3i[(size_t)kB1 * 4608];       // [bn][pair<4608]
__device__ __align__(16) uint2 g_nfi[(size_t)kBP * 64 * 64];    // [bp][n][pair<64]
__device__ float g_oo[(size_t)kBP * 64 * 64];
__device__ float g_mean[256];
__device__ float g_istd[256];
__device__ double g_psS[(size_t)256 * 4096];
__device__ double g_psQ[(size_t)256 * 4096];
__device__ __align__(16) uint2 g_w1i[3 * 256 * 32];
__device__ __align__(16) uint2 g_w2i[3 * 128 * 128];
__device__ __align__(16) uint2 g_w3i[3 * 256 * 64];
__device__ __align__(16) uint2 g_mwi[128 * 64];                 // mapW [out][pair]
__device__ __align__(16) uint2 g_ti [64 * 64];                  // theta [out][pair]

// ---------------- helpers ----------------
__device__ __forceinline__ void mma16816(float* c, const unsigned* a,
                                         unsigned b0, unsigned b1) {
    asm volatile(
        "mma.sync.aligned.m16n8k16.row.col.f32.bf16.bf16.f32 "
        "{%0,%1,%2,%3}, {%4,%5,%6,%7}, {%8,%9}, {%0,%1,%2,%3};"
        : "+f"(c[0]), "+f"(c[1]), "+f"(c[2]), "+f"(c[3])
        : "r"(a[0]), "r"(a[1]), "r"(a[2]), "r"(a[3]), "r"(b0), "r"(b1));
}

__device__ __forceinline__ uint2 pack_hl(float v0, float v1) {
    __nv_bfloat16 h0 = __float2bfloat16(v0);
    __nv_bfloat16 h1 = __float2bfloat16(v1);
    __nv_bfloat16 l0 = __float2bfloat16(v0 - __bfloat162float(h0));
    __nv_bfloat16 l1 = __float2bfloat16(v1 - __bfloat162float(h1));
    uint2 r;
    r.x = (unsigned)__bfloat16_as_ushort(h0) | ((unsigned)__bfloat16_as_ushort(h1) << 16);
    r.y = (unsigned)__bfloat16_as_ushort(l0) | ((unsigned)__bfloat16_as_ushort(l1) << 16);
    return r;
}

__device__ __forceinline__ void cp16(unsigned dst, const void* src, bool full) {
    int sz = full ? 16 : 0;
    asm volatile("cp.async.ca.shared.global [%0], [%1], 16, %2;"
                 :: "r"(dst), "l"(src), "r"(sz));
}
#define CP_COMMIT() asm volatile("cp.async.commit_group;")

// ---------------- prep: x[b,s,n,d] -> xi [bn][s][p], 16B vectorized ----------
__global__ void prep_x_k(const float* __restrict__ x, uint2* __restrict__ XI) {
    size_t idx = (size_t)blockIdx.x * 256 + threadIdx.x;
    if (idx >= (size_t)kB1 * 256 * 16) return;
    int q = idx & 15;
    int s = (idx >> 4) & 255;
    int bn = idx >> 12;
    int b = bn >> 6, n = bn & 63;
    float4 v = *(const float4*)&x[(((size_t)(b * 256 + s)) * 64 + n) * 64 + 4 * q];
    uint2 p01 = pack_hl(v.x, v.y);
    uint2 p23 = pack_hl(v.z, v.w);
    ((uint4*)XI)[idx] = make_uint4(p01.x, p01.y, p23.x, p23.y);
}

// ---------------- weight prep: W[co][ci][k] -> WI[k][co][p] ----------------
__global__ void prep_w_k(const float* __restrict__ W, uint2* __restrict__ WI,
                         int COUT, int CIN) {
    int idx = blockIdx.x * 256 + threadIdx.x;
    if (idx >= COUT * CIN / 2 * 3) return;
    int P = CIN / 2;
    int p = idx % P;
    int co = (idx / P) % COUT;
    int k = idx / (P * COUT);
    float v0 = W[((size_t)co * CIN + 2 * p) * 3 + k];
    float v1 = W[((size_t)co * CIN + 2 * p + 1) * 3 + k];
    WI[idx] = pack_hl(v0, v1);
}

// ---------------- graph weight prep: W[out][in] -> [out][pair] ---------------
__global__ void prep_gw_k(const float* __restrict__ W, uint2* __restrict__ WI,
                          int OUTD, int IND) {
    int idx = blockIdx.x * 256 + threadIdx.x;
    if (idx >= OUTD * IND / 2) return;
    int P = IND / 2;
    int o = idx / P, p = idx % P;
    WI[idx] = pack_hl(W[(size_t)o * IND + 2 * p], W[(size_t)o * IND + 2 * p + 1]);
}

// ---------------- conv1 special: full-W resident, X double-buffered ----------
// 256 threads (8 warps = 2co x 4l), tile 64co x 64l, per-warp 32co x 16l.
// smem 76416 B -> 3 blocks/SM = 24 warps/SM.
__global__ void __launch_bounds__(256, 3)
conv1_mma_k(const uint2* __restrict__ XI, const uint2* __restrict__ WI,
            float* __restrict__ Y,
            double* __restrict__ pS, double* __restrict__ pQ) {
    constexpr int COUT = 256, LIN = 256, LOUT = 256, PAD = 1, LTILE = 64;
    constexpr int WRS = 72, XRS = 40, XROWS = LTILE + 2 * PAD;   // 66
    constexpr int WTW = 192 * WRS;       // 13824 words
    constexpr int XTW = XROWS * XRS;     // 2640 words
    extern __shared__ unsigned dynsm[];  // [W | X0 | X1] = 19104 words
    int bn = blockIdx.x;
    int co0 = blockIdx.y * 64;
    int l0 = blockIdx.z * LTILE;
    int tid = threadIdx.x;
    int lane = tid & 31, wid = tid >> 5;
    int wco = wid & 1, wl = wid >> 1;    // wco 0..1, wl 0..3
    int r4 = lane >> 2, c4 = lane & 3;

    unsigned smbase = (unsigned)__cvta_generic_to_shared(dynsm);

    // W: 192 rows x 16 cp16 = 3072, exactly 12/thread
#pragma unroll
    for (int r = 0; r < 12; r++) {
        int i = r * 256 + tid;
        int row = i >> 4, cw = i & 15;
        int k = row >> 6, co = row & 63;
        const uint2* src = WI + ((size_t)(k * COUT + co0 + co)) * 32 + 2 * cw;
        cp16(smbase + (unsigned)(row * WRS + 4 * cw) * 4u, src, true);
    }
    CP_COMMIT();

    auto load_x = [&](int buf, int ci0) {
        unsigned xbase = smbase + (unsigned)(WTW + buf * XTW) * 4u;
#pragma unroll
        for (int r = 0; r < 3; r++) {
            int i = r * 256 + tid;
            if (i < XROWS * 8) {
                int row = i >> 3, cw = i & 7;
                int gl = l0 - PAD + row;
                bool ok = (gl >= 0 && gl < LIN);
                const uint2* src = ok ? XI + ((size_t)bn * LIN + gl) * 32
                                          + ci0 / 2 + 2 * cw
                                      : XI;
                cp16(xbase + (unsigned)(row * XRS + 4 * cw) * 4u, src, ok);
            }
        }
        CP_COMMIT();
    };

    float acc[2][2][4] = {};

    load_x(0, 0);
    for (int c = 0; c < 2; c++) {
        if (c == 0) {
            load_x(1, 32);
            asm volatile("cp.async.wait_group 1;");
        } else {
            asm volatile("cp.async.wait_group 0;");
        }
        __syncthreads();
        const unsigned* Ws = dynsm;
        const unsigned* Xs = dynsm + WTW + c * XTW;
#pragma unroll
        for (int k = 0; k < 3; k++) {
#pragma unroll
            for (int h = 0; h < 2; h++) {
                int pwb = 2 * (h * 8 + c4);
                int pwa = 32 * c + pwb;
                unsigned ah[2][4], al[2][4];
#pragma unroll
                for (int m = 0; m < 2; m++) {
                    int row = wco * 32 + m * 16 + r4;
                    int base = (k * 64 + row) * WRS + pwa;
                    uint2 a00 = *(const uint2*)&Ws[base];
                    uint2 a10 = *(const uint2*)&Ws[base + 8 * WRS];
                    uint2 a01 = *(const uint2*)&Ws[base + 8];
                    uint2 a11 = *(const uint2*)&Ws[base + 8 * WRS + 8];
                    ah[m][0] = a00.x; ah[m][1] = a10.x; ah[m][2] = a01.x; ah[m][3] = a11.x;
                    al[m][0] = a00.y; al[m][1] = a10.y; al[m][2] = a01.y; al[m][3] = a11.y;
                }
#pragma unroll
                for (int n = 0; n < 2; n++) {
                    int lrow = wl * 16 + n * 8 + r4 + k;
                    int bb = lrow * XRS + pwb;
                    uint2 b0 = *(const uint2*)&Xs[bb];
                    uint2 b1 = *(const uint2*)&Xs[bb + 8];
#pragma unroll
                    for (int m = 0; m < 2; m++) {
                        mma16816(acc[m][n], ah[m], b0.x, b1.x);
                        mma16816(acc[m][n], ah[m], b0.y, b1.y);
                        mma16816(acc[m][n], al[m], b0.x, b1.x);
                    }
                }
            }
        }
        __syncthreads();
    }

    // epilogue: Y stores + fused stats (reduction arrays reuse dynsm)
    float* redS = (float*)dynsm;          // [4][64]
    float* redQ = redS + 256;             // [4][64]
    float sacc[2][2] = {}, qacc[2][2] = {};
#pragma unroll
    for (int m = 0; m < 2; m++) {
        int co = co0 + wco * 32 + m * 16 + r4;
#pragma unroll
        for (int n = 0; n < 2; n++) {
            int l = l0 + wl * 16 + n * 8 + 2 * c4;
            float v0 = acc[m][n][0], v1 = acc[m][n][1];
            float v2 = acc[m][n][2], v3 = acc[m][n][3];
            Y[((size_t)bn * LOUT + l) * COUT + co] = v0;
            Y[((size_t)bn * LOUT + l) * COUT + co + 8] = v2;
            Y[((size_t)bn * LOUT + l + 1) * COUT + co] = v1;
            Y[((size_t)bn * LOUT + l + 1) * COUT + co + 8] = v3;
            sacc[m][0] += v0 + v1; qacc[m][0] += v0 * v0 + v1 * v1;
            sacc[m][1] += v2 + v3; qacc[m][1] += v2 * v2 + v3 * v3;
        }
    }
#pragma unroll
    for (int m = 0; m < 2; m++)
#pragma unroll
        for (int hh = 0; hh < 2; hh++) {
            float s = sacc[m][hh], q = qacc[m][hh];
            s += __shfl_xor_sync(0xFFFFFFFFu, s, 1);
            s += __shfl_xor_sync(0xFFFFFFFFu, s, 2);
            q += __shfl_xor_sync(0xFFFFFFFFu, q, 1);
            q += __shfl_xor_sync(0xFFFFFFFFu, q, 2);
            if (c4 == 0) {
                int ch = wco * 32 + m * 16 + r4 + 8 * hh;
                redS[wl * 64 + ch] = s;
                redQ[wl * 64 + ch] = q;
            }
        }
    __syncthreads();
    if (tid < 64) {
        double s = (double)redS[tid] + redS[64 + tid] + redS[128 + tid] + redS[192 + tid];
        double q = (double)redQ[tid] + redQ[64 + tid] + redQ[128 + tid] + redQ[192 + tid];
        int slot = bn * gridDim.z + blockIdx.z;
        pS[(size_t)(co0 + tid) * 4096 + slot] = s;
        pQ[(size_t)(co0 + tid) * 4096 + slot] = q;
    }
}

// ---------------- generic conv1d via HMMA, cp.async double-buffered ----------
template <int CIN, int LIN, int COUT, int LOUT, int PAD, int LTILE>
__global__ void __launch_bounds__(128, 2)
conv_mma_k(const uint2* __restrict__ XI,
           const uint2* __restrict__ WI,
           float* __restrict__ Y,
           double* __restrict__ pS, double* __restrict__ pQ) {
    constexpr int RS = 40;
    constexpr int NN = LTILE / 16;
    constexpr int XROWS = LTILE + 2 * PAD;
    constexpr int WTW = 192 * RS;
    constexpr int XTW = XROWS * RS;
    constexpr int NCHUNK = CIN / 32;
    constexpr int XCNT = CDIV(XROWS * 8, 128);
    extern __shared__ unsigned dynsm[];
    __shared__ float redS[2][64], redQ[2][64];
    int bn = blockIdx.x;
    int co0 = blockIdx.y * 64;
    int l0 = blockIdx.z * LTILE;
    int tid = threadIdx.x;
    int lane = tid & 31, wid = tid >> 5;
    int wco = wid & 1, wl = wid >> 1;
    int r4 = lane >> 2, c4 = lane & 3;

    unsigned smbase = (unsigned)__cvta_generic_to_shared(dynsm);
    auto wb = [&](int buf) { return smbase + (unsigned)(buf * (WTW + XTW)) * 4u; };
    auto xb = [&](int buf) { return wb(buf) + (unsigned)WTW * 4u; };

    auto load_chunk = [&](int buf, int ci0) {
        unsigned wbase = wb(buf), xbase = xb(buf);
#pragma unroll
        for (int r = 0; r < 12; r++) {
            int i = r * 128 + tid;
            int row = i >> 3, cw = i & 7;
            int k = row >> 6, co = row & 63;
            const uint2* src = WI + ((size_t)(k * COUT + co0 + co)) * (CIN / 2)
                               + ci0 / 2 + 2 * cw;
            cp16(wbase + (unsigned)(row * RS + 4 * cw) * 4u, src, true);
        }
#pragma unroll
        for (int r = 0; r < XCNT; r++) {
            int i = r * 128 + tid;
            if (i < XROWS * 8) {
                int row = i >> 3, cw = i & 7;
                int gl = l0 - PAD + row;
                bool ok = (gl >= 0 && gl < LIN);
                const uint2* src = ok ? XI + ((size_t)bn * LIN + gl) * (CIN / 2)
                                          + ci0 / 2 + 2 * cw
                                      : XI;
                cp16(xbase + (unsigned)(row * RS + 4 * cw) * 4u, src, ok);
            }
        }
        CP_COMMIT();
    };

    float acc[2][NN][4];
#pragma unroll
    for (int m = 0; m < 2; m++)
#pragma unroll
        for (int n = 0; n < NN; n++)
#pragma unroll
            for (int q = 0; q < 4; q++) acc[m][n][q] = 0.f;

    load_chunk(0, 0);
    for (int c = 0; c < NCHUNK; c++) {
        int cb = c & 1;
        if (c + 1 < NCHUNK) {
            load_chunk((c + 1) & 1, (c + 1) * 32);
            asm volatile("cp.async.wait_group 1;");
        } else {
            asm volatile("cp.async.wait_group 0;");
        }
        __syncthreads();

        const unsigned* Ws = dynsm + cb * (WTW + XTW);
        const unsigned* Xs = Ws + WTW;
#pragma unroll
        for (int k = 0; k < 3; k++) {
#pragma unroll
            for (int h = 0; h < 2; h++) {
                int pw = 2 * (h * 8 + c4);
                unsigned ah[2][4], al[2][4];
#pragma unroll
                for (int m = 0; m < 2; m++) {
                    int row = wco * 32 + m * 16 + r4;
                    int base = (k * 64 + row) * RS + pw;
                    uint2 a00 = *(const uint2*)&Ws[base];
                    uint2 a10 = *(const uint2*)&Ws[base + 8 * RS];
                    uint2 a01 = *(const uint2*)&Ws[base + 8];
                    uint2 a11 = *(const uint2*)&Ws[base + 8 * RS + 8];
                    ah[m][0] = a00.x; ah[m][1] = a10.x; ah[m][2] = a01.x; ah[m][3] = a11.x;
                    al[m][0] = a00.y; al[m][1] = a10.y; al[m][2] = a01.y; al[m][3] = a11.y;
                }
#pragma unroll
                for (int n = 0; n < NN; n++) {
                    int lrow = wl * (NN * 8) + n * 8 + r4 + k;
                    int bb = lrow * RS + pw;
                    uint2 b0 = *(const uint2*)&Xs[bb];
                    uint2 b1 = *(const uint2*)&Xs[bb + 8];
#pragma unroll
                    for (int m = 0; m < 2; m++) {
                        mma16816(acc[m][n], ah[m], b0.x, b1.x);
                        mma16816(acc[m][n], ah[m], b0.y, b1.y);
                        mma16816(acc[m][n], al[m], b0.x, b1.x);
                    }
                }
            }
        }
        __syncthreads();
    }

    float sacc[2][2] = {}, qacc[2][2] = {};
#pragma unroll
    for (int m = 0; m < 2; m++) {
        int co = co0 + wco * 32 + m * 16 + r4;
#pragma unroll
        for (int n = 0; n < NN; n++) {
            int l = l0 + wl * (NN * 8) + n * 8 + 2 * c4;
            if (l < LOUT) {
                float v0 = acc[m][n][0], v2 = acc[m][n][2];
                Y[((size_t)bn * LOUT + l) * COUT + co] = v0;
                Y[((size_t)bn * LOUT + l) * COUT + co + 8] = v2;
                sacc[m][0] += v0; qacc[m][0] += v0 * v0;
                sacc[m][1] += v2; qacc[m][1] += v2 * v2;
            }
            if (l + 1 < LOUT) {
                float v1 = acc[m][n][1], v3 = acc[m][n][3];
                Y[((size_t)bn * LOUT + l + 1) * COUT + co] = v1;
                Y[((size_t)bn * LOUT + l + 1) * COUT + co + 8] = v3;
                sacc[m][0] += v1; qacc[m][0] += v1 * v1;
                sacc[m][1] += v3; qacc[m][1] += v3 * v3;
            }
        }
    }
#pragma unroll
    for (int m = 0; m < 2; m++)
#pragma unroll
        for (int hh = 0; hh < 2; hh++) {
            float s = sacc[m][hh], q = qacc[m][hh];
            s += __shfl_xor_sync(0xFFFFFFFFu, s, 1);
            s += __shfl_xor_sync(0xFFFFFFFFu, s, 2);
            q += __shfl_xor_sync(0xFFFFFFFFu, q, 1);
            q += __shfl_xor_sync(0xFFFFFFFFu, q, 2);
            if (c4 == 0) {
                int ch = wco * 32 + m * 16 + r4 + 8 * hh;
                redS[wl][ch] = s;
                redQ[wl][ch] = q;
            }
        }
    __syncthreads();
    if (tid < 64) {
        double s = (double)redS[0][tid] + redS[1][tid];
        double q = (double)redQ[0][tid] + redQ[1][tid];
        int slot = bn * gridDim.z + blockIdx.z;
        pS[(size_t)(co0 + tid) * 4096 + slot] = s;
        pQ[(size_t)(co0 + tid) * 4096 + slot] = q;
    }
}

// ---------------- BN stats finish ----------------
template <int NS>
__global__ void statsC_k(const double* __restrict__ pS, const double* __restrict__ pQ,
                         float* __restrict__ mean, float* __restrict__ istd,
                         double inv_total) {
    int c = blockIdx.x, tid = threadIdx.x;
    double s = 0.0, q = 0.0;
    for (int i = tid; i < NS; i += 256) {
        s += pS[(size_t)c * 4096 + i];
        q += pQ[(size_t)c * 4096 + i];
    }
    __shared__ double ss[256], qs[256];
    ss[tid] = s; qs[tid] = q;
    __syncthreads();
    for (int o = 128; o > 0; o >>= 1) {
        if (tid < o) { ss[tid] += ss[tid + o]; qs[tid] += qs[tid + o]; }
        __syncthreads();
    }
    if (tid == 0) {
        double m = ss[0] * inv_total;
        double var = qs[0] * inv_total - m * m;
        mean[c] = (float)m;
        istd[c] = rsqrtf((float)var + 1e-5f);
    }
}

// ---------------- fused BN + ReLU + maxpool -> interleaved, 16B vectorized ---
template <int C, int Lout, int Lp>
__global__ void bnpool_k(const float* __restrict__ X, uint2* __restrict__ YI,
                         const float* __restrict__ mean, const float* __restrict__ istd,
                         const float* __restrict__ gam, const float* __restrict__ bet) {
    constexpr int P4 = C / 4;
    size_t idx = (size_t)blockIdx.x * 256 + threadIdx.x;
    if (idx >= (size_t)kB1 * Lp * P4) return;
    int p4 = idx % P4;
    int j = (idx / P4) % Lp;
    int bn = idx / ((size_t)P4 * Lp);
    int c0 = 4 * p4;
    float sc[4], sh[4], m[4] = {0.f, 0.f, 0.f, 0.f};
#pragma unroll
    for (int e = 0; e < 4; e++) {
        sc[e] = istd[c0 + e] * gam[c0 + e];
        sh[e] = bet[c0 + e] - mean[c0 + e] * sc[e];
    }
    int l0 = 2 * j - 1, l1 = 2 * j;
    if (l0 >= 0) {
        float4 v = *(const float4*)&X[((size_t)bn * Lout + l0) * C + c0];
        float w[4] = {v.x, v.y, v.z, v.w};
#pragma unroll
        for (int e = 0; e < 4; e++) { float a = fmaf(w[e], sc[e], sh[e]); if (a > m[e]) m[e] = a; }
    }
    if (l1 < Lout) {
        float4 v = *(const float4*)&X[((size_t)bn * Lout + l1) * C + c0];
        float w[4] = {v.x, v.y, v.z, v.w};
#pragma unroll
        for (int e = 0; e < 4; e++) { float a = fmaf(w[e], sc[e], sh[e]); if (a > m[e]) m[e] = a; }
    }
    uint2 p01 = pack_hl(m[0], m[1]);
    uint2 p23 = pack_hl(m[2], m[3]);
    ((uint4*)YI)[idx] = make_uint4(p01.x, p01.y, p23.x, p23.y);
}

// ---------------- bnpool stage 3 -> flat interleaved pairs [bn][4608] --------
__global__ void bnpool3_k(const float* __restrict__ X,   // [bn][70][256]
                          uint2* __restrict__ YI,        // [bn][4608]
                          const float* __restrict__ mean, const float* __restrict__ istd,
                          const float* __restrict__ gam, const float* __restrict__ bet) {
    size_t idx = (size_t)blockIdx.x * 256 + threadIdx.x;
    if (idx >= (size_t)kB1 * 4608) return;
    int pr = idx % 4608;
    int bn = idx / 4608;
    float vv[2];
#pragma unroll
    for (int e = 0; e < 2; e++) {
        int el = 2 * pr + e;
        int c = el / 36, l = el - c * 36;
        float sc = istd[c] * gam[c];
        float sh = bet[c] - mean[c] * sc;
        float m = 0.f;
        int l0 = 2 * l - 1, l1 = 2 * l;
        if (l0 >= 0) { float v = fmaf(X[((size_t)bn * 70 + l0) * 256 + c], sc, sh); if (v > m) m = v; }
        if (l1 < 70) { float v = fmaf(X[((size_t)bn * 70 + l1) * 256 + c], sc, sh); if (v > m) m = v; }
        vv[e] = m;
    }
    YI[idx] = pack_hl(vv[0], vv[1]);
}

// ---------------- nf via HMMA: nf = spa @ mapW^T + mb, split to bf16 ---------
__global__ void __launch_bounds__(256) nf_mma_k(const uint2* __restrict__ P3I,
                                                const uint2* __restrict__ MWI,
                                                const float* __restrict__ MB,
                                                uint2* __restrict__ NFI) {
    extern __shared__ unsigned sm[];
    unsigned* spaW = sm;                 // [64][136 words]
    unsigned* mwW  = sm + 64 * 136;      // [128][136 words]
    int bp = blockIdx.x;
    int b = bp / kTC, tc = bp % kTC;
    int tid = threadIdx.x;
    unsigned smb = (unsigned)__cvta_generic_to_shared(sm);
#pragma unroll
    for (int r = 0; r < 8; r++) {
        int i = r * 256 + tid;
        int row = i >> 5, cw = i & 31;
        const uint2* src = P3I + (size_t)(b * kN + row) * 4608 + tc * 64 + 2 * cw;
        cp16(smb + (unsigned)(row * 136 + 4 * cw) * 4u, src, true);
    }
#pragma unroll
    for (int r = 0; r < 16; r++) {
        int i = r * 256 + tid;
        int row = i >> 5, cw = i & 31;
        const uint2* src = MWI + (size_t)row * 64 + 2 * cw;
        cp16(smb + (unsigned)(64 * 136 + row * 136 + 4 * cw) * 4u, src, true);
    }
    CP_COMMIT();
    asm volatile("cp.async.wait_group 0;");
    __syncthreads();

    int lane = tid & 31, wid = tid >> 5;
    int band = wid >> 1, half = wid & 1;
    int r4 = lane >> 2, c4 = lane & 3;
    float acc[8][4] = {};
#pragma unroll
    for (int kk = 0; kk < 8; kk++) {
        int arow = band * 16 + r4;
        uint2 a0 = *(const uint2*)&spaW[arow * 136 + (kk * 8 + c4) * 2];
        uint2 a1 = *(const uint2*)&spaW[(arow + 8) * 136 + (kk * 8 + c4) * 2];
        uint2 a2 = *(const uint2*)&spaW[arow * 136 + (kk * 8 + c4 + 4) * 2];
        uint2 a3 = *(const uint2*)&spaW[(arow + 8) * 136 + (kk * 8 + c4 + 4) * 2];
        unsigned ah[4] = {a0.x, a1.x, a2.x, a3.x};
        unsigned al[4] = {a0.y, a1.y, a2.y, a3.y};
#pragma unroll
        for (int f = 0; f < 8; f++) {
            int nrow = half * 64 + f * 8 + r4;
            uint2 b0 = *(const uint2*)&mwW[nrow * 136 + (kk * 8 + c4) * 2];
            uint2 b1 = *(const uint2*)&mwW[nrow * 136 + (kk * 8 + c4 + 4) * 2];
            mma16816(acc[f], ah, b0.x, b1.x);
            mma16816(acc[f], ah, b0.y, b1.y);
            mma16816(acc[f], al, b0.x, b1.x);
        }
    }
#pragma unroll
    for (int f = 0; f < 8; f++) {
        int col = half * 64 + f * 8 + 2 * c4;
        float m0 = MB[col], m1 = MB[col + 1];
        int row = band * 16 + r4;
        NFI[((size_t)bp * 64 + row) * 64 + col / 2] = pack_hl(acc[f][0] + m0, acc[f][1] + m1);
        NFI[((size_t)bp * 64 + row + 8) * 64 + col / 2] = pack_hl(acc[f][2] + m0, acc[f][3] + m1);
    }
}

// ---------------- adj via HMMA: gram + theta-map + softmax + aggregate -------
__global__ void __launch_bounds__(256) adj_mma_k(const uint2* __restrict__ NFI,
                                                 const uint2* __restrict__ TI,
                                                 const float* __restrict__ TB,
                                                 float* __restrict__ OUT) {
    extern __shared__ unsigned sm[];
    unsigned* nfW = sm;                           // [64][136 words]
    unsigned* thW = sm + 64 * 136;                // [64][136 words]
    float*    Af  = (float*)(sm + 2 * 64 * 136);  // [64][66] fp32
    unsigned* m2W = sm + 2 * 64 * 136 + 64 * 66;  // M2^T bf16 [o:64][72 words]
    unsigned* apW = m2W + 64 * 72;                // A' bf16 [n:64][72 words]
    int bp = blockIdx.x;
    int tid = threadIdx.x;
    unsigned smb = (unsigned)__cvta_generic_to_shared(sm);
#pragma unroll
    for (int r = 0; r < 8; r++) {
        int i = r * 256 + tid;
        int row = i >> 5, cw = i & 31;
        cp16(smb + (unsigned)(row * 136 + 4 * cw) * 4u,
             NFI + (size_t)bp * 4096 + row * 64 + 2 * cw, true);
    }
#pragma unroll
    for (int r = 0; r < 8; r++) {
        int i = r * 256 + tid;
        int row = i >> 5, cw = i & 31;
        cp16(smb + (unsigned)(64 * 136 + row * 136 + 4 * cw) * 4u,
             TI + (size_t)row * 64 + 2 * cw, true);
    }
    CP_COMMIT();
    asm volatile("cp.async.wait_group 0;");
    __syncthreads();

    int lane = tid & 31, wid = tid >> 5;
    int band = wid >> 1, half = wid & 1;
    int r4 = lane >> 2, c4 = lane & 3;

    {   // stage 1: A = nf@nf^T, M2 = nf@theta^T   (K=128)
        float ag[4][4] = {}, am[4][4] = {};
#pragma unroll
        for (int kk = 0; kk < 8; kk++) {
            int arow = band * 16 + r4;
            uint2 a0 = *(const uint2*)&nfW[arow * 136 + (kk * 8 + c4) * 2];
            uint2 a1 = *(const uint2*)&nfW[(arow + 8) * 136 + (kk * 8 + c4) * 2];
            uint2 a2 = *(const uint2*)&nfW[arow * 136 + (kk * 8 + c4 + 4) * 2];
            uint2 a3 = *(const uint2*)&nfW[(arow + 8) * 136 + (kk * 8 + c4 + 4) * 2];
            unsigned ah[4] = {a0.x, a1.x, a2.x, a3.x};
            unsigned al[4] = {a0.y, a1.y, a2.y, a3.y};
#pragma unroll
            for (int f = 0; f < 4; f++) {
                int nrow = half * 32 + f * 8 + r4;
                uint2 g0 = *(const uint2*)&nfW[nrow * 136 + (kk * 8 + c4) * 2];
                uint2 g1 = *(const uint2*)&nfW[nrow * 136 + (kk * 8 + c4 + 4) * 2];
                mma16816(ag[f], ah, g0.x, g1.x);
                mma16816(ag[f], ah, g0.y, g1.y);
                mma16816(ag[f], al, g0.x, g1.x);
                uint2 t0 = *(const uint2*)&thW[nrow * 136 + (kk * 8 + c4) * 2];
                uint2 t1 = *(const uint2*)&thW[nrow * 136 + (kk * 8 + c4 + 4) * 2];
                mma16816(am[f], ah, t0.x, t1.x);
                mma16816(am[f], ah, t0.y, t1.y);
                mma16816(am[f], al, t0.x, t1.x);
            }
        }
        __nv_bfloat16* m2h = (__nv_bfloat16*)m2W;
#pragma unroll
        for (int f = 0; f < 4; f++) {
            int col = half * 32 + f * 8 + 2 * c4;
#pragma unroll
            for (int q = 0; q < 4; q++) {
                int row = band * 16 + r4 + (q >> 1) * 8;
                int cc = col + (q & 1);
                float v = ag[f][q];
                Af[row * 66 + cc] = v;
                float vm = am[f][q];
                __nv_bfloat16 h = __float2bfloat16(vm);
                __nv_bfloat16 l = __float2bfloat16(vm - __bfloat162float(h));
                int wbase = cc * 72 + (row >> 1) * 2;
                m2h[wbase * 2 + (row & 1)] = h;
                m2h[(wbase + 1) * 2 + (row & 1)] = l;
            }
        }
    }
    __syncthreads();
    {   // stage 2: softmax rows of A
        int row = tid >> 2;
        int part = tid & 3;
        float vals[16];
        float mx = -3.4e38f;
#pragma unroll
        for (int jj = 0; jj < 16; jj++) {
            int col = part * 16 + jj;
            float v = Af[row * 66 + col];
            if (col == row) v -= 1e8f;
            v = v > 0.f ? v : 0.01f * v;
            vals[jj] = v;
            mx = fmaxf(mx, v);
        }
        mx = fmaxf(mx, __shfl_xor_sync(0xFFFFFFFFu, mx, 1));
        mx = fmaxf(mx, __shfl_xor_sync(0xFFFFFFFFu, mx, 2));
        float s = 0.f;
#pragma unroll
        for (int jj = 0; jj < 16; jj++) { vals[jj] = expf(vals[jj] - mx); s += vals[jj]; }
        s += __shfl_xor_sync(0xFFFFFFFFu, s, 1);
        s += __shfl_xor_sync(0xFFFFFFFFu, s, 2);
        float inv = 1.f / s;
#pragma unroll
        for (int j = 0; j < 8; j++) {
            int col = part * 16 + 2 * j;
            float v0 = vals[2 * j] * inv;
            float v1 = vals[2 * j + 1] * inv;
            if (col == row) v0 += 1.f;
            if (col + 1 == row) v1 += 1.f;
            *(uint2*)&apW[(row * 36 + part * 8 + j) * 2] = pack_hl(v0, v1);
        }
    }
    __syncthreads();
    {   // stage 3: out = A' @ M2 + tb   (K=64)
        float acc[4][4] = {};
#pragma unroll
        for (int kk = 0; kk < 4; kk++) {
            int arow = band * 16 + r4;
            uint2 a0 = *(const uint2*)&apW[arow * 72 + (kk * 8 + c4) * 2];
            uint2 a1 = *(const uint2*)&apW[(arow + 8) * 72 + (kk * 8 + c4) * 2];
            uint2 a2 = *(const uint2*)&apW[arow * 72 + (kk * 8 + c4 + 4) * 2];
            uint2 a3 = *(const uint2*)&apW[(arow + 8) * 72 + (kk * 8 + c4 + 4) * 2];
            unsigned ah[4] = {a0.x, a1.x, a2.x, a3.x};
            unsigned al[4] = {a0.y, a1.y, a2.y, a3.y};
#pragma unroll
            for (int f = 0; f < 4; f++) {
                int orow = half * 32 + f * 8 + r4;
                uint2 b0 = *(const uint2*)&m2W[orow * 72 + (kk * 8 + c4) * 2];
                uint2 b1 = *(const uint2*)&m2W[orow * 72 + (kk * 8 + c4 + 4) * 2];
                mma16816(acc[f], ah, b0.x, b1.x);
                mma16816(acc[f], ah, b0.y, b1.y);
                mma16816(acc[f], al, b0.x, b1.x);
            }
        }
#pragma unroll
        for (int f = 0; f < 4; f++) {
            int col = half * 32 + f * 8 + 2 * c4;
            float t0 = TB[col], t1 = TB[col + 1];
            int row = band * 16 + r4;
            OUT[((size_t)bp * 64 + row) * 64 + col] = acc[f][0] + t0;
            OUT[((size_t)bp * 64 + row) * 64 + col + 1] = acc[f][1] + t1;
            OUT[((size_t)bp * 64 + row + 8) * 64 + col] = acc[f][2] + t0;
            OUT[((size_t)bp * 64 + row + 8) * 64 + col + 1] = acc[f][3] + t1;
        }
    }
}

// ---------------- BN stats over rows for [M][C] (channel-last) ----------------
__global__ void stats_last_k(const float* __restrict__ X, int M, int C,
                             float* __restrict__ mean, float* __restrict__ istd) {
    int c = blockIdx.x, tid = threadIdx.x;
    double s = 0.0, q = 0.0;
    for (int i = tid; i < M; i += 256) {
        float v = X[(size_t)i * C + c];
        s += v;
        q += (double)v * v;
    }
    __shared__ double ss[256], qs[256];
    ss[tid] = s; qs[tid] = q;
    __syncthreads();
    for (int o = 128; o > 0; o >>= 1) {
        if (tid < o) { ss[tid] += ss[tid + o]; qs[tid] += qs[tid + o]; }
        __syncthreads();
    }
    if (tid == 0) {
        double m = ss[0] / M;
        double var = qs[0] / M - m * m;
        mean[c] = (float)m;
        istd[c] = rsqrtf((float)var + 1e-5f);
    }
}

// ---------------- final: BN + leaky + pair-mean ----------------
__global__ void final_k(const float* __restrict__ Xo,
                        const float* __restrict__ mean, const float* __restrict__ istd,
                        const float* __restrict__ gam, const float* __restrict__ bet,
                        float* __restrict__ Y) {
    int idx = blockIdx.x * 256 + threadIdx.x;
    if (idx >= kBS * 36 * 64 * 64) return;
    int o = idx & 63;
    int n = (idx >> 6) & 63;
    int w = (idx >> 12) % 36;
    int b = idx / (36 * 4096);
    float sc = istd[o] * gam[o];
    float sh = bet[o] - mean[o] * sc;
    float acc = 0.f;
#pragma unroll
    for (int e = 0; e < 2; e++) {
        float v = fmaf(Xo[(((size_t)(b * kTC + 2 * w + e)) * 64 + n) * 64 + o], sc, sh);
        acc += (v > 0.f ? v : 0.01f * v);
    }
    Y[idx] = 0.5f * acc;
}

// ---------------- launch ----------------
extern "C" void kernel_launch(void* const* d_in, const int* in_sizes, int n_in,
                              void* d_out, int out_size) {
    const float* x   = (const float*)d_in[0];
    const float* w1  = (const float*)d_in[1];
    const float* g1  = (const float*)d_in[2];
    const float* b1  = (const float*)d_in[3];
    const float* w2  = (const float*)d_in[4];
    const float* g2  = (const float*)d_in[5];
    const float* b2  = (const float*)d_in[6];
    const float* w3  = (const float*)d_in[7];
    const float* g3  = (const float*)d_in[8];
    const float* b3  = (const float*)d_in[9];
    const float* mw  = (const float*)d_in[10];
    const float* mb  = (const float*)d_in[11];
    const float* tw  = (const float*)d_in[12];
    const float* tbv = (const float*)d_in[13];
    const float* bg  = (const float*)d_in[14];
    const float* bb  = (const float*)d_in[15];
    float* out = (float*)d_out;

    uint2 *xi, *p1i, *p2i, *p3i, *nfi, *w1i, *w2i, *w3i, *mwi, *ti;
    float *c1, *c2, *c3, *oo, *mn, *is;
    double *psS, *psQ;
    cudaGetSymbolAddress((void**)&xi, g_xi);
    cudaGetSymbolAddress((void**)&c1, g_c1);
    cudaGetSymbolAddress((void**)&p1i, g_p1i);
    cudaGetSymbolAddress((void**)&c2, g_c2);
    cudaGetSymbolAddress((void**)&p2i, g_p2i);
    cudaGetSymbolAddress((void**)&c3, g_c3);
    cudaGetSymbolAddress((void**)&p3i, g_p3i);
    cudaGetSymbolAddress((void**)&nfi, g_nfi);
    cudaGetSymbolAddress((void**)&oo, g_oo);
    cudaGetSymbolAddress((void**)&mn, g_mean);
    cudaGetSymbolAddress((void**)&is, g_istd);
    cudaGetSymbolAddress((void**)&psS, g_psS);
    cudaGetSymbolAddress((void**)&psQ, g_psQ);
    cudaGetSymbolAddress((void**)&w1i, g_w1i);
    cudaGetSymbolAddress((void**)&w2i, g_w2i);
    cudaGetSymbolAddress((void**)&w3i, g_w3i);
    cudaGetSymbolAddress((void**)&mwi, g_mwi);
    cudaGetSymbolAddress((void**)&ti, g_ti);

    const int C1_SMEM = (192 * 72 + 2 * 66 * 40) * 4;            // 76416 B
    const int C2_SMEM = 2 * (192 * 40 + 52 * 40) * 4;            // 78080 B
    const int C3_SMEM = 2 * (192 * 40 + 86 * 40) * 4;            // 88960 B
    const int NF_SMEM  = (64 + 128) * 136 * 4;                   // 104448 B
    const int ADJ_SMEM = (2 * 64 * 136 + 64 * 66 + 2 * 64 * 72) * 4;  // 123392 B
    cudaFuncSetAttribute(conv1_mma_k,
                         cudaFuncAttributeMaxDynamicSharedMemorySize, C1_SMEM);
    cudaFuncSetAttribute(conv_mma_k<256, 129, 128, 131, 2, 48>,
                         cudaFuncAttributeMaxDynamicSharedMemorySize, C2_SMEM);
    cudaFuncSetAttribute(conv_mma_k<128, 66, 256, 70, 3, 80>,
                         cudaFuncAttributeMaxDynamicSharedMemorySize, C3_SMEM);
    cudaFuncSetAttribute(nf_mma_k, cudaFuncAttributeMaxDynamicSharedMemorySize, NF_SMEM);
    cudaFuncSetAttribute(adj_mma_k, cudaFuncAttributeMaxDynamicSharedMemorySize, ADJ_SMEM);

    // launch order: conv1 at index 3 (ncu-profiled slot)
    prep_x_k<<<CDIV(kB1 * 256 * 16, 256), 256>>>(x, xi);                       // 0
    prep_w_k<<<CDIV(3 * 256 * 32, 256), 256>>>(w1, w1i, 256, 64);              // 1
    prep_w_k<<<CDIV(3 * 256 * 64, 256), 256>>>(w3, w3i, 256, 128);             // 2

    conv1_mma_k<<<dim3(kB1, 4, 4), 256, C1_SMEM>>>(xi, w1i, c1, psS, psQ);     // 3
    statsC_k<kB1 * 4><<<256, 256>>>(psS, psQ, mn, is, 1.0 / ((double)kB1 * 256));
    prep_w_k<<<CDIV(3 * 128 * 128, 256), 256>>>(w2, w2i, 128, 256);
    bnpool_k<256, 256, 129><<<CDIV(kB1 * 129 * 64, 256), 256>>>(c1, p1i, mn, is, g1, b1);

    conv_mma_k<256, 129, 128, 131, 2, 48>
        <<<dim3(kB1, 2, 3), 128, C2_SMEM>>>(p1i, w2i, c2, psS, psQ);
    statsC_k<kB1 * 3><<<128, 256>>>(psS, psQ, mn, is, 1.0 / ((double)kB1 * 131));
    bnpool_k<128, 131, 66><<<CDIV(kB1 * 66 * 32, 256), 256>>>(c2, p2i, mn, is, g2, b2);

    conv_mma_k<128, 66, 256, 70, 3, 80>
        <<<dim3(kB1, 4, 1), 128, C3_SMEM>>>(p2i, w3i, c3, psS, psQ);
    statsC_k<kB1><<<256, 256>>>(psS, psQ, mn, is, 1.0 / ((double)kB1 * 70));
    bnpool3_k<<<CDIV(kB1 * 4608, 256), 256>>>(c3, p3i, mn, is, g3, b3);

    // graph part (HMMA)
    prep_gw_k<<<CDIV(128 * 64, 256), 256>>>(mw, mwi, 128, 128);
    prep_gw_k<<<CDIV(64 * 64, 256), 256>>>(tw, ti, 64, 128);
    nf_mma_k<<<kBP, 256, NF_SMEM>>>(p3i, mwi, mb, nfi);
    adj_mma_k<<<kBP, 256, ADJ_SMEM>>>(nfi, ti, tbv, oo);
    stats_last_k<<<64, 256>>>(oo, kBP * 64, 64, mn, is);
    final_k<<<CDIV(kBS * 36 * 64 * 64, 256), 256>>>(oo, mn, is, bg, bb, out);
}

// round 14
// speedup vs baseline: 1.0407x; 1.0407x over previous
#include <cuda_runtime.h>
#include <cuda_bf16.h>
#include <math.h>

#define CDIV(a,b) (((a)+(b)-1)/(b))

// ---------------- problem dims ----------------
constexpr int kBS = 16, kN = 64;
constexpr int kB1 = kBS * kN;              // 1024 sequences
constexpr int kTC = 72, kBP = kBS * kTC;   // 1152 graph batches

// ---------------- scratch ----------------
__device__ __align__(16) uint2 g_xi [(size_t)kB1 * 256 * 32];   // [bn][s][p<32]
__device__ float g_c1[(size_t)kB1 * 256 * 256];
__device__ __align__(16) uint2 g_p1i[(size_t)kB1 * 129 * 128];
__device__ float g_c2[(size_t)kB1 * 131 * 128];
__device__ __align__(16) uint2 g_p2i[(size_t)kB1 * 66 * 64];
__device__ float g_c3[(size_t)kB1 * 70 * 256];
__device__ __align__(16) uint2 g_p3i[(size_t)kB1 * 4608];       // [bn][pair<4608]
__device__ __align__(16) uint2 g_nfi[(size_t)kBP * 64 * 64];    // [bp][n][pair<64]
__device__ float g_oo[(size_t)kBP * 64 * 64];
__device__ float g_mean[256];
__device__ float g_istd[256];
__device__ double g_psS[(size_t)256 * 4096];
__device__ double g_psQ[(size_t)256 * 4096];
__device__ __align__(16) uint2 g_w1i[3 * 256 * 32];
__device__ __align__(16) uint2 g_w2i[3 * 128 * 128];
__device__ __align__(16) uint2 g_w3i[3 * 256 * 64];
__device__ __align__(16) uint2 g_mwi[128 * 64];                 // mapW [out][pair]
__device__ __align__(16) uint2 g_ti [64 * 64];                  // theta [out][pair]

// ---------------- helpers ----------------
__device__ __forceinline__ void mma16816(float* c, const unsigned* a,
                                         unsigned b0, unsigned b1) {
    asm volatile(
        "mma.sync.aligned.m16n8k16.row.col.f32.bf16.bf16.f32 "
        "{%0,%1,%2,%3}, {%4,%5,%6,%7}, {%8,%9}, {%0,%1,%2,%3};"
        : "+f"(c[0]), "+f"(c[1]), "+f"(c[2]), "+f"(c[3])
        : "r"(a[0]), "r"(a[1]), "r"(a[2]), "r"(a[3]), "r"(b0), "r"(b1));
}

__device__ __forceinline__ uint2 pack_hl(float v0, float v1) {
    __nv_bfloat16 h0 = __float2bfloat16(v0);
    __nv_bfloat16 h1 = __float2bfloat16(v1);
    __nv_bfloat16 l0 = __float2bfloat16(v0 - __bfloat162float(h0));
    __nv_bfloat16 l1 = __float2bfloat16(v1 - __bfloat162float(h1));
    uint2 r;
    r.x = (unsigned)__bfloat16_as_ushort(h0) | ((unsigned)__bfloat16_as_ushort(h1) << 16);
    r.y = (unsigned)__bfloat16_as_ushort(l0) | ((unsigned)__bfloat16_as_ushort(l1) << 16);
    return r;
}

__device__ __forceinline__ void cp16(unsigned dst, const void* src, bool full) {
    int sz = full ? 16 : 0;
    asm volatile("cp.async.ca.shared.global [%0], [%1], 16, %2;"
                 :: "r"(dst), "l"(src), "r"(sz));
}
#define CP_COMMIT() asm volatile("cp.async.commit_group;")

// ---------------- prep: x[b,s,n,d] -> xi [bn][s][p], 16B vectorized ----------
__global__ void prep_x_k(const float* __restrict__ x, uint2* __restrict__ XI) {
    size_t idx = (size_t)blockIdx.x * 256 + threadIdx.x;
    if (idx >= (size_t)kB1 * 256 * 16) return;
    int q = idx & 15;
    int s = (idx >> 4) & 255;
    int bn = idx >> 12;
    int b = bn >> 6, n = bn & 63;
    float4 v = *(const float4*)&x[(((size_t)(b * 256 + s)) * 64 + n) * 64 + 4 * q];
    uint2 p01 = pack_hl(v.x, v.y);
    uint2 p23 = pack_hl(v.z, v.w);
    ((uint4*)XI)[idx] = make_uint4(p01.x, p01.y, p23.x, p23.y);
}

// ---------------- weight prep: W[co][ci][k] -> WI[k][co][p] ----------------
__global__ void prep_w_k(const float* __restrict__ W, uint2* __restrict__ WI,
                         int COUT, int CIN) {
    int idx = blockIdx.x * 256 + threadIdx.x;
    if (idx >= COUT * CIN / 2 * 3) return;
    int P = CIN / 2;
    int p = idx % P;
    int co = (idx / P) % COUT;
    int k = idx / (P * COUT);
    float v0 = W[((size_t)co * CIN + 2 * p) * 3 + k];
    float v1 = W[((size_t)co * CIN + 2 * p + 1) * 3 + k];
    WI[idx] = pack_hl(v0, v1);
}

// ---------------- graph weight prep: W[out][in] -> [out][pair] ---------------
__global__ void prep_gw_k(const float* __restrict__ W, uint2* __restrict__ WI,
                          int OUTD, int IND) {
    int idx = blockIdx.x * 256 + threadIdx.x;
    if (idx >= OUTD * IND / 2) return;
    int P = IND / 2;
    int o = idx / P, p = idx % P;
    WI[idx] = pack_hl(W[(size_t)o * IND + 2 * p], W[(size_t)o * IND + 2 * p + 1]);
}

// ---------------- conv1 special: full-W resident, X double-buffered ----------
// R11 config: 128 threads (4 warps = 2co x 2l), per-warp 32co x 32l (NN=4).
// smem 76416 B -> 3 blocks/SM = 12 warps/SM.
__global__ void __launch_bounds__(128, 3)
conv1_mma_k(const uint2* __restrict__ XI, const uint2* __restrict__ WI,
            float* __restrict__ Y,
            double* __restrict__ pS, double* __restrict__ pQ) {
    constexpr int COUT = 256, LIN = 256, LOUT = 256, PAD = 1, LTILE = 64;
    constexpr int WRS = 72, XRS = 40, XROWS = LTILE + 2 * PAD;   // 66
    constexpr int WTW = 192 * WRS;       // 13824 words
    constexpr int XTW = XROWS * XRS;     // 2640 words
    extern __shared__ unsigned dynsm[];  // [W | X0 | X1] = 19104 words
    int bn = blockIdx.x;
    int co0 = blockIdx.y * 64;
    int l0 = blockIdx.z * LTILE;
    int tid = threadIdx.x;
    int lane = tid & 31, wid = tid >> 5;
    int wco = wid & 1, wl = wid >> 1;
    int r4 = lane >> 2, c4 = lane & 3;

    unsigned smbase = (unsigned)__cvta_generic_to_shared(dynsm);

    // W: 192 rows x 16 cp16 = 3072, exactly 24/thread
#pragma unroll
    for (int r = 0; r < 24; r++) {
        int i = r * 128 + tid;
        int row = i >> 4, cw = i & 15;
        int k = row >> 6, co = row & 63;
        const uint2* src = WI + ((size_t)(k * COUT + co0 + co)) * 32 + 2 * cw;
        cp16(smbase + (unsigned)(row * WRS + 4 * cw) * 4u, src, true);
    }
    CP_COMMIT();

    auto load_x = [&](int buf, int ci0) {
        unsigned xbase = smbase + (unsigned)(WTW + buf * XTW) * 4u;
#pragma unroll
        for (int r = 0; r < 5; r++) {
            int i = r * 128 + tid;
            if (i < XROWS * 8) {
                int row = i >> 3, cw = i & 7;
                int gl = l0 - PAD + row;
                bool ok = (gl >= 0 && gl < LIN);
                const uint2* src = ok ? XI + ((size_t)bn * LIN + gl) * 32
                                          + ci0 / 2 + 2 * cw
                                      : XI;
                cp16(xbase + (unsigned)(row * XRS + 4 * cw) * 4u, src, ok);
            }
        }
        CP_COMMIT();
    };

    float acc[2][4][4] = {};

    load_x(0, 0);
    for (int c = 0; c < 2; c++) {
        if (c == 0) {
            load_x(1, 32);
            asm volatile("cp.async.wait_group 1;");
        } else {
            asm volatile("cp.async.wait_group 0;");
        }
        __syncthreads();
        const unsigned* Ws = dynsm;
        const unsigned* Xs = dynsm + WTW + c * XTW;
#pragma unroll
        for (int k = 0; k < 3; k++) {
#pragma unroll
            for (int h = 0; h < 2; h++) {
                int pwb = 2 * (h * 8 + c4);
                int pwa = 32 * c + pwb;
                unsigned ah[2][4], al[2][4];
#pragma unroll
                for (int m = 0; m < 2; m++) {
                    int row = wco * 32 + m * 16 + r4;
                    int base = (k * 64 + row) * WRS + pwa;
                    uint2 a00 = *(const uint2*)&Ws[base];
                    uint2 a10 = *(const uint2*)&Ws[base + 8 * WRS];
                    uint2 a01 = *(const uint2*)&Ws[base + 8];
                    uint2 a11 = *(const uint2*)&Ws[base + 8 * WRS + 8];
                    ah[m][0] = a00.x; ah[m][1] = a10.x; ah[m][2] = a01.x; ah[m][3] = a11.x;
                    al[m][0] = a00.y; al[m][1] = a10.y; al[m][2] = a01.y; al[m][3] = a11.y;
                }
#pragma unroll
                for (int n = 0; n < 4; n++) {
                    int lrow = wl * 32 + n * 8 + r4 + k;
                    int bb = lrow * XRS + pwb;
                    uint2 b0 = *(const uint2*)&Xs[bb];
                    uint2 b1 = *(const uint2*)&Xs[bb + 8];
#pragma unroll
                    for (int m = 0; m < 2; m++) {
                        mma16816(acc[m][n], ah[m], b0.x, b1.x);
                        mma16816(acc[m][n], ah[m], b0.y, b1.y);
                        mma16816(acc[m][n], al[m], b0.x, b1.x);
                    }
                }
            }
        }
        __syncthreads();
    }

    // epilogue: Y stores + fused stats (reduction arrays reuse dynsm)
    float* redS = (float*)dynsm;          // [2][64]
    float* redQ = redS + 128;             // [2][64]
    float sacc[2][2] = {}, qacc[2][2] = {};
#pragma unroll
    for (int m = 0; m < 2; m++) {
        int co = co0 + wco * 32 + m * 16 + r4;
#pragma unroll
        for (int n = 0; n < 4; n++) {
            int l = l0 + wl * 32 + n * 8 + 2 * c4;
            float v0 = acc[m][n][0], v1 = acc[m][n][1];
            float v2 = acc[m][n][2], v3 = acc[m][n][3];
            Y[((size_t)bn * LOUT + l) * COUT + co] = v0;
            Y[((size_t)bn * LOUT + l) * COUT + co + 8] = v2;
            Y[((size_t)bn * LOUT + l + 1) * COUT + co] = v1;
            Y[((size_t)bn * LOUT + l + 1) * COUT + co + 8] = v3;
            sacc[m][0] += v0 + v1; qacc[m][0] += v0 * v0 + v1 * v1;
            sacc[m][1] += v2 + v3; qacc[m][1] += v2 * v2 + v3 * v3;
        }
    }
#pragma unroll
    for (int m = 0; m < 2; m++)
#pragma unroll
        for (int hh = 0; hh < 2; hh++) {
            float s = sacc[m][hh], q = qacc[m][hh];
            s += __shfl_xor_sync(0xFFFFFFFFu, s, 1);
            s += __shfl_xor_sync(0xFFFFFFFFu, s, 2);
            q += __shfl_xor_sync(0xFFFFFFFFu, q, 1);
            q += __shfl_xor_sync(0xFFFFFFFFu, q, 2);
            if (c4 == 0) {
                int ch = wco * 32 + m * 16 + r4 + 8 * hh;
                redS[wl * 64 + ch] = s;
                redQ[wl * 64 + ch] = q;
            }
        }
    __syncthreads();
    if (tid < 64) {
        double s = (double)redS[tid] + redS[64 + tid];
        double q = (double)redQ[tid] + redQ[64 + tid];
        int slot = bn * gridDim.z + blockIdx.z;
        pS[(size_t)(co0 + tid) * 4096 + slot] = s;
        pQ[(size_t)(co0 + tid) * 4096 + slot] = q;
    }
}

// ---------------- generic conv1d via HMMA, cp.async double-buffered ----------
template <int CIN, int LIN, int COUT, int LOUT, int PAD, int LTILE>
__global__ void __launch_bounds__(128, 2)
conv_mma_k(const uint2* __restrict__ XI,
           const uint2* __restrict__ WI,
           float* __restrict__ Y,
           double* __restrict__ pS, double* __restrict__ pQ) {
    constexpr int RS = 40;
    constexpr int NN = LTILE / 16;
    constexpr int XROWS = LTILE + 2 * PAD;
    constexpr int WTW = 192 * RS;
    constexpr int XTW = XROWS * RS;
    constexpr int NCHUNK = CIN / 32;
    constexpr int XCNT = CDIV(XROWS * 8, 128);
    extern __shared__ unsigned dynsm[];
    __shared__ float redS[2][64], redQ[2][64];
    int bn = blockIdx.x;
    int co0 = blockIdx.y * 64;
    int l0 = blockIdx.z * LTILE;
    int tid = threadIdx.x;
    int lane = tid & 31, wid = tid >> 5;
    int wco = wid & 1, wl = wid >> 1;
    int r4 = lane >> 2, c4 = lane & 3;

    unsigned smbase = (unsigned)__cvta_generic_to_shared(dynsm);
    auto wb = [&](int buf) { return smbase + (unsigned)(buf * (WTW + XTW)) * 4u; };
    auto xb = [&](int buf) { return wb(buf) + (unsigned)WTW * 4u; };

    auto load_chunk = [&](int buf, int ci0) {
        unsigned wbase = wb(buf), xbase = xb(buf);
#pragma unroll
        for (int r = 0; r < 12; r++) {
            int i = r * 128 + tid;
            int row = i >> 3, cw = i & 7;
            int k = row >> 6, co = row & 63;
            const uint2* src = WI + ((size_t)(k * COUT + co0 + co)) * (CIN / 2)
                               + ci0 / 2 + 2 * cw;
            cp16(wbase + (unsigned)(row * RS + 4 * cw) * 4u, src, true);
        }
#pragma unroll
        for (int r = 0; r < XCNT; r++) {
            int i = r * 128 + tid;
            if (i < XROWS * 8) {
                int row = i >> 3, cw = i & 7;
                int gl = l0 - PAD + row;
                bool ok = (gl >= 0 && gl < LIN);
                const uint2* src = ok ? XI + ((size_t)bn * LIN + gl) * (CIN / 2)
                                          + ci0 / 2 + 2 * cw
                                      : XI;
                cp16(xbase + (unsigned)(row * RS + 4 * cw) * 4u, src, ok);
            }
        }
        CP_COMMIT();
    };

    float acc[2][NN][4];
#pragma unroll
    for (int m = 0; m < 2; m++)
#pragma unroll
        for (int n = 0; n < NN; n++)
#pragma unroll
            for (int q = 0; q < 4; q++) acc[m][n][q] = 0.f;

    load_chunk(0, 0);
    for (int c = 0; c < NCHUNK; c++) {
        int cb = c & 1;
        if (c + 1 < NCHUNK) {
            load_chunk((c + 1) & 1, (c + 1) * 32);
            asm volatile("cp.async.wait_group 1;");
        } else {
            asm volatile("cp.async.wait_group 0;");
        }
        __syncthreads();

        const unsigned* Ws = dynsm + cb * (WTW + XTW);
        const unsigned* Xs = Ws + WTW;
#pragma unroll
        for (int k = 0; k < 3; k++) {
#pragma unroll
            for (int h = 0; h < 2; h++) {
                int pw = 2 * (h * 8 + c4);
                unsigned ah[2][4], al[2][4];
#pragma unroll
                for (int m = 0; m < 2; m++) {
                    int row = wco * 32 + m * 16 + r4;
                    int base = (k * 64 + row) * RS + pw;
                    uint2 a00 = *(const uint2*)&Ws[base];
                    uint2 a10 = *(const uint2*)&Ws[base + 8 * RS];
                    uint2 a01 = *(const uint2*)&Ws[base + 8];
                    uint2 a11 = *(const uint2*)&Ws[base + 8 * RS + 8];
                    ah[m][0] = a00.x; ah[m][1] = a10.x; ah[m][2] = a01.x; ah[m][3] = a11.x;
                    al[m][0] = a00.y; al[m][1] = a10.y; al[m][2] = a01.y; al[m][3] = a11.y;
                }
#pragma unroll
                for (int n = 0; n < NN; n++) {
                    int lrow = wl * (NN * 8) + n * 8 + r4 + k;
                    int bb = lrow * RS + pw;
                    uint2 b0 = *(const uint2*)&Xs[bb];
                    uint2 b1 = *(const uint2*)&Xs[bb + 8];
#pragma unroll
                    for (int m = 0; m < 2; m++) {
                        mma16816(acc[m][n], ah[m], b0.x, b1.x);
                        mma16816(acc[m][n], ah[m], b0.y, b1.y);
                        mma16816(acc[m][n], al[m], b0.x, b1.x);
                    }
                }
            }
        }
        __syncthreads();
    }

    float sacc[2][2] = {}, qacc[2][2] = {};
#pragma unroll
    for (int m = 0; m < 2; m++) {
        int co = co0 + wco * 32 + m * 16 + r4;
#pragma unroll
        for (int n = 0; n < NN; n++) {
            int l = l0 + wl * (NN * 8) + n * 8 + 2 * c4;
            if (l < LOUT) {
                float v0 = acc[m][n][0], v2 = acc[m][n][2];
                Y[((size_t)bn * LOUT + l) * COUT + co] = v0;
                Y[((size_t)bn * LOUT + l) * COUT + co + 8] = v2;
                sacc[m][0] += v0; qacc[m][0] += v0 * v0;
                sacc[m][1] += v2; qacc[m][1] += v2 * v2;
            }
            if (l + 1 < LOUT) {
                float v1 = acc[m][n][1], v3 = acc[m][n][3];
                Y[((size_t)bn * LOUT + l + 1) * COUT + co] = v1;
                Y[((size_t)bn * LOUT + l + 1) * COUT + co + 8] = v3;
                sacc[m][0] += v1; qacc[m][0] += v1 * v1;
                sacc[m][1] += v3; qacc[m][1] += v3 * v3;
            }
        }
    }
#pragma unroll
    for (int m = 0; m < 2; m++)
#pragma unroll
        for (int hh = 0; hh < 2; hh++) {
            float s = sacc[m][hh], q = qacc[m][hh];
            s += __shfl_xor_sync(0xFFFFFFFFu, s, 1);
            s += __shfl_xor_sync(0xFFFFFFFFu, s, 2);
            q += __shfl_xor_sync(0xFFFFFFFFu, q, 1);
            q += __shfl_xor_sync(0xFFFFFFFFu, q, 2);
            if (c4 == 0) {
                int ch = wco * 32 + m * 16 + r4 + 8 * hh;
                redS[wl][ch] = s;
                redQ[wl][ch] = q;
            }
        }
    __syncthreads();
    if (tid < 64) {
        double s = (double)redS[0][tid] + redS[1][tid];
        double q = (double)redQ[0][tid] + redQ[1][tid];
        int slot = bn * gridDim.z + blockIdx.z;
        pS[(size_t)(co0 + tid) * 4096 + slot] = s;
        pQ[(size_t)(co0 + tid) * 4096 + slot] = q;
    }
}

// ---------------- BN stats finish ----------------
template <int NS>
__global__ void statsC_k(const double* __restrict__ pS, const double* __restrict__ pQ,
                         float* __restrict__ mean, float* __restrict__ istd,
                         double inv_total) {
    int c = blockIdx.x, tid = threadIdx.x;
    double s = 0.0, q = 0.0;
    for (int i = tid; i < NS; i += 256) {
        s += pS[(size_t)c * 4096 + i];
        q += pQ[(size_t)c * 4096 + i];
    }
    __shared__ double ss[256], qs[256];
    ss[tid] = s; qs[tid] = q;
    __syncthreads();
    for (int o = 128; o > 0; o >>= 1) {
        if (tid < o) { ss[tid] += ss[tid + o]; qs[tid] += qs[tid + o]; }
        __syncthreads();
    }
    if (tid == 0) {
        double m = ss[0] * inv_total;
        double var = qs[0] * inv_total - m * m;
        mean[c] = (float)m;
        istd[c] = rsqrtf((float)var + 1e-5f);
    }
}

// ---------------- fused BN + ReLU + maxpool -> interleaved, 16B vectorized ---
template <int C, int Lout, int Lp>
__global__ void bnpool_k(const float* __restrict__ X, uint2* __restrict__ YI,
                         const float* __restrict__ mean, const float* __restrict__ istd,
                         const float* __restrict__ gam, const float* __restrict__ bet) {
    constexpr int P4 = C / 4;
    size_t idx = (size_t)blockIdx.x * 256 + threadIdx.x;
    if (idx >= (size_t)kB1 * Lp * P4) return;
    int p4 = idx % P4;
    int j = (idx / P4) % Lp;
    int bn = idx / ((size_t)P4 * Lp);
    int c0 = 4 * p4;
    float sc[4], sh[4], m[4] = {0.f, 0.f, 0.f, 0.f};
#pragma unroll
    for (int e = 0; e < 4; e++) {
        sc[e] = istd[c0 + e] * gam[c0 + e];
        sh[e] = bet[c0 + e] - mean[c0 + e] * sc[e];
    }
    int l0 = 2 * j - 1, l1 = 2 * j;
    if (l0 >= 0) {
        float4 v = *(const float4*)&X[((size_t)bn * Lout + l0) * C + c0];
        float w[4] = {v.x, v.y, v.z, v.w};
#pragma unroll
        for (int e = 0; e < 4; e++) { float a = fmaf(w[e], sc[e], sh[e]); if (a > m[e]) m[e] = a; }
    }
    if (l1 < Lout) {
        float4 v = *(const float4*)&X[((size_t)bn * Lout + l1) * C + c0];
        float w[4] = {v.x, v.y, v.z, v.w};
#pragma unroll
        for (int e = 0; e < 4; e++) { float a = fmaf(w[e], sc[e], sh[e]); if (a > m[e]) m[e] = a; }
    }
    uint2 p01 = pack_hl(m[0], m[1]);
    uint2 p23 = pack_hl(m[2], m[3]);
    ((uint4*)YI)[idx] = make_uint4(p01.x, p01.y, p23.x, p23.y);
}

// ---------------- bnpool stage 3 -> flat interleaved pairs [bn][4608] --------
__global__ void bnpool3_k(const float* __restrict__ X,   // [bn][70][256]
                          uint2* __restrict__ YI,        // [bn][4608]
                          const float* __restrict__ mean, const float* __restrict__ istd,
                          const float* __restrict__ gam, const float* __restrict__ bet) {
    size_t idx = (size_t)blockIdx.x * 256 + threadIdx.x;
    if (idx >= (size_t)kB1 * 4608) return;
    int pr = idx % 4608;
    int bn = idx / 4608;
    float vv[2];
#pragma unroll
    for (int e = 0; e < 2; e++) {
        int el = 2 * pr + e;
        int c = el / 36, l = el - c * 36;
        float sc = istd[c] * gam[c];
        float sh = bet[c] - mean[c] * sc;
        float m = 0.f;
        int l0 = 2 * l - 1, l1 = 2 * l;
        if (l0 >= 0) { float v = fmaf(X[((size_t)bn * 70 + l0) * 256 + c], sc, sh); if (v > m) m = v; }
        if (l1 < 70) { float v = fmaf(X[((size_t)bn * 70 + l1) * 256 + c], sc, sh); if (v > m) m = v; }
        vv[e] = m;
    }
    YI[idx] = pack_hl(vv[0], vv[1]);
}

// ---------------- nf via HMMA: nf = spa @ mapW^T + mb, split to bf16 ---------
__global__ void __launch_bounds__(256) nf_mma_k(const uint2* __restrict__ P3I,
                                                const uint2* __restrict__ MWI,
                                                const float* __restrict__ MB,
                                                uint2* __restrict__ NFI) {
    extern __shared__ unsigned sm[];
    unsigned* spaW = sm;                 // [64][136 words]
    unsigned* mwW  = sm + 64 * 136;      // [128][136 words]
    int bp = blockIdx.x;
    int b = bp / kTC, tc = bp % kTC;
    int tid = threadIdx.x;
    unsigned smb = (unsigned)__cvta_generic_to_shared(sm);
#pragma unroll
    for (int r = 0; r < 8; r++) {
        int i = r * 256 + tid;
        int row = i >> 5, cw = i & 31;
        const uint2* src = P3I + (size_t)(b * kN + row) * 4608 + tc * 64 + 2 * cw;
        cp16(smb + (unsigned)(row * 136 + 4 * cw) * 4u, src, true);
    }
#pragma unroll
    for (int r = 0; r < 16; r++) {
        int i = r * 256 + tid;
        int row = i >> 5, cw = i & 31;
        const uint2* src = MWI + (size_t)row * 64 + 2 * cw;
        cp16(smb + (unsigned)(64 * 136 + row * 136 + 4 * cw) * 4u, src, true);
    }
    CP_COMMIT();
    asm volatile("cp.async.wait_group 0;");
    __syncthreads();

    int lane = tid & 31, wid = tid >> 5;
    int band = wid >> 1, half = wid & 1;
    int r4 = lane >> 2, c4 = lane & 3;
    float acc[8][4] = {};
#pragma unroll
    for (int kk = 0; kk < 8; kk++) {
        int arow = band * 16 + r4;
        uint2 a0 = *(const uint2*)&spaW[arow * 136 + (kk * 8 + c4) * 2];
        uint2 a1 = *(const uint2*)&spaW[(arow + 8) * 136 + (kk * 8 + c4) * 2];
        uint2 a2 = *(const uint2*)&spaW[arow * 136 + (kk * 8 + c4 + 4) * 2];
        uint2 a3 = *(const uint2*)&spaW[(arow + 8) * 136 + (kk * 8 + c4 + 4) * 2];
        unsigned ah[4] = {a0.x, a1.x, a2.x, a3.x};
        unsigned al[4] = {a0.y, a1.y, a2.y, a3.y};
#pragma unroll
        for (int f = 0; f < 8; f++) {
            int nrow = half * 64 + f * 8 + r4;
            uint2 b0 = *(const uint2*)&mwW[nrow * 136 + (kk * 8 + c4) * 2];
            uint2 b1 = *(const uint2*)&mwW[nrow * 136 + (kk * 8 + c4 + 4) * 2];
            mma16816(acc[f], ah, b0.x, b1.x);
            mma16816(acc[f], ah, b0.y, b1.y);
            mma16816(acc[f], al, b0.x, b1.x);
        }
    }
#pragma unroll
    for (int f = 0; f < 8; f++) {
        int col = half * 64 + f * 8 + 2 * c4;
        float m0 = MB[col], m1 = MB[col + 1];
        int row = band * 16 + r4;
        NFI[((size_t)bp * 64 + row) * 64 + col / 2] = pack_hl(acc[f][0] + m0, acc[f][1] + m1);
        NFI[((size_t)bp * 64 + row + 8) * 64 + col / 2] = pack_hl(acc[f][2] + m0, acc[f][3] + m1);
    }
}

// ---------------- adj via HMMA: gram + theta-map + softmax + aggregate -------
__global__ void __launch_bounds__(256) adj_mma_k(const uint2* __restrict__ NFI,
                                                 const uint2* __restrict__ TI,
                                                 const float* __restrict__ TB,
                                                 float* __restrict__ OUT) {
    extern __shared__ unsigned sm[];
    unsigned* nfW = sm;                           // [64][136 words]
    unsigned* thW = sm + 64 * 136;                // [64][136 words]
    float*    Af  = (float*)(sm + 2 * 64 * 136);  // [64][66] fp32
    unsigned* m2W = sm + 2 * 64 * 136 + 64 * 66;  // M2^T bf16 [o:64][72 words]
    unsigned* apW = m2W + 64 * 72;                // A' bf16 [n:64][72 words]
    int bp = blockIdx.x;
    int tid = threadIdx.x;
    unsigned smb = (unsigned)__cvta_generic_to_shared(sm);
#pragma unroll
    for (int r = 0; r < 8; r++) {
        int i = r * 256 + tid;
        int row = i >> 5, cw = i & 31;
        cp16(smb + (unsigned)(row * 136 + 4 * cw) * 4u,
             NFI + (size_t)bp * 4096 + row * 64 + 2 * cw, true);
    }
#pragma unroll
    for (int r = 0; r < 8; r++) {
        int i = r * 256 + tid;
        int row = i >> 5, cw = i & 31;
        cp16(smb + (unsigned)(64 * 136 + row * 136 + 4 * cw) * 4u,
             TI + (size_t)row * 64 + 2 * cw, true);
    }
    CP_COMMIT();
    asm volatile("cp.async.wait_group 0;");
    __syncthreads();

    int lane = tid & 31, wid = tid >> 5;
    int band = wid >> 1, half = wid & 1;
    int r4 = lane >> 2, c4 = lane & 3;

    {   // stage 1: A = nf@nf^T, M2 = nf@theta^T   (K=128)
        float ag[4][4] = {}, am[4][4] = {};
#pragma unroll
        for (int kk = 0; kk < 8; kk++) {
            int arow = band * 16 + r4;
            uint2 a0 = *(const uint2*)&nfW[arow * 136 + (kk * 8 + c4) * 2];
            uint2 a1 = *(const uint2*)&nfW[(arow + 8) * 136 + (kk * 8 + c4) * 2];
            uint2 a2 = *(const uint2*)&nfW[arow * 136 + (kk * 8 + c4 + 4) * 2];
            uint2 a3 = *(const uint2*)&nfW[(arow + 8) * 136 + (kk * 8 + c4 + 4) * 2];
            unsigned ah[4] = {a0.x, a1.x, a2.x, a3.x};
            unsigned al[4] = {a0.y, a1.y, a2.y, a3.y};
#pragma unroll
            for (int f = 0; f < 4; f++) {
                int nrow = half * 32 + f * 8 + r4;
                uint2 g0 = *(const uint2*)&nfW[nrow * 136 + (kk * 8 + c4) * 2];
                uint2 g1 = *(const uint2*)&nfW[nrow * 136 + (kk * 8 + c4 + 4) * 2];
                mma16816(ag[f], ah, g0.x, g1.x);
                mma16816(ag[f], ah, g0.y, g1.y);
                mma16816(ag[f], al, g0.x, g1.x);
                uint2 t0 = *(const uint2*)&thW[nrow * 136 + (kk * 8 + c4) * 2];
                uint2 t1 = *(const uint2*)&thW[nrow * 136 + (kk * 8 + c4 + 4) * 2];
                mma16816(am[f], ah, t0.x, t1.x);
                mma16816(am[f], ah, t0.y, t1.y);
                mma16816(am[f], al, t0.x, t1.x);
            }
        }
        __nv_bfloat16* m2h = (__nv_bfloat16*)m2W;
#pragma unroll
        for (int f = 0; f < 4; f++) {
            int col = half * 32 + f * 8 + 2 * c4;
#pragma unroll
            for (int q = 0; q < 4; q++) {
                int row = band * 16 + r4 + (q >> 1) * 8;
                int cc = col + (q & 1);
                float v = ag[f][q];
                Af[row * 66 + cc] = v;
                float vm = am[f][q];
                __nv_bfloat16 h = __float2bfloat16(vm);
                __nv_bfloat16 l = __float2bfloat16(vm - __bfloat162float(h));
                int wbase = cc * 72 + (row >> 1) * 2;
                m2h[wbase * 2 + (row & 1)] = h;
                m2h[(wbase + 1) * 2 + (row & 1)] = l;
            }
        }
    }
    __syncthreads();
    {   // stage 2: softmax rows of A
        int row = tid >> 2;
        int part = tid & 3;
        float vals[16];
        float mx = -3.4e38f;
#pragma unroll
        for (int jj = 0; jj < 16; jj++) {
            int col = part * 16 + jj;
            float v = Af[row * 66 + col];
            if (col == row) v -= 1e8f;
            v = v > 0.f ? v : 0.01f * v;
            vals[jj] = v;
            mx = fmaxf(mx, v);
        }
        mx = fmaxf(mx, __shfl_xor_sync(0xFFFFFFFFu, mx, 1));
        mx = fmaxf(mx, __shfl_xor_sync(0xFFFFFFFFu, mx, 2));
        float s = 0.f;
#pragma unroll
        for (int jj = 0; jj < 16; jj++) { vals[jj] = expf(vals[jj] - mx); s += vals[jj]; }
        s += __shfl_xor_sync(0xFFFFFFFFu, s, 1);
        s += __shfl_xor_sync(0xFFFFFFFFu, s, 2);
        float inv = 1.f / s;
#pragma unroll
        for (int j = 0; j < 8; j++) {
            int col = part * 16 + 2 * j;
            float v0 = vals[2 * j] * inv;
            float v1 = vals[2 * j + 1] * inv;
            if (col == row) v0 += 1.f;
            if (col + 1 == row) v1 += 1.f;
            *(uint2*)&apW[(row * 36 + part * 8 + j) * 2] = pack_hl(v0, v1);
        }
    }
    __syncthreads();
    {   // stage 3: out = A' @ M2 + tb   (K=64)
        float acc[4][4] = {};
#pragma unroll
        for (int kk = 0; kk < 4; kk++) {
            int arow = band * 16 + r4;
            uint2 a0 = *(const uint2*)&apW[arow * 72 + (kk * 8 + c4) * 2];
            uint2 a1 = *(const uint2*)&apW[(arow + 8) * 72 + (kk * 8 + c4) * 2];
            uint2 a2 = *(const uint2*)&apW[arow * 72 + (kk * 8 + c4 + 4) * 2];
            uint2 a3 = *(const uint2*)&apW[(arow + 8) * 72 + (kk * 8 + c4 + 4) * 2];
            unsigned ah[4] = {a0.x, a1.x, a2.x, a3.x};
            unsigned al[4] = {a0.y, a1.y, a2.y, a3.y};
#pragma unroll
            for (int f = 0; f < 4; f++) {
                int orow = half * 32 + f * 8 + r4;
                uint2 b0 = *(const uint2*)&m2W[orow * 72 + (kk * 8 + c4) * 2];
                uint2 b1 = *(const uint2*)&m2W[orow * 72 + (kk * 8 + c4 + 4) * 2];
                mma16816(acc[f], ah, b0.x, b1.x);
                mma16816(acc[f], ah, b0.y, b1.y);
                mma16816(acc[f], al, b0.x, b1.x);
            }
        }
#pragma unroll
        for (int f = 0; f < 4; f++) {
            int col = half * 32 + f * 8 + 2 * c4;
            float t0 = TB[col], t1 = TB[col + 1];
            int row = band * 16 + r4;
            OUT[((size_t)bp * 64 + row) * 64 + col] = acc[f][0] + t0;
            OUT[((size_t)bp * 64 + row) * 64 + col + 1] = acc[f][1] + t1;
            OUT[((size_t)bp * 64 + row + 8) * 64 + col] = acc[f][2] + t0;
            OUT[((size_t)bp * 64 + row + 8) * 64 + col + 1] = acc[f][3] + t1;
        }
    }
}

// ---------------- final BN stats, two-stage: stage A (256 chunks) ------------
__global__ void statsLA_k(const float* __restrict__ X,   // [M][64]
                          double* __restrict__ pS, double* __restrict__ pQ) {
    constexpr int M = kBP * 64;             // 73728 rows
    constexpr int RPC = M / 256;            // 288 rows per chunk
    int chunk = blockIdx.x;
    int tid = threadIdx.x;
    int c = tid & 63;                       // channel
    int rs = tid >> 6;                      // row-subgroup 0..3
    double q = 0.0, sd = 0.0;
    for (int r = rs; r < RPC; r += 4) {
        float v = X[(size_t)(chunk * RPC + r) * 64 + c];
        sd += v;
        q += (double)v * v;
    }
    __shared__ double ss[256], qs[256];
    ss[tid] = sd; qs[tid] = q;
    __syncthreads();
    if (tid < 128) { ss[tid] += ss[tid + 128]; qs[tid] += qs[tid + 128]; }
    __syncthreads();
    if (tid < 64) {
        pS[(size_t)tid * 4096 + chunk] = ss[tid] + ss[tid + 64];
        pQ[(size_t)tid * 4096 + chunk] = qs[tid] + qs[tid + 64];
    }
}

// ---------------- final: BN + leaky + pair-mean ----------------
__global__ void final_k(const float* __restrict__ Xo,
                        const float* __restrict__ mean, const float* __restrict__ istd,
                        const float* __restrict__ gam, const float* __restrict__ bet,
                        float* __restrict__ Y) {
    int idx = blockIdx.x * 256 + threadIdx.x;
    if (idx >= kBS * 36 * 64 * 64) return;
    int o = idx & 63;
    int n = (idx >> 6) & 63;
    int w = (idx >> 12) % 36;
    int b = idx / (36 * 4096);
    float sc = istd[o] * gam[o];
    float sh = bet[o] - mean[o] * sc;
    float acc = 0.f;
#pragma unroll
    for (int e = 0; e < 2; e++) {
        float v = fmaf(Xo[(((size_t)(b * kTC + 2 * w + e)) * 64 + n) * 64 + o], sc, sh);
        acc += (v > 0.f ? v : 0.01f * v);
    }
    Y[idx] = 0.5f * acc;
}

// ---------------- launch ----------------
extern "C" void kernel_launch(void* const* d_in, const int* in_sizes, int n_in,
                              void* d_out, int out_size) {
    const float* x   = (const float*)d_in[0];
    const float* w1  = (const float*)d_in[1];
    const float* g1  = (const float*)d_in[2];
    const float* b1  = (const float*)d_in[3];
    const float* w2  = (const float*)d_in[4];
    const float* g2  = (const float*)d_in[5];
    const float* b2  = (const float*)d_in[6];
    const float* w3  = (const float*)d_in[7];
    const float* g3  = (const float*)d_in[8];
    const float* b3  = (const float*)d_in[9];
    const float* mw  = (const float*)d_in[10];
    const float* mb  = (const float*)d_in[11];
    const float* tw  = (const float*)d_in[12];
    const float* tbv = (const float*)d_in[13];
    const float* bg  = (const float*)d_in[14];
    const float* bb  = (const float*)d_in[15];
    float* out = (float*)d_out;

    uint2 *xi, *p1i, *p2i, *p3i, *nfi, *w1i, *w2i, *w3i, *mwi, *ti;
    float *c1, *c2, *c3, *oo, *mn, *is;
    double *psS, *psQ;
    cudaGetSymbolAddress((void**)&xi, g_xi);
    cudaGetSymbolAddress((void**)&c1, g_c1);
    cudaGetSymbolAddress((void**)&p1i, g_p1i);
    cudaGetSymbolAddress((void**)&c2, g_c2);
    cudaGetSymbolAddress((void**)&p2i, g_p2i);
    cudaGetSymbolAddress((void**)&c3, g_c3);
    cudaGetSymbolAddress((void**)&p3i, g_p3i);
    cudaGetSymbolAddress((void**)&nfi, g_nfi);
    cudaGetSymbolAddress((void**)&oo, g_oo);
    cudaGetSymbolAddress((void**)&mn, g_mean);
    cudaGetSymbolAddress((void**)&is, g_istd);
    cudaGetSymbolAddress((void**)&psS, g_psS);
    cudaGetSymbolAddress((void**)&psQ, g_psQ);
    cudaGetSymbolAddress((void**)&w1i, g_w1i);
    cudaGetSymbolAddress((void**)&w2i, g_w2i);
    cudaGetSymbolAddress((void**)&w3i, g_w3i);
    cudaGetSymbolAddress((void**)&mwi, g_mwi);
    cudaGetSymbolAddress((void**)&ti, g_ti);

    const int C1_SMEM = (192 * 72 + 2 * 66 * 40) * 4;            // 76416 B
    const int C2_SMEM = 2 * (192 * 40 + 52 * 40) * 4;            // 78080 B
    const int C3_SMEM = 2 * (192 * 40 + 86 * 40) * 4;            // 88960 B
    const int NF_SMEM  = (64 + 128) * 136 * 4;                   // 104448 B
    const int ADJ_SMEM = (2 * 64 * 136 + 64 * 66 + 2 * 64 * 72) * 4;  // 123392 B
    cudaFuncSetAttribute(conv1_mma_k,
                         cudaFuncAttributeMaxDynamicSharedMemorySize, C1_SMEM);
    cudaFuncSetAttribute(conv_mma_k<256, 129, 128, 131, 2, 48>,
                         cudaFuncAttributeMaxDynamicSharedMemorySize, C2_SMEM);
    cudaFuncSetAttribute(conv_mma_k<128, 66, 256, 70, 3, 80>,
                         cudaFuncAttributeMaxDynamicSharedMemorySize, C3_SMEM);
    cudaFuncSetAttribute(nf_mma_k, cudaFuncAttributeMaxDynamicSharedMemorySize, NF_SMEM);
    cudaFuncSetAttribute(adj_mma_k, cudaFuncAttributeMaxDynamicSharedMemorySize, ADJ_SMEM);

    // launch order: conv1 at index 3 (ncu-profiled slot)
    prep_x_k<<<CDIV(kB1 * 256 * 16, 256), 256>>>(x, xi);                       // 0
    prep_w_k<<<CDIV(3 * 256 * 32, 256), 256>>>(w1, w1i, 256, 64);              // 1
    prep_w_k<<<CDIV(3 * 256 * 64, 256), 256>>>(w3, w3i, 256, 128);             // 2

    conv1_mma_k<<<dim3(kB1, 4, 4), 128, C1_SMEM>>>(xi, w1i, c1, psS, psQ);     // 3
    statsC_k<kB1 * 4><<<256, 256>>>(psS, psQ, mn, is, 1.0 / ((double)kB1 * 256));
    prep_w_k<<<CDIV(3 * 128 * 128, 256), 256>>>(w2, w2i, 128, 256);
    bnpool_k<256, 256, 129><<<CDIV(kB1 * 129 * 64, 256), 256>>>(c1, p1i, mn, is, g1, b1);

    conv_mma_k<256, 129, 128, 131, 2, 48>
        <<<dim3(kB1, 2, 3), 128, C2_SMEM>>>(p1i, w2i, c2, psS, psQ);
    statsC_k<kB1 * 3><<<128, 256>>>(psS, psQ, mn, is, 1.0 / ((double)kB1 * 131));
    bnpool_k<128, 131, 66><<<CDIV(kB1 * 66 * 32, 256), 256>>>(c2, p2i, mn, is, g2, b2);

    conv_mma_k<128, 66, 256, 70, 3, 80>
        <<<dim3(kB1, 4, 1), 128, C3_SMEM>>>(p2i, w3i, c3, psS, psQ);
    statsC_k<kB1><<<256, 256>>>(psS, psQ, mn, is, 1.0 / ((double)kB1 * 70));
    bnpool3_k<<<CDIV(kB1 * 4608, 256), 256>>>(c3, p3i, mn, is, g3, b3);

    // graph part (HMMA)
    prep_gw_k<<<CDIV(128 * 64, 256), 256>>>(mw, mwi, 128, 128);
    prep_gw_k<<<CDIV(64 * 64, 256), 256>>>(tw, ti, 64, 128);
    nf_mma_k<<<kBP, 256, NF_SMEM>>>(p3i, mwi, mb, nfi);
    adj_mma_k<<<kBP, 256, ADJ_SMEM>>>(nfi, ti, tbv, oo);
    statsLA_k<<<256, 256>>>(oo, psS, psQ);
    statsC_k<256><<<64, 256>>>(psS, psQ, mn, is, 1.0 / ((double)kBP * 64));
    final_k<<<CDIV(kBS * 36 * 64 * 64, 256), 256>>>(oo, mn, is, bg, bb, out);
}

// round 15
// speedup vs baseline: 1.0449x; 1.0040x over previous
#include <cuda_runtime.h>
#include <cuda_bf16.h>
#include <math.h>

#define CDIV(a,b) (((a)+(b)-1)/(b))

// ---------------- problem dims ----------------
constexpr int kBS = 16, kN = 64;
constexpr int kB1 = kBS * kN;              // 1024 sequences
constexpr int kTC = 72, kBP = kBS * kTC;   // 1152 graph batches

// ---------------- scratch ----------------
__device__ __align__(16) uint2 g_xi [(size_t)kB1 * 256 * 32];   // [bn][s][p<32]
__device__ float g_c1[(size_t)kB1 * 256 * 256];
__device__ __align__(16) uint2 g_p1i[(size_t)kB1 * 129 * 128];
__device__ float g_c2[(size_t)kB1 * 131 * 128];
__device__ __align__(16) uint2 g_p2i[(size_t)kB1 * 66 * 64];
__device__ float g_c3[(size_t)kB1 * 70 * 256];
__device__ __align__(16) uint2 g_p3i[(size_t)kB1 * 4608];       // [bn][pair<4608]
__device__ __align__(16) uint2 g_nfi[(size_t)kBP * 64 * 64];    // [bp][n][pair<64]
__device__ float g_oo[(size_t)kBP * 64 * 64];
__device__ float g_mean[256];
__device__ float g_istd[256];
__device__ double g_psS[(size_t)256 * 4096];
__device__ double g_psQ[(size_t)256 * 4096];
__device__ __align__(16) uint2 g_w1i[3 * 256 * 32];
__device__ __align__(16) uint2 g_w2i[3 * 128 * 128];
__device__ __align__(16) uint2 g_w3i[3 * 256 * 64];
__device__ __align__(16) uint2 g_mwi[128 * 64];                 // mapW [out][pair]
__device__ __align__(16) uint2 g_ti [64 * 64];                  // theta [out][pair]

// ---------------- helpers ----------------
__device__ __forceinline__ void mma16816(float* c, const unsigned* a,
                                         unsigned b0, unsigned b1) {
    asm volatile(
        "mma.sync.aligned.m16n8k16.row.col.f32.bf16.bf16.f32 "
        "{%0,%1,%2,%3}, {%4,%5,%6,%7}, {%8,%9}, {%0,%1,%2,%3};"
        : "+f"(c[0]), "+f"(c[1]), "+f"(c[2]), "+f"(c[3])
        : "r"(a[0]), "r"(a[1]), "r"(a[2]), "r"(a[3]), "r"(b0), "r"(b1));
}

__device__ __forceinline__ uint2 pack_hl(float v0, float v1) {
    __nv_bfloat16 h0 = __float2bfloat16(v0);
    __nv_bfloat16 h1 = __float2bfloat16(v1);
    __nv_bfloat16 l0 = __float2bfloat16(v0 - __bfloat162float(h0));
    __nv_bfloat16 l1 = __float2bfloat16(v1 - __bfloat162float(h1));
    uint2 r;
    r.x = (unsigned)__bfloat16_as_ushort(h0) | ((unsigned)__bfloat16_as_ushort(h1) << 16);
    r.y = (unsigned)__bfloat16_as_ushort(l0) | ((unsigned)__bfloat16_as_ushort(l1) << 16);
    return r;
}

__device__ __forceinline__ void cp16(unsigned dst, const void* src, bool full) {
    int sz = full ? 16 : 0;
    asm volatile("cp.async.ca.shared.global [%0], [%1], 16, %2;"
                 :: "r"(dst), "l"(src), "r"(sz));
}
#define CP_COMMIT() asm volatile("cp.async.commit_group;")

// ---------------- prep: x[b,s,n,d] -> xi [bn][s][p], 16B vectorized ----------
__global__ void prep_x_k(const float* __restrict__ x, uint2* __restrict__ XI) {
    size_t idx = (size_t)blockIdx.x * 256 + threadIdx.x;
    if (idx >= (size_t)kB1 * 256 * 16) return;
    int q = idx & 15;
    int s = (idx >> 4) & 255;
    int bn = idx >> 12;
    int b = bn >> 6, n = bn & 63;
    float4 v = *(const float4*)&x[(((size_t)(b * 256 + s)) * 64 + n) * 64 + 4 * q];
    uint2 p01 = pack_hl(v.x, v.y);
    uint2 p23 = pack_hl(v.z, v.w);
    ((uint4*)XI)[idx] = make_uint4(p01.x, p01.y, p23.x, p23.y);
}

// ---------------- weight prep: W[co][ci][k] -> WI[k][co][p] ----------------
__global__ void prep_w_k(const float* __restrict__ W, uint2* __restrict__ WI,
                         int COUT, int CIN) {
    int idx = blockIdx.x * 256 + threadIdx.x;
    if (idx >= COUT * CIN / 2 * 3) return;
    int P = CIN / 2;
    int p = idx % P;
    int co = (idx / P) % COUT;
    int k = idx / (P * COUT);
    float v0 = W[((size_t)co * CIN + 2 * p) * 3 + k];
    float v1 = W[((size_t)co * CIN + 2 * p + 1) * 3 + k];
    WI[idx] = pack_hl(v0, v1);
}

// ---------------- graph weight prep: W[out][in] -> [out][pair] ---------------
__global__ void prep_gw_k(const float* __restrict__ W, uint2* __restrict__ WI,
                          int OUTD, int IND) {
    int idx = blockIdx.x * 256 + threadIdx.x;
    if (idx >= OUTD * IND / 2) return;
    int P = IND / 2;
    int o = idx / P, p = idx % P;
    WI[idx] = pack_hl(W[(size_t)o * IND + 2 * p], W[(size_t)o * IND + 2 * p + 1]);
}

// ---------------- conv1 special: full-W resident, X double-buffered ----------
// LTILE=128: 128 threads (4 warps = 2co x 2l), per-warp 32co x 64l (NN=8).
// 0.5 LDS.64/MMA. smem 96896 B -> 2 blocks/SM.
__global__ void __launch_bounds__(128, 2)
conv1_mma_k(const uint2* __restrict__ XI, const uint2* __restrict__ WI,
            float* __restrict__ Y,
            double* __restrict__ pS, double* __restrict__ pQ) {
    constexpr int COUT = 256, LIN = 256, LOUT = 256, PAD = 1, LTILE = 128;
    constexpr int WRS = 72, XRS = 40, XROWS = LTILE + 2 * PAD;   // 130
    constexpr int WTW = 192 * WRS;       // 13824 words
    constexpr int XTW = XROWS * XRS;     // 5200 words
    extern __shared__ unsigned dynsm[];  // [W | X0 | X1] = 24224 words
    int bn = blockIdx.x;
    int co0 = blockIdx.y * 64;
    int l0 = blockIdx.z * LTILE;
    int tid = threadIdx.x;
    int lane = tid & 31, wid = tid >> 5;
    int wco = wid & 1, wl = wid >> 1;
    int r4 = lane >> 2, c4 = lane & 3;

    unsigned smbase = (unsigned)__cvta_generic_to_shared(dynsm);

    // W: 192 rows x 16 cp16 = 3072, exactly 24/thread
#pragma unroll
    for (int r = 0; r < 24; r++) {
        int i = r * 128 + tid;
        int row = i >> 4, cw = i & 15;
        int k = row >> 6, co = row & 63;
        const uint2* src = WI + ((size_t)(k * COUT + co0 + co)) * 32 + 2 * cw;
        cp16(smbase + (unsigned)(row * WRS + 4 * cw) * 4u, src, true);
    }
    CP_COMMIT();

    auto load_x = [&](int buf, int ci0) {
        unsigned xbase = smbase + (unsigned)(WTW + buf * XTW) * 4u;
#pragma unroll
        for (int r = 0; r < 9; r++) {
            int i = r * 128 + tid;
            if (i < XROWS * 8) {
                int row = i >> 3, cw = i & 7;
                int gl = l0 - PAD + row;
                bool ok = (gl >= 0 && gl < LIN);
                const uint2* src = ok ? XI + ((size_t)bn * LIN + gl) * 32
                                          + ci0 / 2 + 2 * cw
                                      : XI;
                cp16(xbase + (unsigned)(row * XRS + 4 * cw) * 4u, src, ok);
            }
        }
        CP_COMMIT();
    };

    float acc[2][8][4] = {};

    load_x(0, 0);
    for (int c = 0; c < 2; c++) {
        if (c == 0) {
            load_x(1, 32);
            asm volatile("cp.async.wait_group 1;");
        } else {
            asm volatile("cp.async.wait_group 0;");
        }
        __syncthreads();
        const unsigned* Ws = dynsm;
        const unsigned* Xs = dynsm + WTW + c * XTW;
#pragma unroll
        for (int k = 0; k < 3; k++) {
#pragma unroll
            for (int h = 0; h < 2; h++) {
                int pwb = 2 * (h * 8 + c4);
                int pwa = 32 * c + pwb;
                unsigned ah[2][4], al[2][4];
#pragma unroll
                for (int m = 0; m < 2; m++) {
                    int row = wco * 32 + m * 16 + r4;
                    int base = (k * 64 + row) * WRS + pwa;
                    uint2 a00 = *(const uint2*)&Ws[base];
                    uint2 a10 = *(const uint2*)&Ws[base + 8 * WRS];
                    uint2 a01 = *(const uint2*)&Ws[base + 8];
                    uint2 a11 = *(const uint2*)&Ws[base + 8 * WRS + 8];
                    ah[m][0] = a00.x; ah[m][1] = a10.x; ah[m][2] = a01.x; ah[m][3] = a11.x;
                    al[m][0] = a00.y; al[m][1] = a10.y; al[m][2] = a01.y; al[m][3] = a11.y;
                }
#pragma unroll
                for (int n = 0; n < 8; n++) {
                    int lrow = wl * 64 + n * 8 + r4 + k;
                    int bb = lrow * XRS + pwb;
                    uint2 b0 = *(const uint2*)&Xs[bb];
                    uint2 b1 = *(const uint2*)&Xs[bb + 8];
#pragma unroll
                    for (int m = 0; m < 2; m++) {
                        mma16816(acc[m][n], ah[m], b0.x, b1.x);
                        mma16816(acc[m][n], ah[m], b0.y, b1.y);
                        mma16816(acc[m][n], al[m], b0.x, b1.x);
                    }
                }
            }
        }
        __syncthreads();
    }

    // epilogue: Y stores + fused stats (reduction arrays reuse dynsm)
    float* redS = (float*)dynsm;          // [2][64]
    float* redQ = redS + 128;             // [2][64]
    float sacc[2][2] = {}, qacc[2][2] = {};
#pragma unroll
    for (int m = 0; m < 2; m++) {
        int co = co0 + wco * 32 + m * 16 + r4;
#pragma unroll
        for (int n = 0; n < 8; n++) {
            int l = l0 + wl * 64 + n * 8 + 2 * c4;
            float v0 = acc[m][n][0], v1 = acc[m][n][1];
            float v2 = acc[m][n][2], v3 = acc[m][n][3];
            Y[((size_t)bn * LOUT + l) * COUT + co] = v0;
            Y[((size_t)bn * LOUT + l) * COUT + co + 8] = v2;
            Y[((size_t)bn * LOUT + l + 1) * COUT + co] = v1;
            Y[((size_t)bn * LOUT + l + 1) * COUT + co + 8] = v3;
            sacc[m][0] += v0 + v1; qacc[m][0] += v0 * v0 + v1 * v1;
            sacc[m][1] += v2 + v3; qacc[m][1] += v2 * v2 + v3 * v3;
        }
    }
#pragma unroll
    for (int m = 0; m < 2; m++)
#pragma unroll
        for (int hh = 0; hh < 2; hh++) {
            float s = sacc[m][hh], q = qacc[m][hh];
            s += __shfl_xor_sync(0xFFFFFFFFu, s, 1);
            s += __shfl_xor_sync(0xFFFFFFFFu, s, 2);
            q += __shfl_xor_sync(0xFFFFFFFFu, q, 1);
            q += __shfl_xor_sync(0xFFFFFFFFu, q, 2);
            if (c4 == 0) {
                int ch = wco * 32 + m * 16 + r4 + 8 * hh;
                redS[wl * 64 + ch] = s;
                redQ[wl * 64 + ch] = q;
            }
        }
    __syncthreads();
    if (tid < 64) {
        double s = (double)redS[tid] + redS[64 + tid];
        double q = (double)redQ[tid] + redQ[64 + tid];
        int slot = bn * gridDim.z + blockIdx.z;
        pS[(size_t)(co0 + tid) * 4096 + slot] = s;
        pQ[(size_t)(co0 + tid) * 4096 + slot] = q;
    }
}

// ---------------- generic conv1d via HMMA, cp.async double-buffered ----------
template <int CIN, int LIN, int COUT, int LOUT, int PAD, int LTILE>
__global__ void __launch_bounds__(128, 2)
conv_mma_k(const uint2* __restrict__ XI,
           const uint2* __restrict__ WI,
           float* __restrict__ Y,
           double* __restrict__ pS, double* __restrict__ pQ) {
    constexpr int RS = 40;
    constexpr int NN = LTILE / 16;
    constexpr int XROWS = LTILE + 2 * PAD;
    constexpr int WTW = 192 * RS;
    constexpr int XTW = XROWS * RS;
    constexpr int NCHUNK = CIN / 32;
    constexpr int XCNT = CDIV(XROWS * 8, 128);
    extern __shared__ unsigned dynsm[];
    __shared__ float redS[2][64], redQ[2][64];
    int bn = blockIdx.x;
    int co0 = blockIdx.y * 64;
    int l0 = blockIdx.z * LTILE;
    int tid = threadIdx.x;
    int lane = tid & 31, wid = tid >> 5;
    int wco = wid & 1, wl = wid >> 1;
    int r4 = lane >> 2, c4 = lane & 3;

    unsigned smbase = (unsigned)__cvta_generic_to_shared(dynsm);
    auto wb = [&](int buf) { return smbase + (unsigned)(buf * (WTW + XTW)) * 4u; };
    auto xb = [&](int buf) { return wb(buf) + (unsigned)WTW * 4u; };

    auto load_chunk = [&](int buf, int ci0) {
        unsigned wbase = wb(buf), xbase = xb(buf);
#pragma unroll
        for (int r = 0; r < 12; r++) {
            int i = r * 128 + tid;
            int row = i >> 3, cw = i & 7;
            int k = row >> 6, co = row & 63;
            const uint2* src = WI + ((size_t)(k * COUT + co0 + co)) * (CIN / 2)
                               + ci0 / 2 + 2 * cw;
            cp16(wbase + (unsigned)(row * RS + 4 * cw) * 4u, src, true);
        }
#pragma unroll
        for (int r = 0; r < XCNT; r++) {
            int i = r * 128 + tid;
            if (i < XROWS * 8) {
                int row = i >> 3, cw = i & 7;
                int gl = l0 - PAD + row;
                bool ok = (gl >= 0 && gl < LIN);
                const uint2* src = ok ? XI + ((size_t)bn * LIN + gl) * (CIN / 2)
                                          + ci0 / 2 + 2 * cw
                                      : XI;
                cp16(xbase + (unsigned)(row * RS + 4 * cw) * 4u, src, ok);
            }
        }
        CP_COMMIT();
    };

    float acc[2][NN][4];
#pragma unroll
    for (int m = 0; m < 2; m++)
#pragma unroll
        for (int n = 0; n < NN; n++)
#pragma unroll
            for (int q = 0; q < 4; q++) acc[m][n][q] = 0.f;

    load_chunk(0, 0);
    for (int c = 0; c < NCHUNK; c++) {
        int cb = c & 1;
        if (c + 1 < NCHUNK) {
            load_chunk((c + 1) & 1, (c + 1) * 32);
            asm volatile("cp.async.wait_group 1;");
        } else {
            asm volatile("cp.async.wait_group 0;");
        }
        __syncthreads();

        const unsigned* Ws = dynsm + cb * (WTW + XTW);
        const unsigned* Xs = Ws + WTW;
#pragma unroll
        for (int k = 0; k < 3; k++) {
#pragma unroll
            for (int h = 0; h < 2; h++) {
                int pw = 2 * (h * 8 + c4);
                unsigned ah[2][4], al[2][4];
#pragma unroll
                for (int m = 0; m < 2; m++) {
                    int row = wco * 32 + m * 16 + r4;
                    int base = (k * 64 + row) * RS + pw;
                    uint2 a00 = *(const uint2*)&Ws[base];
                    uint2 a10 = *(const uint2*)&Ws[base + 8 * RS];
                    uint2 a01 = *(const uint2*)&Ws[base + 8];
                    uint2 a11 = *(const uint2*)&Ws[base + 8 * RS + 8];
                    ah[m][0] = a00.x; ah[m][1] = a10.x; ah[m][2] = a01.x; ah[m][3] = a11.x;
                    al[m][0] = a00.y; al[m][1] = a10.y; al[m][2] = a01.y; al[m][3] = a11.y;
                }
#pragma unroll
                for (int n = 0; n < NN; n++) {
                    int lrow = wl * (NN * 8) + n * 8 + r4 + k;
                    int bb = lrow * RS + pw;
                    uint2 b0 = *(const uint2*)&Xs[bb];
                    uint2 b1 = *(const uint2*)&Xs[bb + 8];
#pragma unroll
                    for (int m = 0; m < 2; m++) {
                        mma16816(acc[m][n], ah[m], b0.x, b1.x);
                        mma16816(acc[m][n], ah[m], b0.y, b1.y);
                        mma16816(acc[m][n], al[m], b0.x, b1.x);
                    }
                }
            }
        }
        __syncthreads();
    }

    float sacc[2][2] = {}, qacc[2][2] = {};
#pragma unroll
    for (int m = 0; m < 2; m++) {
        int co = co0 + wco * 32 + m * 16 + r4;
#pragma unroll
        for (int n = 0; n < NN; n++) {
            int l = l0 + wl * (NN * 8) + n * 8 + 2 * c4;
            if (l < LOUT) {
                float v0 = acc[m][n][0], v2 = acc[m][n][2];
                Y[((size_t)bn * LOUT + l) * COUT + co] = v0;
                Y[((size_t)bn * LOUT + l) * COUT + co + 8] = v2;
                sacc[m][0] += v0; qacc[m][0] += v0 * v0;
                sacc[m][1] += v2; qacc[m][1] += v2 * v2;
            }
            if (l + 1 < LOUT) {
                float v1 = acc[m][n][1], v3 = acc[m][n][3];
                Y[((size_t)bn * LOUT + l + 1) * COUT + co] = v1;
                Y[((size_t)bn * LOUT + l + 1) * COUT + co + 8] = v3;
                sacc[m][0] += v1; qacc[m][0] += v1 * v1;
                sacc[m][1] += v3; qacc[m][1] += v3 * v3;
            }
        }
    }
#pragma unroll
    for (int m = 0; m < 2; m++)
#pragma unroll
        for (int hh = 0; hh < 2; hh++) {
            float s = sacc[m][hh], q = qacc[m][hh];
            s += __shfl_xor_sync(0xFFFFFFFFu, s, 1);
            s += __shfl_xor_sync(0xFFFFFFFFu, s, 2);
            q += __shfl_xor_sync(0xFFFFFFFFu, q, 1);
            q += __shfl_xor_sync(0xFFFFFFFFu, q, 2);
            if (c4 == 0) {
                int ch = wco * 32 + m * 16 + r4 + 8 * hh;
                redS[wl][ch] = s;
                redQ[wl][ch] = q;
            }
        }
    __syncthreads();
    if (tid < 64) {
        double s = (double)redS[0][tid] + redS[1][tid];
        double q = (double)redQ[0][tid] + redQ[1][tid];
        int slot = bn * gridDim.z + blockIdx.z;
        pS[(size_t)(co0 + tid) * 4096 + slot] = s;
        pQ[(size_t)(co0 + tid) * 4096 + slot] = q;
    }
}

// ---------------- BN stats finish ----------------
template <int NS>
__global__ void statsC_k(const double* __restrict__ pS, const double* __restrict__ pQ,
                         float* __restrict__ mean, float* __restrict__ istd,
                         double inv_total) {
    int c = blockIdx.x, tid = threadIdx.x;
    double s = 0.0, q = 0.0;
    for (int i = tid; i < NS; i += 256) {
        s += pS[(size_t)c * 4096 + i];
        q += pQ[(size_t)c * 4096 + i];
    }
    __shared__ double ss[256], qs[256];
    ss[tid] = s; qs[tid] = q;
    __syncthreads();
    for (int o = 128; o > 0; o >>= 1) {
        if (tid < o) { ss[tid] += ss[tid + o]; qs[tid] += qs[tid + o]; }
        __syncthreads();
    }
    if (tid == 0) {
        double m = ss[0] * inv_total;
        double var = qs[0] * inv_total - m * m;
        mean[c] = (float)m;
        istd[c] = rsqrtf((float)var + 1e-5f);
    }
}

// ---------------- fused BN + ReLU + maxpool -> interleaved, 16B vectorized ---
template <int C, int Lout, int Lp>
__global__ void bnpool_k(const float* __restrict__ X, uint2* __restrict__ YI,
                         const float* __restrict__ mean, const float* __restrict__ istd,
                         const float* __restrict__ gam, const float* __restrict__ bet) {
    constexpr int P4 = C / 4;
    size_t idx = (size_t)blockIdx.x * 256 + threadIdx.x;
    if (idx >= (size_t)kB1 * Lp * P4) return;
    int p4 = idx % P4;
    int j = (idx / P4) % Lp;
    int bn = idx / ((size_t)P4 * Lp);
    int c0 = 4 * p4;
    float sc[4], sh[4], m[4] = {0.f, 0.f, 0.f, 0.f};
#pragma unroll
    for (int e = 0; e < 4; e++) {
        sc[e] = istd[c0 + e] * gam[c0 + e];
        sh[e] = bet[c0 + e] - mean[c0 + e] * sc[e];
    }
    int l0 = 2 * j - 1, l1 = 2 * j;
    if (l0 >= 0) {
        float4 v = *(const float4*)&X[((size_t)bn * Lout + l0) * C + c0];
        float w[4] = {v.x, v.y, v.z, v.w};
#pragma unroll
        for (int e = 0; e < 4; e++) { float a = fmaf(w[e], sc[e], sh[e]); if (a > m[e]) m[e] = a; }
    }
    if (l1 < Lout) {
        float4 v = *(const float4*)&X[((size_t)bn * Lout + l1) * C + c0];
        float w[4] = {v.x, v.y, v.z, v.w};
#pragma unroll
        for (int e = 0; e < 4; e++) { float a = fmaf(w[e], sc[e], sh[e]); if (a > m[e]) m[e] = a; }
    }
    uint2 p01 = pack_hl(m[0], m[1]);
    uint2 p23 = pack_hl(m[2], m[3]);
    ((uint4*)YI)[idx] = make_uint4(p01.x, p01.y, p23.x, p23.y);
}

// ---------------- bnpool stage 3 -> flat interleaved pairs [bn][4608] --------
__global__ void bnpool3_k(const float* __restrict__ X,   // [bn][70][256]
                          uint2* __restrict__ YI,        // [bn][4608]
                          const float* __restrict__ mean, const float* __restrict__ istd,
                          const float* __restrict__ gam, const float* __restrict__ bet) {
    size_t idx = (size_t)blockIdx.x * 256 + threadIdx.x;
    if (idx >= (size_t)kB1 * 4608) return;
    int pr = idx % 4608;
    int bn = idx / 4608;
    float vv[2];
#pragma unroll
    for (int e = 0; e < 2; e++) {
        int el = 2 * pr + e;
        int c = el / 36, l = el - c * 36;
        float sc = istd[c] * gam[c];
        float sh = bet[c] - mean[c] * sc;
        float m = 0.f;
        int l0 = 2 * l - 1, l1 = 2 * l;
        if (l0 >= 0) { float v = fmaf(X[((size_t)bn * 70 + l0) * 256 + c], sc, sh); if (v > m) m = v; }
        if (l1 < 70) { float v = fmaf(X[((size_t)bn * 70 + l1) * 256 + c], sc, sh); if (v > m) m = v; }
        vv[e] = m;
    }
    YI[idx] = pack_hl(vv[0], vv[1]);
}

// ---------------- nf via HMMA: nf = spa @ mapW^T + mb, split to bf16 ---------
__global__ void __launch_bounds__(256) nf_mma_k(const uint2* __restrict__ P3I,
                                                const uint2* __restrict__ MWI,
                                                const float* __restrict__ MB,
                                                uint2* __restrict__ NFI) {
    extern __shared__ unsigned sm[];
    unsigned* spaW = sm;                 // [64][136 words]
    unsigned* mwW  = sm + 64 * 136;      // [128][136 words]
    int bp = blockIdx.x;
    int b = bp / kTC, tc = bp % kTC;
    int tid = threadIdx.x;
    unsigned smb = (unsigned)__cvta_generic_to_shared(sm);
#pragma unroll
    for (int r = 0; r < 8; r++) {
        int i = r * 256 + tid;
        int row = i >> 5, cw = i & 31;
        const uint2* src = P3I + (size_t)(b * kN + row) * 4608 + tc * 64 + 2 * cw;
        cp16(smb + (unsigned)(row * 136 + 4 * cw) * 4u, src, true);
    }
#pragma unroll
    for (int r = 0; r < 16; r++) {
        int i = r * 256 + tid;
        int row = i >> 5, cw = i & 31;
        const uint2* src = MWI + (size_t)row * 64 + 2 * cw;
        cp16(smb + (unsigned)(64 * 136 + row * 136 + 4 * cw) * 4u, src, true);
    }
    CP_COMMIT();
    asm volatile("cp.async.wait_group 0;");
    __syncthreads();

    int lane = tid & 31, wid = tid >> 5;
    int band = wid >> 1, half = wid & 1;
    int r4 = lane >> 2, c4 = lane & 3;
    float acc[8][4] = {};
#pragma unroll
    for (int kk = 0; kk < 8; kk++) {
        int arow = band * 16 + r4;
        uint2 a0 = *(const uint2*)&spaW[arow * 136 + (kk * 8 + c4) * 2];
        uint2 a1 = *(const uint2*)&spaW[(arow + 8) * 136 + (kk * 8 + c4) * 2];
        uint2 a2 = *(const uint2*)&spaW[arow * 136 + (kk * 8 + c4 + 4) * 2];
        uint2 a3 = *(const uint2*)&spaW[(arow + 8) * 136 + (kk * 8 + c4 + 4) * 2];
        unsigned ah[4] = {a0.x, a1.x, a2.x, a3.x};
        unsigned al[4] = {a0.y, a1.y, a2.y, a3.y};
#pragma unroll
        for (int f = 0; f < 8; f++) {
            int nrow = half * 64 + f * 8 + r4;
            uint2 b0 = *(const uint2*)&mwW[nrow * 136 + (kk * 8 + c4) * 2];
            uint2 b1 = *(const uint2*)&mwW[nrow * 136 + (kk * 8 + c4 + 4) * 2];
            mma16816(acc[f], ah, b0.x, b1.x);
            mma16816(acc[f], ah, b0.y, b1.y);
            mma16816(acc[f], al, b0.x, b1.x);
        }
    }
#pragma unroll
    for (int f = 0; f < 8; f++) {
        int col = half * 64 + f * 8 + 2 * c4;
        float m0 = MB[col], m1 = MB[col + 1];
        int row = band * 16 + r4;
        NFI[((size_t)bp * 64 + row) * 64 + col / 2] = pack_hl(acc[f][0] + m0, acc[f][1] + m1);
        NFI[((size_t)bp * 64 + row + 8) * 64 + col / 2] = pack_hl(acc[f][2] + m0, acc[f][3] + m1);
    }
}

// ---------------- adj via HMMA: gram + theta-map + softmax + aggregate -------
__global__ void __launch_bounds__(256) adj_mma_k(const uint2* __restrict__ NFI,
                                                 const uint2* __restrict__ TI,
                                                 const float* __restrict__ TB,
                                                 float* __restrict__ OUT) {
    extern __shared__ unsigned sm[];
    unsigned* nfW = sm;                           // [64][136 words]
    unsigned* thW = sm + 64 * 136;                // [64][136 words]
    float*    Af  = (float*)(sm + 2 * 64 * 136);  // [64][66] fp32
    unsigned* m2W = sm + 2 * 64 * 136 + 64 * 66;  // M2^T bf16 [o:64][72 words]
    unsigned* apW = m2W + 64 * 72;                // A' bf16 [n:64][72 words]
    int bp = blockIdx.x;
    int tid = threadIdx.x;
    unsigned smb = (unsigned)__cvta_generic_to_shared(sm);
#pragma unroll
    for (int r = 0; r < 8; r++) {
        int i = r * 256 + tid;
        int row = i >> 5, cw = i & 31;
        cp16(smb + (unsigned)(row * 136 + 4 * cw) * 4u,
             NFI + (size_t)bp * 4096 + row * 64 + 2 * cw, true);
    }
#pragma unroll
    for (int r = 0; r < 8; r++) {
        int i = r * 256 + tid;
        int row = i >> 5, cw = i & 31;
        cp16(smb + (unsigned)(64 * 136 + row * 136 + 4 * cw) * 4u,
             TI + (size_t)row * 64 + 2 * cw, true);
    }
    CP_COMMIT();
    asm volatile("cp.async.wait_group 0;");
    __syncthreads();

    int lane = tid & 31, wid = tid >> 5;
    int band = wid >> 1, half = wid & 1;
    int r4 = lane >> 2, c4 = lane & 3;

    {   // stage 1: A = nf@nf^T, M2 = nf@theta^T   (K=128)
        float ag[4][4] = {}, am[4][4] = {};
#pragma unroll
        for (int kk = 0; kk < 8; kk++) {
            int arow = band * 16 + r4;
            uint2 a0 = *(const uint2*)&nfW[arow * 136 + (kk * 8 + c4) * 2];
            uint2 a1 = *(const uint2*)&nfW[(arow + 8) * 136 + (kk * 8 + c4) * 2];
            uint2 a2 = *(const uint2*)&nfW[arow * 136 + (kk * 8 + c4 + 4) * 2];
            uint2 a3 = *(const uint2*)&nfW[(arow + 8) * 136 + (kk * 8 + c4 + 4) * 2];
            unsigned ah[4] = {a0.x, a1.x, a2.x, a3.x};
            unsigned al[4] = {a0.y, a1.y, a2.y, a3.y};
#pragma unroll
            for (int f = 0; f < 4; f++) {
                int nrow = half * 32 + f * 8 + r4;
                uint2 g0 = *(const uint2*)&nfW[nrow * 136 + (kk * 8 + c4) * 2];
                uint2 g1 = *(const uint2*)&nfW[nrow * 136 + (kk * 8 + c4 + 4) * 2];
                mma16816(ag[f], ah, g0.x, g1.x);
                mma16816(ag[f], ah, g0.y, g1.y);
                mma16816(ag[f], al, g0.x, g1.x);
                uint2 t0 = *(const uint2*)&thW[nrow * 136 + (kk * 8 + c4) * 2];
                uint2 t1 = *(const uint2*)&thW[nrow * 136 + (kk * 8 + c4 + 4) * 2];
                mma16816(am[f], ah, t0.x, t1.x);
                mma16816(am[f], ah, t0.y, t1.y);
                mma16816(am[f], al, t0.x, t1.x);
            }
        }
        __nv_bfloat16* m2h = (__nv_bfloat16*)m2W;
#pragma unroll
        for (int f = 0; f < 4; f++) {
            int col = half * 32 + f * 8 + 2 * c4;
#pragma unroll
            for (int q = 0; q < 4; q++) {
                int row = band * 16 + r4 + (q >> 1) * 8;
                int cc = col + (q & 1);
                float v = ag[f][q];
                Af[row * 66 + cc] = v;
                float vm = am[f][q];
                __nv_bfloat16 h = __float2bfloat16(vm);
                __nv_bfloat16 l = __float2bfloat16(vm - __bfloat162float(h));
                int wbase = cc * 72 + (row >> 1) * 2;
                m2h[wbase * 2 + (row & 1)] = h;
                m2h[(wbase + 1) * 2 + (row & 1)] = l;
            }
        }
    }
    __syncthreads();
    {   // stage 2: softmax rows of A
        int row = tid >> 2;
        int part = tid & 3;
        float vals[16];
        float mx = -3.4e38f;
#pragma unroll
        for (int jj = 0; jj < 16; jj++) {
            int col = part * 16 + jj;
            float v = Af[row * 66 + col];
            if (col == row) v -= 1e8f;
            v = v > 0.f ? v : 0.01f * v;
            vals[jj] = v;
            mx = fmaxf(mx, v);
        }
        mx = fmaxf(mx, __shfl_xor_sync(0xFFFFFFFFu, mx, 1));
        mx = fmaxf(mx, __shfl_xor_sync(0xFFFFFFFFu, mx, 2));
        float s = 0.f;
#pragma unroll
        for (int jj = 0; jj < 16; jj++) { vals[jj] = expf(vals[jj] - mx); s += vals[jj]; }
        s += __shfl_xor_sync(0xFFFFFFFFu, s, 1);
        s += __shfl_xor_sync(0xFFFFFFFFu, s, 2);
        float inv = 1.f / s;
#pragma unroll
        for (int j = 0; j < 8; j++) {
            int col = part * 16 + 2 * j;
            float v0 = vals[2 * j] * inv;
            float v1 = vals[2 * j + 1] * inv;
            if (col == row) v0 += 1.f;
            if (col + 1 == row) v1 += 1.f;
            *(uint2*)&apW[(row * 36 + part * 8 + j) * 2] = pack_hl(v0, v1);
        }
    }
    __syncthreads();
    {   // stage 3: out = A' @ M2 + tb   (K=64)
        float acc[4][4] = {};
#pragma unroll
        for (int kk = 0; kk < 4; kk++) {
            int arow = band * 16 + r4;
            uint2 a0 = *(const uint2*)&apW[arow * 72 + (kk * 8 + c4) * 2];
            uint2 a1 = *(const uint2*)&apW[(arow + 8) * 72 + (kk * 8 + c4) * 2];
            uint2 a2 = *(const uint2*)&apW[arow * 72 + (kk * 8 + c4 + 4) * 2];
            uint2 a3 = *(const uint2*)&apW[(arow + 8) * 72 + (kk * 8 + c4 + 4) * 2];
            unsigned ah[4] = {a0.x, a1.x, a2.x, a3.x};
            unsigned al[4] = {a0.y, a1.y, a2.y, a3.y};
#pragma unroll
            for (int f = 0; f < 4; f++) {
                int orow = half * 32 + f * 8 + r4;
                uint2 b0 = *(const uint2*)&m2W[orow * 72 + (kk * 8 + c4) * 2];
                uint2 b1 = *(const uint2*)&m2W[orow * 72 + (kk * 8 + c4 + 4) * 2];
                mma16816(acc[f], ah, b0.x, b1.x);
                mma16816(acc[f], ah, b0.y, b1.y);
                mma16816(acc[f], al, b0.x, b1.x);
            }
        }
#pragma unroll
        for (int f = 0; f < 4; f++) {
            int col = half * 32 + f * 8 + 2 * c4;
            float t0 = TB[col], t1 = TB[col + 1];
            int row = band * 16 + r4;
            OUT[((size_t)bp * 64 + row) * 64 + col] = acc[f][0] + t0;
            OUT[((size_t)bp * 64 + row) * 64 + col + 1] = acc[f][1] + t1;
            OUT[((size_t)bp * 64 + row + 8) * 64 + col] = acc[f][2] + t0;
            OUT[((size_t)bp * 64 + row + 8) * 64 + col + 1] = acc[f][3] + t1;
        }
    }
}

// ---------------- final BN stats, two-stage: stage A (256 chunks) ------------
__global__ void statsLA_k(const float* __restrict__ X,   // [M][64]
                          double* __restrict__ pS, double* __restrict__ pQ) {
    constexpr int M = kBP * 64;             // 73728 rows
    constexpr int RPC = M / 256;            // 288 rows per chunk
    int chunk = blockIdx.x;
    int tid = threadIdx.x;
    int c = tid & 63;                       // channel
    int rs = tid >> 6;                      // row-subgroup 0..3
    double q = 0.0, sd = 0.0;
    for (int r = rs; r < RPC; r += 4) {
        float v = X[(size_t)(chunk * RPC + r) * 64 + c];
        sd += v;
        q += (double)v * v;
    }
    __shared__ double ss[256], qs[256];
    ss[tid] = sd; qs[tid] = q;
    __syncthreads();
    if (tid < 128) { ss[tid] += ss[tid + 128]; qs[tid] += qs[tid + 128]; }
    __syncthreads();
    if (tid < 64) {
        pS[(size_t)tid * 4096 + chunk] = ss[tid] + ss[tid + 64];
        pQ[(size_t)tid * 4096 + chunk] = qs[tid] + qs[tid + 64];
    }
}

// ---------------- final: BN + leaky + pair-mean ----------------
__global__ void final_k(const float* __restrict__ Xo,
                        const float* __restrict__ mean, const float* __restrict__ istd,
                        const float* __restrict__ gam, const float* __restrict__ bet,
                        float* __restrict__ Y) {
    int idx = blockIdx.x * 256 + threadIdx.x;
    if (idx >= kBS * 36 * 64 * 64) return;
    int o = idx & 63;
    int n = (idx >> 6) & 63;
    int w = (idx >> 12) % 36;
    int b = idx / (36 * 4096);
    float sc = istd[o] * gam[o];
    float sh = bet[o] - mean[o] * sc;
    float acc = 0.f;
#pragma unroll
    for (int e = 0; e < 2; e++) {
        float v = fmaf(Xo[(((size_t)(b * kTC + 2 * w + e)) * 64 + n) * 64 + o], sc, sh);
        acc += (v > 0.f ? v : 0.01f * v);
    }
    Y[idx] = 0.5f * acc;
}

// ---------------- launch ----------------
extern "C" void kernel_launch(void* const* d_in, const int* in_sizes, int n_in,
                              void* d_out, int out_size) {
    const float* x   = (const float*)d_in[0];
    const float* w1  = (const float*)d_in[1];
    const float* g1  = (const float*)d_in[2];
    const float* b1  = (const float*)d_in[3];
    const float* w2  = (const float*)d_in[4];
    const float* g2  = (const float*)d_in[5];
    const float* b2  = (const float*)d_in[6];
    const float* w3  = (const float*)d_in[7];
    const float* g3  = (const float*)d_in[8];
    const float* b3  = (const float*)d_in[9];
    const float* mw  = (const float*)d_in[10];
    const float* mb  = (const float*)d_in[11];
    const float* tw  = (const float*)d_in[12];
    const float* tbv = (const float*)d_in[13];
    const float* bg  = (const float*)d_in[14];
    const float* bb  = (const float*)d_in[15];
    float* out = (float*)d_out;

    uint2 *xi, *p1i, *p2i, *p3i, *nfi, *w1i, *w2i, *w3i, *mwi, *ti;
    float *c1, *c2, *c3, *oo, *mn, *is;
    double *psS, *psQ;
    cudaGetSymbolAddress((void**)&xi, g_xi);
    cudaGetSymbolAddress((void**)&c1, g_c1);
    cudaGetSymbolAddress((void**)&p1i, g_p1i);
    cudaGetSymbolAddress((void**)&c2, g_c2);
    cudaGetSymbolAddress((void**)&p2i, g_p2i);
    cudaGetSymbolAddress((void**)&c3, g_c3);
    cudaGetSymbolAddress((void**)&p3i, g_p3i);
    cudaGetSymbolAddress((void**)&nfi, g_nfi);
    cudaGetSymbolAddress((void**)&oo, g_oo);
    cudaGetSymbolAddress((void**)&mn, g_mean);
    cudaGetSymbolAddress((void**)&is, g_istd);
    cudaGetSymbolAddress((void**)&psS, g_psS);
    cudaGetSymbolAddress((void**)&psQ, g_psQ);
    cudaGetSymbolAddress((void**)&w1i, g_w1i);
    cudaGetSymbolAddress((void**)&w2i, g_w2i);
    cudaGetSymbolAddress((void**)&w3i, g_w3i);
    cudaGetSymbolAddress((void**)&mwi, g_mwi);
    cudaGetSymbolAddress((void**)&ti, g_ti);

    const int C1_SMEM = (192 * 72 + 2 * 130 * 40) * 4;           // 96896 B
    const int C2_SMEM = 2 * (192 * 40 + 52 * 40) * 4;            // 78080 B
    const int C3_SMEM = 2 * (192 * 40 + 86 * 40) * 4;            // 88960 B
    const int NF_SMEM  = (64 + 128) * 136 * 4;                   // 104448 B
    const int ADJ_SMEM = (2 * 64 * 136 + 64 * 66 + 2 * 64 * 72) * 4;  // 123392 B
    cudaFuncSetAttribute(conv1_mma_k,
                         cudaFuncAttributeMaxDynamicSharedMemorySize, C1_SMEM);
    cudaFuncSetAttribute(conv_mma_k<256, 129, 128, 131, 2, 48>,
                         cudaFuncAttributeMaxDynamicSharedMemorySize, C2_SMEM);
    cudaFuncSetAttribute(conv_mma_k<128, 66, 256, 70, 3, 80>,
                         cudaFuncAttributeMaxDynamicSharedMemorySize, C3_SMEM);
    cudaFuncSetAttribute(nf_mma_k, cudaFuncAttributeMaxDynamicSharedMemorySize, NF_SMEM);
    cudaFuncSetAttribute(adj_mma_k, cudaFuncAttributeMaxDynamicSharedMemorySize, ADJ_SMEM);

    // launch order: conv1 at index 3 (ncu-profiled slot)
    prep_x_k<<<CDIV(kB1 * 256 * 16, 256), 256>>>(x, xi);                       // 0
    prep_w_k<<<CDIV(3 * 256 * 32, 256), 256>>>(w1, w1i, 256, 64);              // 1
    prep_w_k<<<CDIV(3 * 256 * 64, 256), 256>>>(w3, w3i, 256, 128);             // 2

    conv1_mma_k<<<dim3(kB1, 4, 2), 128, C1_SMEM>>>(xi, w1i, c1, psS, psQ);     // 3
    statsC_k<kB1 * 2><<<256, 256>>>(psS, psQ, mn, is, 1.0 / ((double)kB1 * 256));
    prep_w_k<<<CDIV(3 * 128 * 128, 256), 256>>>(w2, w2i, 128, 256);
    bnpool_k<256, 256, 129><<<CDIV(kB1 * 129 * 64, 256), 256>>>(c1, p1i, mn, is, g1, b1);

    conv_mma_k<256, 129, 128, 131, 2, 48>
        <<<dim3(kB1, 2, 3), 128, C2_SMEM>>>(p1i, w2i, c2, psS, psQ);
    statsC_k<kB1 * 3><<<128, 256>>>(psS, psQ, mn, is, 1.0 / ((double)kB1 * 131));
    bnpool_k<128, 131, 66><<<CDIV(kB1 * 66 * 32, 256), 256>>>(c2, p2i, mn, is, g2, b2);

    conv_mma_k<128, 66, 256, 70, 3, 80>
        <<<dim3(kB1, 4, 1), 128, C3_SMEM>>>(p2i, w3i, c3, psS, psQ);
    statsC_k<kB1><<<256, 256>>>(psS, psQ, mn, is, 1.0 / ((double)kB1 * 70));
    bnpool3_k<<<CDIV(kB1 * 4608, 256), 256>>>(c3, p3i, mn, is, g3, b3);

    // graph part (HMMA)
    prep_gw_k<<<CDIV(128 * 64, 256), 256>>>(mw, mwi, 128, 128);
    prep_gw_k<<<CDIV(64 * 64, 256), 256>>>(tw, ti, 64, 128);
    nf_mma_k<<<kBP, 256, NF_SMEM>>>(p3i, mwi, mb, nfi);
    adj_mma_k<<<kBP, 256, ADJ_SMEM>>>(nfi, ti, tbv, oo);
    statsLA_k<<<256, 256>>>(oo, psS, psQ);
    statsC_k<256><<<64, 256>>>(psS, psQ, mn, is, 1.0 / ((double)kBP * 64));
    final_k<<<CDIV(kBS * 36 * 64 * 64, 256), 256>>>(oo, mn, is, bg, bb, out);
}

// round 16
// speedup vs baseline: 1.0623x; 1.0167x over previous
#include <cuda_runtime.h>
#include <cuda_bf16.h>
#include <math.h>

#define CDIV(a,b) (((a)+(b)-1)/(b))

// ---------------- problem dims ----------------
constexpr int kBS = 16, kN = 64;
constexpr int kB1 = kBS * kN;              // 1024 sequences
constexpr int kTC = 72, kBP = kBS * kTC;   // 1152 graph batches

// ---------------- scratch ----------------
__device__ __align__(16) uint2 g_xi [(size_t)kB1 * 256 * 32];   // [bn][s][p<32]
__device__ float g_c1[(size_t)kB1 * 256 * 256];
__device__ __align__(16) uint2 g_p1i[(size_t)kB1 * 129 * 128];
__device__ float g_c2[(size_t)kB1 * 131 * 128];
__device__ __align__(16) uint2 g_p2i[(size_t)kB1 * 66 * 64];
__device__ float g_c3[(size_t)kB1 * 70 * 256];
__device__ __align__(16) uint2 g_p3i[(size_t)kB1 * 4608];       // [bn][pair<4608]
__device__ __align__(16) uint2 g_nfi[(size_t)kBP * 64 * 64];    // [bp][n][pair<64]
__device__ float g_oo[(size_t)kBP * 64 * 64];
__device__ float g_mean[256];
__device__ float g_istd[256];
__device__ double g_psS[(size_t)256 * 4096];
__device__ double g_psQ[(size_t)256 * 4096];
__device__ __align__(16) uint2 g_w1i[3 * 256 * 32];
__device__ __align__(16) uint2 g_w2i[3 * 128 * 128];
__device__ __align__(16) uint2 g_w3i[3 * 256 * 64];
__device__ __align__(16) uint2 g_mwi[128 * 64];                 // mapW [out][pair]
__device__ __align__(16) uint2 g_ti [64 * 64];                  // theta [out][pair]

// ---------------- helpers ----------------
__device__ __forceinline__ void mma16816(float* c, const unsigned* a,
                                         unsigned b0, unsigned b1) {
    asm volatile(
        "mma.sync.aligned.m16n8k16.row.col.f32.bf16.bf16.f32 "
        "{%0,%1,%2,%3}, {%4,%5,%6,%7}, {%8,%9}, {%0,%1,%2,%3};"
        : "+f"(c[0]), "+f"(c[1]), "+f"(c[2]), "+f"(c[3])
        : "r"(a[0]), "r"(a[1]), "r"(a[2]), "r"(a[3]), "r"(b0), "r"(b1));
}

__device__ __forceinline__ uint2 pack_hl(float v0, float v1) {
    __nv_bfloat16 h0 = __float2bfloat16(v0);
    __nv_bfloat16 h1 = __float2bfloat16(v1);
    __nv_bfloat16 l0 = __float2bfloat16(v0 - __bfloat162float(h0));
    __nv_bfloat16 l1 = __float2bfloat16(v1 - __bfloat162float(h1));
    uint2 r;
    r.x = (unsigned)__bfloat16_as_ushort(h0) | ((unsigned)__bfloat16_as_ushort(h1) << 16);
    r.y = (unsigned)__bfloat16_as_ushort(l0) | ((unsigned)__bfloat16_as_ushort(l1) << 16);
    return r;
}

__device__ __forceinline__ void cp16(unsigned dst, const void* src, bool full) {
    int sz = full ? 16 : 0;
    asm volatile("cp.async.ca.shared.global [%0], [%1], 16, %2;"
                 :: "r"(dst), "l"(src), "r"(sz));
}
#define CP_COMMIT() asm volatile("cp.async.commit_group;")

// ---------------- prep: x[b,s,n,d] -> xi [bn][s][p], 16B vectorized ----------
__global__ void prep_x_k(const float* __restrict__ x, uint2* __restrict__ XI) {
    size_t idx = (size_t)blockIdx.x * 256 + threadIdx.x;
    if (idx >= (size_t)kB1 * 256 * 16) return;
    int q = idx & 15;
    int s = (idx >> 4) & 255;
    int bn = idx >> 12;
    int b = bn >> 6, n = bn & 63;
    float4 v = *(const float4*)&x[(((size_t)(b * 256 + s)) * 64 + n) * 64 + 4 * q];
    uint2 p01 = pack_hl(v.x, v.y);
    uint2 p23 = pack_hl(v.z, v.w);
    ((uint4*)XI)[idx] = make_uint4(p01.x, p01.y, p23.x, p23.y);
}

// ---------------- weight prep: W[co][ci][k] -> WI[k][co][p] ----------------
__global__ void prep_w_k(const float* __restrict__ W, uint2* __restrict__ WI,
                         int COUT, int CIN) {
    int idx = blockIdx.x * 256 + threadIdx.x;
    if (idx >= COUT * CIN / 2 * 3) return;
    int P = CIN / 2;
    int p = idx % P;
    int co = (idx / P) % COUT;
    int k = idx / (P * COUT);
    float v0 = W[((size_t)co * CIN + 2 * p) * 3 + k];
    float v1 = W[((size_t)co * CIN + 2 * p + 1) * 3 + k];
    WI[idx] = pack_hl(v0, v1);
}

// ---------------- graph weight prep: W[out][in] -> [out][pair] ---------------
__global__ void prep_gw_k(const float* __restrict__ W, uint2* __restrict__ WI,
                          int OUTD, int IND) {
    int idx = blockIdx.x * 256 + threadIdx.x;
    if (idx >= OUTD * IND / 2) return;
    int P = IND / 2;
    int o = idx / P, p = idx % P;
    WI[idx] = pack_hl(W[(size_t)o * IND + 2 * p], W[(size_t)o * IND + 2 * p + 1]);
}

// ---------------- conv1 special: full-W resident, X double-buffered ----------
// LTILE=128: 128 threads (4 warps = 2co x 2l), per-warp 32co x 64l (NN=8).
// 0.5 LDS.64/MMA. smem 96896 B -> 2 blocks/SM.
__global__ void __launch_bounds__(128, 2)
conv1_mma_k(const uint2* __restrict__ XI, const uint2* __restrict__ WI,
            float* __restrict__ Y,
            double* __restrict__ pS, double* __restrict__ pQ) {
    constexpr int COUT = 256, LIN = 256, LOUT = 256, PAD = 1, LTILE = 128;
    constexpr int WRS = 72, XRS = 40, XROWS = LTILE + 2 * PAD;   // 130
    constexpr int WTW = 192 * WRS;       // 13824 words
    constexpr int XTW = XROWS * XRS;     // 5200 words
    extern __shared__ unsigned dynsm[];  // [W | X0 | X1] = 24224 words
    int bn = blockIdx.x;
    int co0 = blockIdx.y * 64;
    int l0 = blockIdx.z * LTILE;
    int tid = threadIdx.x;
    int lane = tid & 31, wid = tid >> 5;
    int wco = wid & 1, wl = wid >> 1;
    int r4 = lane >> 2, c4 = lane & 3;

    unsigned smbase = (unsigned)__cvta_generic_to_shared(dynsm);

    // W: 192 rows x 16 cp16 = 3072, exactly 24/thread
#pragma unroll
    for (int r = 0; r < 24; r++) {
        int i = r * 128 + tid;
        int row = i >> 4, cw = i & 15;
        int k = row >> 6, co = row & 63;
        const uint2* src = WI + ((size_t)(k * COUT + co0 + co)) * 32 + 2 * cw;
        cp16(smbase + (unsigned)(row * WRS + 4 * cw) * 4u, src, true);
    }
    CP_COMMIT();

    auto load_x = [&](int buf, int ci0) {
        unsigned xbase = smbase + (unsigned)(WTW + buf * XTW) * 4u;
#pragma unroll
        for (int r = 0; r < 9; r++) {
            int i = r * 128 + tid;
            if (i < XROWS * 8) {
                int row = i >> 3, cw = i & 7;
                int gl = l0 - PAD + row;
                bool ok = (gl >= 0 && gl < LIN);
                const uint2* src = ok ? XI + ((size_t)bn * LIN + gl) * 32
                                          + ci0 / 2 + 2 * cw
                                      : XI;
                cp16(xbase + (unsigned)(row * XRS + 4 * cw) * 4u, src, ok);
            }
        }
        CP_COMMIT();
    };

    float acc[2][8][4] = {};

    load_x(0, 0);
    for (int c = 0; c < 2; c++) {
        if (c == 0) {
            load_x(1, 32);
            asm volatile("cp.async.wait_group 1;");
        } else {
            asm volatile("cp.async.wait_group 0;");
        }
        __syncthreads();
        const unsigned* Ws = dynsm;
        const unsigned* Xs = dynsm + WTW + c * XTW;
#pragma unroll
        for (int k = 0; k < 3; k++) {
#pragma unroll
            for (int h = 0; h < 2; h++) {
                int pwb = 2 * (h * 8 + c4);
                int pwa = 32 * c + pwb;
                unsigned ah[2][4], al[2][4];
#pragma unroll
                for (int m = 0; m < 2; m++) {
                    int row = wco * 32 + m * 16 + r4;
                    int base = (k * 64 + row) * WRS + pwa;
                    uint2 a00 = *(const uint2*)&Ws[base];
                    uint2 a10 = *(const uint2*)&Ws[base + 8 * WRS];
                    uint2 a01 = *(const uint2*)&Ws[base + 8];
                    uint2 a11 = *(const uint2*)&Ws[base + 8 * WRS + 8];
                    ah[m][0] = a00.x; ah[m][1] = a10.x; ah[m][2] = a01.x; ah[m][3] = a11.x;
                    al[m][0] = a00.y; al[m][1] = a10.y; al[m][2] = a01.y; al[m][3] = a11.y;
                }
#pragma unroll
                for (int n = 0; n < 8; n++) {
                    int lrow = wl * 64 + n * 8 + r4 + k;
                    int bb = lrow * XRS + pwb;
                    uint2 b0 = *(const uint2*)&Xs[bb];
                    uint2 b1 = *(const uint2*)&Xs[bb + 8];
#pragma unroll
                    for (int m = 0; m < 2; m++) {
                        mma16816(acc[m][n], ah[m], b0.x, b1.x);
                        mma16816(acc[m][n], ah[m], b0.y, b1.y);
                        mma16816(acc[m][n], al[m], b0.x, b1.x);
                    }
                }
            }
        }
        __syncthreads();
    }

    // epilogue: Y stores + fused stats (reduction arrays reuse dynsm)
    float* redS = (float*)dynsm;          // [2][64]
    float* redQ = redS + 128;             // [2][64]
    float sacc[2][2] = {}, qacc[2][2] = {};
#pragma unroll
    for (int m = 0; m < 2; m++) {
        int co = co0 + wco * 32 + m * 16 + r4;
#pragma unroll
        for (int n = 0; n < 8; n++) {
            int l = l0 + wl * 64 + n * 8 + 2 * c4;
            float v0 = acc[m][n][0], v1 = acc[m][n][1];
            float v2 = acc[m][n][2], v3 = acc[m][n][3];
            Y[((size_t)bn * LOUT + l) * COUT + co] = v0;
            Y[((size_t)bn * LOUT + l) * COUT + co + 8] = v2;
            Y[((size_t)bn * LOUT + l + 1) * COUT + co] = v1;
            Y[((size_t)bn * LOUT + l + 1) * COUT + co + 8] = v3;
            sacc[m][0] += v0 + v1; qacc[m][0] += v0 * v0 + v1 * v1;
            sacc[m][1] += v2 + v3; qacc[m][1] += v2 * v2 + v3 * v3;
        }
    }
#pragma unroll
    for (int m = 0; m < 2; m++)
#pragma unroll
        for (int hh = 0; hh < 2; hh++) {
            float s = sacc[m][hh], q = qacc[m][hh];
            s += __shfl_xor_sync(0xFFFFFFFFu, s, 1);
            s += __shfl_xor_sync(0xFFFFFFFFu, s, 2);
            q += __shfl_xor_sync(0xFFFFFFFFu, q, 1);
            q += __shfl_xor_sync(0xFFFFFFFFu, q, 2);
            if (c4 == 0) {
                int ch = wco * 32 + m * 16 + r4 + 8 * hh;
                redS[wl * 64 + ch] = s;
                redQ[wl * 64 + ch] = q;
            }
        }
    __syncthreads();
    if (tid < 64) {
        double s = (double)redS[tid] + redS[64 + tid];
        double q = (double)redQ[tid] + redQ[64 + tid];
        int slot = bn * gridDim.z + blockIdx.z;
        pS[(size_t)(co0 + tid) * 4096 + slot] = s;
        pQ[(size_t)(co0 + tid) * 4096 + slot] = q;
    }
}

// ---------------- generic conv1d via HMMA, cp.async double-buffered ----------
template <int CIN, int LIN, int COUT, int LOUT, int PAD, int LTILE>
__global__ void __launch_bounds__(128, 2)
conv_mma_k(const uint2* __restrict__ XI,
           const uint2* __restrict__ WI,
           float* __restrict__ Y,
           double* __restrict__ pS, double* __restrict__ pQ) {
    constexpr int RS = 40;
    constexpr int NN = LTILE / 16;
    constexpr int XROWS = LTILE + 2 * PAD;
    constexpr int WTW = 192 * RS;
    constexpr int XTW = XROWS * RS;
    constexpr int NCHUNK = CIN / 32;
    constexpr int XCNT = CDIV(XROWS * 8, 128);
    extern __shared__ unsigned dynsm[];
    __shared__ float redS[2][64], redQ[2][64];
    int bn = blockIdx.x;
    int co0 = blockIdx.y * 64;
    int l0 = blockIdx.z * LTILE;
    int tid = threadIdx.x;
    int lane = tid & 31, wid = tid >> 5;
    int wco = wid & 1, wl = wid >> 1;
    int r4 = lane >> 2, c4 = lane & 3;

    unsigned smbase = (unsigned)__cvta_generic_to_shared(dynsm);
    auto wb = [&](int buf) { return smbase + (unsigned)(buf * (WTW + XTW)) * 4u; };
    auto xb = [&](int buf) { return wb(buf) + (unsigned)WTW * 4u; };

    auto load_chunk = [&](int buf, int ci0) {
        unsigned wbase = wb(buf), xbase = xb(buf);
#pragma unroll
        for (int r = 0; r < 12; r++) {
            int i = r * 128 + tid;
            int row = i >> 3, cw = i & 7;
            int k = row >> 6, co = row & 63;
            const uint2* src = WI + ((size_t)(k * COUT + co0 + co)) * (CIN / 2)
                               + ci0 / 2 + 2 * cw;
            cp16(wbase + (unsigned)(row * RS + 4 * cw) * 4u, src, true);
        }
#pragma unroll
        for (int r = 0; r < XCNT; r++) {
            int i = r * 128 + tid;
            if (i < XROWS * 8) {
                int row = i >> 3, cw = i & 7;
                int gl = l0 - PAD + row;
                bool ok = (gl >= 0 && gl < LIN);
                const uint2* src = ok ? XI + ((size_t)bn * LIN + gl) * (CIN / 2)
                                          + ci0 / 2 + 2 * cw
                                      : XI;
                cp16(xbase + (unsigned)(row * RS + 4 * cw) * 4u, src, ok);
            }
        }
        CP_COMMIT();
    };

    float acc[2][NN][4];
#pragma unroll
    for (int m = 0; m < 2; m++)
#pragma unroll
        for (int n = 0; n < NN; n++)
#pragma unroll
            for (int q = 0; q < 4; q++) acc[m][n][q] = 0.f;

    load_chunk(0, 0);
    for (int c = 0; c < NCHUNK; c++) {
        int cb = c & 1;
        if (c + 1 < NCHUNK) {
            load_chunk((c + 1) & 1, (c + 1) * 32);
            asm volatile("cp.async.wait_group 1;");
        } else {
            asm volatile("cp.async.wait_group 0;");
        }
        __syncthreads();

        const unsigned* Ws = dynsm + cb * (WTW + XTW);
        const unsigned* Xs = Ws + WTW;
#pragma unroll
        for (int k = 0; k < 3; k++) {
#pragma unroll
            for (int h = 0; h < 2; h++) {
                int pw = 2 * (h * 8 + c4);
                unsigned ah[2][4], al[2][4];
#pragma unroll
                for (int m = 0; m < 2; m++) {
                    int row = wco * 32 + m * 16 + r4;
                    int base = (k * 64 + row) * RS + pw;
                    uint2 a00 = *(const uint2*)&Ws[base];
                    uint2 a10 = *(const uint2*)&Ws[base + 8 * RS];
                    uint2 a01 = *(const uint2*)&Ws[base + 8];
                    uint2 a11 = *(const uint2*)&Ws[base + 8 * RS + 8];
                    ah[m][0] = a00.x; ah[m][1] = a10.x; ah[m][2] = a01.x; ah[m][3] = a11.x;
                    al[m][0] = a00.y; al[m][1] = a10.y; al[m][2] = a01.y; al[m][3] = a11.y;
                }
#pragma unroll
                for (int n = 0; n < NN; n++) {
                    int lrow = wl * (NN * 8) + n * 8 + r4 + k;
                    int bb = lrow * RS + pw;
                    uint2 b0 = *(const uint2*)&Xs[bb];
                    uint2 b1 = *(const uint2*)&Xs[bb + 8];
#pragma unroll
                    for (int m = 0; m < 2; m++) {
                        mma16816(acc[m][n], ah[m], b0.x, b1.x);
                        mma16816(acc[m][n], ah[m], b0.y, b1.y);
                        mma16816(acc[m][n], al[m], b0.x, b1.x);
                    }
                }
            }
        }
        __syncthreads();
    }

    float sacc[2][2] = {}, qacc[2][2] = {};
#pragma unroll
    for (int m = 0; m < 2; m++) {
        int co = co0 + wco * 32 + m * 16 + r4;
#pragma unroll
        for (int n = 0; n < NN; n++) {
            int l = l0 + wl * (NN * 8) + n * 8 + 2 * c4;
            if (l < LOUT) {
                float v0 = acc[m][n][0], v2 = acc[m][n][2];
                Y[((size_t)bn * LOUT + l) * COUT + co] = v0;
                Y[((size_t)bn * LOUT + l) * COUT + co + 8] = v2;
                sacc[m][0] += v0; qacc[m][0] += v0 * v0;
                sacc[m][1] += v2; qacc[m][1] += v2 * v2;
            }
            if (l + 1 < LOUT) {
                float v1 = acc[m][n][1], v3 = acc[m][n][3];
                Y[((size_t)bn * LOUT + l + 1) * COUT + co] = v1;
                Y[((size_t)bn * LOUT + l + 1) * COUT + co + 8] = v3;
                sacc[m][0] += v1; qacc[m][0] += v1 * v1;
                sacc[m][1] += v3; qacc[m][1] += v3 * v3;
            }
        }
    }
#pragma unroll
    for (int m = 0; m < 2; m++)
#pragma unroll
        for (int hh = 0; hh < 2; hh++) {
            float s = sacc[m][hh], q = qacc[m][hh];
            s += __shfl_xor_sync(0xFFFFFFFFu, s, 1);
            s += __shfl_xor_sync(0xFFFFFFFFu, s, 2);
            q += __shfl_xor_sync(0xFFFFFFFFu, q, 1);
            q += __shfl_xor_sync(0xFFFFFFFFu, q, 2);
            if (c4 == 0) {
                int ch = wco * 32 + m * 16 + r4 + 8 * hh;
                redS[wl][ch] = s;
                redQ[wl][ch] = q;
            }
        }
    __syncthreads();
    if (tid < 64) {
        double s = (double)redS[0][tid] + redS[1][tid];
        double q = (double)redQ[0][tid] + redQ[1][tid];
        int slot = bn * gridDim.z + blockIdx.z;
        pS[(size_t)(co0 + tid) * 4096 + slot] = s;
        pQ[(size_t)(co0 + tid) * 4096 + slot] = q;
    }
}

// ---------------- BN stats finish ----------------
template <int NS>
__global__ void statsC_k(const double* __restrict__ pS, const double* __restrict__ pQ,
                         float* __restrict__ mean, float* __restrict__ istd,
                         double inv_total) {
    int c = blockIdx.x, tid = threadIdx.x;
    double s = 0.0, q = 0.0;
    for (int i = tid; i < NS; i += 256) {
        s += pS[(size_t)c * 4096 + i];
        q += pQ[(size_t)c * 4096 + i];
    }
    __shared__ double ss[256], qs[256];
    ss[tid] = s; qs[tid] = q;
    __syncthreads();
    for (int o = 128; o > 0; o >>= 1) {
        if (tid < o) { ss[tid] += ss[tid + o]; qs[tid] += qs[tid + o]; }
        __syncthreads();
    }
    if (tid == 0) {
        double m = ss[0] * inv_total;
        double var = qs[0] * inv_total - m * m;
        mean[c] = (float)m;
        istd[c] = rsqrtf((float)var + 1e-5f);
    }
}

// ---------------- fused BN + ReLU + maxpool -> interleaved, 16B vectorized ---
template <int C, int Lout, int Lp>
__global__ void bnpool_k(const float* __restrict__ X, uint2* __restrict__ YI,
                         const float* __restrict__ mean, const float* __restrict__ istd,
                         const float* __restrict__ gam, const float* __restrict__ bet) {
    constexpr int P4 = C / 4;
    size_t idx = (size_t)blockIdx.x * 256 + threadIdx.x;
    if (idx >= (size_t)kB1 * Lp * P4) return;
    int p4 = idx % P4;
    int j = (idx / P4) % Lp;
    int bn = idx / ((size_t)P4 * Lp);
    int c0 = 4 * p4;
    float sc[4], sh[4], m[4] = {0.f, 0.f, 0.f, 0.f};
#pragma unroll
    for (int e = 0; e < 4; e++) {
        sc[e] = istd[c0 + e] * gam[c0 + e];
        sh[e] = bet[c0 + e] - mean[c0 + e] * sc[e];
    }
    int l0 = 2 * j - 1, l1 = 2 * j;
    if (l0 >= 0) {
        float4 v = *(const float4*)&X[((size_t)bn * Lout + l0) * C + c0];
        float w[4] = {v.x, v.y, v.z, v.w};
#pragma unroll
        for (int e = 0; e < 4; e++) { float a = fmaf(w[e], sc[e], sh[e]); if (a > m[e]) m[e] = a; }
    }
    if (l1 < Lout) {
        float4 v = *(const float4*)&X[((size_t)bn * Lout + l1) * C + c0];
        float w[4] = {v.x, v.y, v.z, v.w};
#pragma unroll
        for (int e = 0; e < 4; e++) { float a = fmaf(w[e], sc[e], sh[e]); if (a > m[e]) m[e] = a; }
    }
    uint2 p01 = pack_hl(m[0], m[1]);
    uint2 p23 = pack_hl(m[2], m[3]);
    ((uint4*)YI)[idx] = make_uint4(p01.x, p01.y, p23.x, p23.y);
}

// ---------------- bnpool stage 3 -> flat interleaved pairs [bn][4608] --------
__global__ void bnpool3_k(const float* __restrict__ X,   // [bn][70][256]
                          uint2* __restrict__ YI,        // [bn][4608]
                          const float* __restrict__ mean, const float* __restrict__ istd,
                          const float* __restrict__ gam, const float* __restrict__ bet) {
    size_t idx = (size_t)blockIdx.x * 256 + threadIdx.x;
    if (idx >= (size_t)kB1 * 4608) return;
    int pr = idx % 4608;
    int bn = idx / 4608;
    float vv[2];
#pragma unroll
    for (int e = 0; e < 2; e++) {
        int el = 2 * pr + e;
        int c = el / 36, l = el - c * 36;
        float sc = istd[c] * gam[c];
        float sh = bet[c] - mean[c] * sc;
        float m = 0.f;
        int l0 = 2 * l - 1, l1 = 2 * l;
        if (l0 >= 0) { float v = fmaf(X[((size_t)bn * 70 + l0) * 256 + c], sc, sh); if (v > m) m = v; }
        if (l1 < 70) { float v = fmaf(X[((size_t)bn * 70 + l1) * 256 + c], sc, sh); if (v > m) m = v; }
        vv[e] = m;
    }
    YI[idx] = pack_hl(vv[0], vv[1]);
}

// ---------------- nf via HMMA: nf = spa @ mapW^T + mb, split to bf16 ---------
__global__ void __launch_bounds__(256) nf_mma_k(const uint2* __restrict__ P3I,
                                                const uint2* __restrict__ MWI,
                                                const float* __restrict__ MB,
                                                uint2* __restrict__ NFI) {
    extern __shared__ unsigned sm[];
    unsigned* spaW = sm;                 // [64][136 words]
    unsigned* mwW  = sm + 64 * 136;      // [128][136 words]
    int bp = blockIdx.x;
    int b = bp / kTC, tc = bp % kTC;
    int tid = threadIdx.x;
    unsigned smb = (unsigned)__cvta_generic_to_shared(sm);
#pragma unroll
    for (int r = 0; r < 8; r++) {
        int i = r * 256 + tid;
        int row = i >> 5, cw = i & 31;
        const uint2* src = P3I + (size_t)(b * kN + row) * 4608 + tc * 64 + 2 * cw;
        cp16(smb + (unsigned)(row * 136 + 4 * cw) * 4u, src, true);
    }
#pragma unroll
    for (int r = 0; r < 16; r++) {
        int i = r * 256 + tid;
        int row = i >> 5, cw = i & 31;
        const uint2* src = MWI + (size_t)row * 64 + 2 * cw;
        cp16(smb + (unsigned)(64 * 136 + row * 136 + 4 * cw) * 4u, src, true);
    }
    CP_COMMIT();
    asm volatile("cp.async.wait_group 0;");
    __syncthreads();

    int lane = tid & 31, wid = tid >> 5;
    int band = wid >> 1, half = wid & 1;
    int r4 = lane >> 2, c4 = lane & 3;
    float acc[8][4] = {};
#pragma unroll
    for (int kk = 0; kk < 8; kk++) {
        int arow = band * 16 + r4;
        uint2 a0 = *(const uint2*)&spaW[arow * 136 + (kk * 8 + c4) * 2];
        uint2 a1 = *(const uint2*)&spaW[(arow + 8) * 136 + (kk * 8 + c4) * 2];
        uint2 a2 = *(const uint2*)&spaW[arow * 136 + (kk * 8 + c4 + 4) * 2];
        uint2 a3 = *(const uint2*)&spaW[(arow + 8) * 136 + (kk * 8 + c4 + 4) * 2];
        unsigned ah[4] = {a0.x, a1.x, a2.x, a3.x};
        unsigned al[4] = {a0.y, a1.y, a2.y, a3.y};
#pragma unroll
        for (int f = 0; f < 8; f++) {
            int nrow = half * 64 + f * 8 + r4;
            uint2 b0 = *(const uint2*)&mwW[nrow * 136 + (kk * 8 + c4) * 2];
            uint2 b1 = *(const uint2*)&mwW[nrow * 136 + (kk * 8 + c4 + 4) * 2];
            mma16816(acc[f], ah, b0.x, b1.x);
            mma16816(acc[f], ah, b0.y, b1.y);
            mma16816(acc[f], al, b0.x, b1.x);
        }
    }
#pragma unroll
    for (int f = 0; f < 8; f++) {
        int col = half * 64 + f * 8 + 2 * c4;
        float m0 = MB[col], m1 = MB[col + 1];
        int row = band * 16 + r4;
        NFI[((size_t)bp * 64 + row) * 64 + col / 2] = pack_hl(acc[f][0] + m0, acc[f][1] + m1);
        NFI[((size_t)bp * 64 + row + 8) * 64 + col / 2] = pack_hl(acc[f][2] + m0, acc[f][3] + m1);
    }
}

// ---------------- adj via HMMA: gram + theta-map + softmax + aggregate -------
__global__ void __launch_bounds__(256) adj_mma_k(const uint2* __restrict__ NFI,
                                                 const uint2* __restrict__ TI,
                                                 const float* __restrict__ TB,
                                                 float* __restrict__ OUT) {
    extern __shared__ unsigned sm[];
    unsigned* nfW = sm;                           // [64][136 words]
    unsigned* thW = sm + 64 * 136;                // [64][136 words]
    float*    Af  = (float*)(sm + 2 * 64 * 136);  // [64][66] fp32
    unsigned* m2W = sm + 2 * 64 * 136 + 64 * 66;  // M2^T bf16 [o:64][72 words]
    unsigned* apW = m2W + 64 * 72;                // A' bf16 [n:64][72 words]
    int bp = blockIdx.x;
    int tid = threadIdx.x;
    unsigned smb = (unsigned)__cvta_generic_to_shared(sm);
#pragma unroll
    for (int r = 0; r < 8; r++) {
        int i = r * 256 + tid;
        int row = i >> 5, cw = i & 31;
        cp16(smb + (unsigned)(row * 136 + 4 * cw) * 4u,
             NFI + (size_t)bp * 4096 + row * 64 + 2 * cw, true);
    }
#pragma unroll
    for (int r = 0; r < 8; r++) {
        int i = r * 256 + tid;
        int row = i >> 5, cw = i & 31;
        cp16(smb + (unsigned)(64 * 136 + row * 136 + 4 * cw) * 4u,
             TI + (size_t)row * 64 + 2 * cw, true);
    }
    CP_COMMIT();
    asm volatile("cp.async.wait_group 0;");
    __syncthreads();

    int lane = tid & 31, wid = tid >> 5;
    int band = wid >> 1, half = wid & 1;
    int r4 = lane >> 2, c4 = lane & 3;

    {   // stage 1: A = nf@nf^T, M2 = nf@theta^T   (K=128)
        float ag[4][4] = {}, am[4][4] = {};
#pragma unroll
        for (int kk = 0; kk < 8; kk++) {
            int arow = band * 16 + r4;
            uint2 a0 = *(const uint2*)&nfW[arow * 136 + (kk * 8 + c4) * 2];
            uint2 a1 = *(const uint2*)&nfW[(arow + 8) * 136 + (kk * 8 + c4) * 2];
            uint2 a2 = *(const uint2*)&nfW[arow * 136 + (kk * 8 + c4 + 4) * 2];
            uint2 a3 = *(const uint2*)&nfW[(arow + 8) * 136 + (kk * 8 + c4 + 4) * 2];
            unsigned ah[4] = {a0.x, a1.x, a2.x, a3.x};
            unsigned al[4] = {a0.y, a1.y, a2.y, a3.y};
#pragma unroll
            for (int f = 0; f < 4; f++) {
                int nrow = half * 32 + f * 8 + r4;
                uint2 g0 = *(const uint2*)&nfW[nrow * 136 + (kk * 8 + c4) * 2];
                uint2 g1 = *(const uint2*)&nfW[nrow * 136 + (kk * 8 + c4 + 4) * 2];
                mma16816(ag[f], ah, g0.x, g1.x);
                mma16816(ag[f], ah, g0.y, g1.y);
                mma16816(ag[f], al, g0.x, g1.x);
                uint2 t0 = *(const uint2*)&thW[nrow * 136 + (kk * 8 + c4) * 2];
                uint2 t1 = *(const uint2*)&thW[nrow * 136 + (kk * 8 + c4 + 4) * 2];
                mma16816(am[f], ah, t0.x, t1.x);
                mma16816(am[f], ah, t0.y, t1.y);
                mma16816(am[f], al, t0.x, t1.x);
            }
        }
        __nv_bfloat16* m2h = (__nv_bfloat16*)m2W;
#pragma unroll
        for (int f = 0; f < 4; f++) {
            int col = half * 32 + f * 8 + 2 * c4;
#pragma unroll
            for (int q = 0; q < 4; q++) {
                int row = band * 16 + r4 + (q >> 1) * 8;
                int cc = col + (q & 1);
                float v = ag[f][q];
                Af[row * 66 + cc] = v;
                float vm = am[f][q];
                __nv_bfloat16 h = __float2bfloat16(vm);
                __nv_bfloat16 l = __float2bfloat16(vm - __bfloat162float(h));
                int wbase = cc * 72 + (row >> 1) * 2;
                m2h[wbase * 2 + (row & 1)] = h;
                m2h[(wbase + 1) * 2 + (row & 1)] = l;
            }
        }
    }
    __syncthreads();
    {   // stage 2: softmax rows of A
        int row = tid >> 2;
        int part = tid & 3;
        float vals[16];
        float mx = -3.4e38f;
#pragma unroll
        for (int jj = 0; jj < 16; jj++) {
            int col = part * 16 + jj;
            float v = Af[row * 66 + col];
            if (col == row) v -= 1e8f;
            v = v > 0.f ? v : 0.01f * v;
            vals[jj] = v;
            mx = fmaxf(mx, v);
        }
        mx = fmaxf(mx, __shfl_xor_sync(0xFFFFFFFFu, mx, 1));
        mx = fmaxf(mx, __shfl_xor_sync(0xFFFFFFFFu, mx, 2));
        float s = 0.f;
#pragma unroll
        for (int jj = 0; jj < 16; jj++) { vals[jj] = expf(vals[jj] - mx); s += vals[jj]; }
        s += __shfl_xor_sync(0xFFFFFFFFu, s, 1);
        s += __shfl_xor_sync(0xFFFFFFFFu, s, 2);
        float inv = 1.f / s;
#pragma unroll
        for (int j = 0; j < 8; j++) {
            int col = part * 16 + 2 * j;
            float v0 = vals[2 * j] * inv;
            float v1 = vals[2 * j + 1] * inv;
            if (col == row) v0 += 1.f;
            if (col + 1 == row) v1 += 1.f;
            *(uint2*)&apW[(row * 36 + part * 8 + j) * 2] = pack_hl(v0, v1);
        }
    }
    __syncthreads();
    {   // stage 3: out = A' @ M2 + tb   (K=64)
        float acc[4][4] = {};
#pragma unroll
        for (int kk = 0; kk < 4; kk++) {
            int arow = band * 16 + r4;
            uint2 a0 = *(const uint2*)&apW[arow * 72 + (kk * 8 + c4) * 2];
            uint2 a1 = *(const uint2*)&apW[(arow + 8) * 72 + (kk * 8 + c4) * 2];
            uint2 a2 = *(const uint2*)&apW[arow * 72 + (kk * 8 + c4 + 4) * 2];
            uint2 a3 = *(const uint2*)&apW[(arow + 8) * 72 + (kk * 8 + c4 + 4) * 2];
            unsigned ah[4] = {a0.x, a1.x, a2.x, a3.x};
            unsigned al[4] = {a0.y, a1.y, a2.y, a3.y};
#pragma unroll
            for (int f = 0; f < 4; f++) {
                int orow = half * 32 + f * 8 + r4;
                uint2 b0 = *(const uint2*)&m2W[orow * 72 + (kk * 8 + c4) * 2];
                uint2 b1 = *(const uint2*)&m2W[orow * 72 + (kk * 8 + c4 + 4) * 2];
                mma16816(acc[f], ah, b0.x, b1.x);
                mma16816(acc[f], ah, b0.y, b1.y);
                mma16816(acc[f], al, b0.x, b1.x);
            }
        }
#pragma unroll
        for (int f = 0; f < 4; f++) {
            int col = half * 32 + f * 8 + 2 * c4;
            float t0 = TB[col], t1 = TB[col + 1];
            int row = band * 16 + r4;
            OUT[((size_t)bp * 64 + row) * 64 + col] = acc[f][0] + t0;
            OUT[((size_t)bp * 64 + row) * 64 + col + 1] = acc[f][1] + t1;
            OUT[((size_t)bp * 64 + row + 8) * 64 + col] = acc[f][2] + t0;
            OUT[((size_t)bp * 64 + row + 8) * 64 + col + 1] = acc[f][3] + t1;
        }
    }
}

// ---------------- final BN stats, two-stage: stage A (256 chunks) ------------
__global__ void statsLA_k(const float* __restrict__ X,   // [M][64]
                          double* __restrict__ pS, double* __restrict__ pQ) {
    constexpr int M = kBP * 64;             // 73728 rows
    constexpr int RPC = M / 256;            // 288 rows per chunk
    int chunk = blockIdx.x;
    int tid = threadIdx.x;
    int c = tid & 63;                       // channel
    int rs = tid >> 6;                      // row-subgroup 0..3
    double q = 0.0, sd = 0.0;
    for (int r = rs; r < RPC; r += 4) {
        float v = X[(size_t)(chunk * RPC + r) * 64 + c];
        sd += v;
        q += (double)v * v;
    }
    __shared__ double ss[256], qs[256];
    ss[tid] = sd; qs[tid] = q;
    __syncthreads();
    if (tid < 128) { ss[tid] += ss[tid + 128]; qs[tid] += qs[tid + 128]; }
    __syncthreads();
    if (tid < 64) {
        pS[(size_t)tid * 4096 + chunk] = ss[tid] + ss[tid + 64];
        pQ[(size_t)tid * 4096 + chunk] = qs[tid] + qs[tid + 64];
    }
}

// ---------------- final: BN + leaky + pair-mean ----------------
__global__ void final_k(const float* __restrict__ Xo,
                        const float* __restrict__ mean, const float* __restrict__ istd,
                        const float* __restrict__ gam, const float* __restrict__ bet,
                        float* __restrict__ Y) {
    int idx = blockIdx.x * 256 + threadIdx.x;
    if (idx >= kBS * 36 * 64 * 64) return;
    int o = idx & 63;
    int n = (idx >> 6) & 63;
    int w = (idx >> 12) % 36;
    int b = idx / (36 * 4096);
    float sc = istd[o] * gam[o];
    float sh = bet[o] - mean[o] * sc;
    float acc = 0.f;
#pragma unroll
    for (int e = 0; e < 2; e++) {
        float v = fmaf(Xo[(((size_t)(b * kTC + 2 * w + e)) * 64 + n) * 64 + o], sc, sh);
        acc += (v > 0.f ? v : 0.01f * v);
    }
    Y[idx] = 0.5f * acc;
}

// ---------------- launch ----------------
extern "C" void kernel_launch(void* const* d_in, const int* in_sizes, int n_in,
                              void* d_out, int out_size) {
    const float* x   = (const float*)d_in[0];
    const float* w1  = (const float*)d_in[1];
    const float* g1  = (const float*)d_in[2];
    const float* b1  = (const float*)d_in[3];
    const float* w2  = (const float*)d_in[4];
    const float* g2  = (const float*)d_in[5];
    const float* b2  = (const float*)d_in[6];
    const float* w3  = (const float*)d_in[7];
    const float* g3  = (const float*)d_in[8];
    const float* b3  = (const float*)d_in[9];
    const float* mw  = (const float*)d_in[10];
    const float* mb  = (const float*)d_in[11];
    const float* tw  = (const float*)d_in[12];
    const float* tbv = (const float*)d_in[13];
    const float* bg  = (const float*)d_in[14];
    const float* bb  = (const float*)d_in[15];
    float* out = (float*)d_out;

    uint2 *xi, *p1i, *p2i, *p3i, *nfi, *w1i, *w2i, *w3i, *mwi, *ti;
    float *c1, *c2, *c3, *oo, *mn, *is;
    double *psS, *psQ;
    cudaGetSymbolAddress((void**)&xi, g_xi);
    cudaGetSymbolAddress((void**)&c1, g_c1);
    cudaGetSymbolAddress((void**)&p1i, g_p1i);
    cudaGetSymbolAddress((void**)&c2, g_c2);
    cudaGetSymbolAddress((void**)&p2i, g_p2i);
    cudaGetSymbolAddress((void**)&c3, g_c3);
    cudaGetSymbolAddress((void**)&p3i, g_p3i);
    cudaGetSymbolAddress((void**)&nfi, g_nfi);
    cudaGetSymbolAddress((void**)&oo, g_oo);
    cudaGetSymbolAddress((void**)&mn, g_mean);
    cudaGetSymbolAddress((void**)&is, g_istd);
    cudaGetSymbolAddress((void**)&psS, g_psS);
    cudaGetSymbolAddress((void**)&psQ, g_psQ);
    cudaGetSymbolAddress((void**)&w1i, g_w1i);
    cudaGetSymbolAddress((void**)&w2i, g_w2i);
    cudaGetSymbolAddress((void**)&w3i, g_w3i);
    cudaGetSymbolAddress((void**)&mwi, g_mwi);
    cudaGetSymbolAddress((void**)&ti, g_ti);

    const int C1_SMEM = (192 * 72 + 2 * 130 * 40) * 4;           // 96896 B
    const int C2_SMEM = 2 * (192 * 40 + 148 * 40) * 4;           // 108800 B
    const int C3_SMEM = 2 * (192 * 40 + 86 * 40) * 4;            // 88960 B
    const int NF_SMEM  = (64 + 128) * 136 * 4;                   // 104448 B
    const int ADJ_SMEM = (2 * 64 * 136 + 64 * 66 + 2 * 64 * 72) * 4;  // 123392 B
    cudaFuncSetAttribute(conv1_mma_k,
                         cudaFuncAttributeMaxDynamicSharedMemorySize, C1_SMEM);
    cudaFuncSetAttribute(conv_mma_k<256, 129, 128, 131, 2, 144>,
                         cudaFuncAttributeMaxDynamicSharedMemorySize, C2_SMEM);
    cudaFuncSetAttribute(conv_mma_k<128, 66, 256, 70, 3, 80>,
                         cudaFuncAttributeMaxDynamicSharedMemorySize, C3_SMEM);
    cudaFuncSetAttribute(nf_mma_k, cudaFuncAttributeMaxDynamicSharedMemorySize, NF_SMEM);
    cudaFuncSetAttribute(adj_mma_k, cudaFuncAttributeMaxDynamicSharedMemorySize, ADJ_SMEM);

    // launch order: conv1 at index 3 (ncu-profiled slot)
    prep_x_k<<<CDIV(kB1 * 256 * 16, 256), 256>>>(x, xi);                       // 0
    prep_w_k<<<CDIV(3 * 256 * 32, 256), 256>>>(w1, w1i, 256, 64);              // 1
    prep_w_k<<<CDIV(3 * 256 * 64, 256), 256>>>(w3, w3i, 256, 128);             // 2

    conv1_mma_k<<<dim3(kB1, 4, 2), 128, C1_SMEM>>>(xi, w1i, c1, psS, psQ);     // 3
    statsC_k<kB1 * 2><<<256, 256>>>(psS, psQ, mn, is, 1.0 / ((double)kB1 * 256));
    prep_w_k<<<CDIV(3 * 128 * 128, 256), 256>>>(w2, w2i, 128, 256);
    bnpool_k<256, 256, 129><<<CDIV(kB1 * 129 * 64, 256), 256>>>(c1, p1i, mn, is, g1, b1);

    conv_mma_k<256, 129, 128, 131, 2, 144>
        <<<dim3(kB1, 2, 1), 128, C2_SMEM>>>(p1i, w2i, c2, psS, psQ);
    statsC_k<kB1><<<128, 256>>>(psS, psQ, mn, is, 1.0 / ((double)kB1 * 131));
    bnpool_k<128, 131, 66><<<CDIV(kB1 * 66 * 32, 256), 256>>>(c2, p2i, mn, is, g2, b2);

    conv_mma_k<128, 66, 256, 70, 3, 80>
        <<<dim3(kB1, 4, 1), 128, C3_SMEM>>>(p2i, w3i, c3, psS, psQ);
    statsC_k<kB1><<<256, 256>>>(psS, psQ, mn, is, 1.0 / ((double)kB1 * 70));
    bnpool3_k<<<CDIV(kB1 * 4608, 256), 256>>>(c3, p3i, mn, is, g3, b3);

    // graph part (HMMA)
    prep_gw_k<<<CDIV(128 * 64, 256), 256>>>(mw, mwi, 128, 128);
    prep_gw_k<<<CDIV(64 * 64, 256), 256>>>(tw, ti, 64, 128);
    nf_mma_k<<<kBP, 256, NF_SMEM>>>(p3i, mwi, mb, nfi);
    adj_mma_k<<<kBP, 256, ADJ_SMEM>>>(nfi, ti, tbv, oo);
    statsLA_k<<<256, 256>>>(oo, psS, psQ);
    statsC_k<256><<<64, 256>>>(psS, psQ, mn, is, 1.0 / ((double)kBP * 64));
    final_k<<<CDIV(kBS * 36 * 64 * 64, 256), 256>>>(oo, mn, is, bg, bb, out);
}

// round 17
// speedup vs baseline: 1.0879x; 1.0240x over previous
#include <cuda_runtime.h>
#include <cuda_bf16.h>
#include <math.h>

#define CDIV(a,b) (((a)+(b)-1)/(b))

// ---------------- problem dims ----------------
constexpr int kBS = 16, kN = 64;
constexpr int kB1 = kBS * kN;              // 1024 sequences
constexpr int kTC = 72, kBP = kBS * kTC;   // 1152 graph batches

// ---------------- scratch ----------------
__device__ __align__(16) uint2 g_xi [(size_t)kB1 * 256 * 32];   // [bn][s][p<32]
__device__ float g_c1[(size_t)kB1 * 256 * 256];
__device__ __align__(16) uint2 g_p1i[(size_t)kB1 * 129 * 128];
__device__ float g_c2[(size_t)kB1 * 131 * 128];
__device__ __align__(16) uint2 g_p2i[(size_t)kB1 * 66 * 64];
__device__ float g_c3[(size_t)kB1 * 70 * 256];
__device__ __align__(16) uint2 g_p3i[(size_t)kB1 * 4608];       // [bn][pair<4608]
__device__ __align__(16) uint2 g_nfi[(size_t)kBP * 64 * 64];    // [bp][n][pair<64]
__device__ float g_oo[(size_t)kBP * 64 * 64];
__device__ float g_mean[256];
__device__ float g_istd[256];
__device__ double g_psS[(size_t)256 * 4096];
__device__ double g_psQ[(size_t)256 * 4096];
__device__ __align__(16) uint2 g_w1i[3 * 256 * 32];
__device__ __align__(16) uint2 g_w2i[3 * 128 * 128];
__device__ __align__(16) uint2 g_w3i[3 * 256 * 64];
__device__ __align__(16) uint2 g_mwi[128 * 64];                 // mapW [out][pair]
__device__ __align__(16) uint2 g_ti [64 * 64];                  // theta [out][pair]

// ---------------- helpers ----------------
__device__ __forceinline__ void mma16816(float* c, const unsigned* a,
                                         unsigned b0, unsigned b1) {
    asm volatile(
        "mma.sync.aligned.m16n8k16.row.col.f32.bf16.bf16.f32 "
        "{%0,%1,%2,%3}, {%4,%5,%6,%7}, {%8,%9}, {%0,%1,%2,%3};"
        : "+f"(c[0]), "+f"(c[1]), "+f"(c[2]), "+f"(c[3])
        : "r"(a[0]), "r"(a[1]), "r"(a[2]), "r"(a[3]), "r"(b0), "r"(b1));
}

__device__ __forceinline__ uint2 pack_hl(float v0, float v1) {
    __nv_bfloat16 h0 = __float2bfloat16(v0);
    __nv_bfloat16 h1 = __float2bfloat16(v1);
    __nv_bfloat16 l0 = __float2bfloat16(v0 - __bfloat162float(h0));
    __nv_bfloat16 l1 = __float2bfloat16(v1 - __bfloat162float(h1));
    uint2 r;
    r.x = (unsigned)__bfloat16_as_ushort(h0) | ((unsigned)__bfloat16_as_ushort(h1) << 16);
    r.y = (unsigned)__bfloat16_as_ushort(l0) | ((unsigned)__bfloat16_as_ushort(l1) << 16);
    return r;
}

__device__ __forceinline__ void cp16(unsigned dst, const void* src, bool full) {
    int sz = full ? 16 : 0;
    asm volatile("cp.async.ca.shared.global [%0], [%1], 16, %2;"
                 :: "r"(dst), "l"(src), "r"(sz));
}
#define CP_COMMIT() asm volatile("cp.async.commit_group;")

// ---------------- prep: x[b,s,n,d] -> xi [bn][s][p], 4-way MLP ----------
__global__ void prep_x_k(const float* __restrict__ x, uint2* __restrict__ XI) {
    constexpr size_t total = (size_t)kB1 * 256 * 16;
    constexpr size_t S = total / 4;
    size_t t = (size_t)blockIdx.x * 256 + threadIdx.x;
    if (t >= S) return;
    float4 v[4];
#pragma unroll
    for (int it = 0; it < 4; it++) {
        size_t idx = t + (size_t)it * S;
        int q = idx & 15;
        int s = (idx >> 4) & 255;
        int bn = idx >> 12;
        int b = bn >> 6, n = bn & 63;
        v[it] = *(const float4*)&x[(((size_t)(b * 256 + s)) * 64 + n) * 64 + 4 * q];
    }
#pragma unroll
    for (int it = 0; it < 4; it++) {
        size_t idx = t + (size_t)it * S;
        uint2 p01 = pack_hl(v[it].x, v[it].y);
        uint2 p23 = pack_hl(v[it].z, v[it].w);
        ((uint4*)XI)[idx] = make_uint4(p01.x, p01.y, p23.x, p23.y);
    }
}

// ---------------- weight prep: W[co][ci][k] -> WI[k][co][p] ----------------
__global__ void prep_w_k(const float* __restrict__ W, uint2* __restrict__ WI,
                         int COUT, int CIN) {
    int idx = blockIdx.x * 256 + threadIdx.x;
    if (idx >= COUT * CIN / 2 * 3) return;
    int P = CIN / 2;
    int p = idx % P;
    int co = (idx / P) % COUT;
    int k = idx / (P * COUT);
    float v0 = W[((size_t)co * CIN + 2 * p) * 3 + k];
    float v1 = W[((size_t)co * CIN + 2 * p + 1) * 3 + k];
    WI[idx] = pack_hl(v0, v1);
}

// ---------------- graph weight prep: W[out][in] -> [out][pair] ---------------
__global__ void prep_gw_k(const float* __restrict__ W, uint2* __restrict__ WI,
                          int OUTD, int IND) {
    int idx = blockIdx.x * 256 + threadIdx.x;
    if (idx >= OUTD * IND / 2) return;
    int P = IND / 2;
    int o = idx / P, p = idx % P;
    WI[idx] = pack_hl(W[(size_t)o * IND + 2 * p], W[(size_t)o * IND + 2 * p + 1]);
}

// ---------------- conv1 special: full-W resident, X double-buffered ----------
// LTILE=128: 128 threads (4 warps = 2co x 2l), per-warp 32co x 64l (NN=8).
__global__ void __launch_bounds__(128, 2)
conv1_mma_k(const uint2* __restrict__ XI, const uint2* __restrict__ WI,
            float* __restrict__ Y,
            double* __restrict__ pS, double* __restrict__ pQ) {
    constexpr int COUT = 256, LIN = 256, LOUT = 256, PAD = 1, LTILE = 128;
    constexpr int WRS = 72, XRS = 40, XROWS = LTILE + 2 * PAD;   // 130
    constexpr int WTW = 192 * WRS;       // 13824 words
    constexpr int XTW = XROWS * XRS;     // 5200 words
    extern __shared__ unsigned dynsm[];
    int bn = blockIdx.x;
    int co0 = blockIdx.y * 64;
    int l0 = blockIdx.z * LTILE;
    int tid = threadIdx.x;
    int lane = tid & 31, wid = tid >> 5;
    int wco = wid & 1, wl = wid >> 1;
    int r4 = lane >> 2, c4 = lane & 3;

    unsigned smbase = (unsigned)__cvta_generic_to_shared(dynsm);

#pragma unroll
    for (int r = 0; r < 24; r++) {
        int i = r * 128 + tid;
        int row = i >> 4, cw = i & 15;
        int k = row >> 6, co = row & 63;
        const uint2* src = WI + ((size_t)(k * COUT + co0 + co)) * 32 + 2 * cw;
        cp16(smbase + (unsigned)(row * WRS + 4 * cw) * 4u, src, true);
    }
    CP_COMMIT();

    auto load_x = [&](int buf, int ci0) {
        unsigned xbase = smbase + (unsigned)(WTW + buf * XTW) * 4u;
#pragma unroll
        for (int r = 0; r < 9; r++) {
            int i = r * 128 + tid;
            if (i < XROWS * 8) {
                int row = i >> 3, cw = i & 7;
                int gl = l0 - PAD + row;
                bool ok = (gl >= 0 && gl < LIN);
                const uint2* src = ok ? XI + ((size_t)bn * LIN + gl) * 32
                                          + ci0 / 2 + 2 * cw
                                      : XI;
                cp16(xbase + (unsigned)(row * XRS + 4 * cw) * 4u, src, ok);
            }
        }
        CP_COMMIT();
    };

    float acc[2][8][4] = {};

    load_x(0, 0);
    for (int c = 0; c < 2; c++) {
        if (c == 0) {
            load_x(1, 32);
            asm volatile("cp.async.wait_group 1;");
        } else {
            asm volatile("cp.async.wait_group 0;");
        }
        __syncthreads();
        const unsigned* Ws = dynsm;
        const unsigned* Xs = dynsm + WTW + c * XTW;
#pragma unroll
        for (int k = 0; k < 3; k++) {
#pragma unroll
            for (int h = 0; h < 2; h++) {
                int pwb = 2 * (h * 8 + c4);
                int pwa = 32 * c + pwb;
                unsigned ah[2][4], al[2][4];
#pragma unroll
                for (int m = 0; m < 2; m++) {
                    int row = wco * 32 + m * 16 + r4;
                    int base = (k * 64 + row) * WRS + pwa;
                    uint2 a00 = *(const uint2*)&Ws[base];
                    uint2 a10 = *(const uint2*)&Ws[base + 8 * WRS];
                    uint2 a01 = *(const uint2*)&Ws[base + 8];
                    uint2 a11 = *(const uint2*)&Ws[base + 8 * WRS + 8];
                    ah[m][0] = a00.x; ah[m][1] = a10.x; ah[m][2] = a01.x; ah[m][3] = a11.x;
                    al[m][0] = a00.y; al[m][1] = a10.y; al[m][2] = a01.y; al[m][3] = a11.y;
                }
#pragma unroll
                for (int n = 0; n < 8; n++) {
                    int lrow = wl * 64 + n * 8 + r4 + k;
                    int bb = lrow * XRS + pwb;
                    uint2 b0 = *(const uint2*)&Xs[bb];
                    uint2 b1 = *(const uint2*)&Xs[bb + 8];
#pragma unroll
                    for (int m = 0; m < 2; m++) {
                        mma16816(acc[m][n], ah[m], b0.x, b1.x);
                        mma16816(acc[m][n], ah[m], b0.y, b1.y);
                        mma16816(acc[m][n], al[m], b0.x, b1.x);
                    }
                }
            }
        }
        __syncthreads();
    }

    float* redS = (float*)dynsm;
    float* redQ = redS + 128;
    float sacc[2][2] = {}, qacc[2][2] = {};
#pragma unroll
    for (int m = 0; m < 2; m++) {
        int co = co0 + wco * 32 + m * 16 + r4;
#pragma unroll
        for (int n = 0; n < 8; n++) {
            int l = l0 + wl * 64 + n * 8 + 2 * c4;
            float v0 = acc[m][n][0], v1 = acc[m][n][1];
            float v2 = acc[m][n][2], v3 = acc[m][n][3];
            Y[((size_t)bn * LOUT + l) * COUT + co] = v0;
            Y[((size_t)bn * LOUT + l) * COUT + co + 8] = v2;
            Y[((size_t)bn * LOUT + l + 1) * COUT + co] = v1;
            Y[((size_t)bn * LOUT + l + 1) * COUT + co + 8] = v3;
            sacc[m][0] += v0 + v1; qacc[m][0] += v0 * v0 + v1 * v1;
            sacc[m][1] += v2 + v3; qacc[m][1] += v2 * v2 + v3 * v3;
        }
    }
#pragma unroll
    for (int m = 0; m < 2; m++)
#pragma unroll
        for (int hh = 0; hh < 2; hh++) {
            float s = sacc[m][hh], q = qacc[m][hh];
            s += __shfl_xor_sync(0xFFFFFFFFu, s, 1);
            s += __shfl_xor_sync(0xFFFFFFFFu, s, 2);
            q += __shfl_xor_sync(0xFFFFFFFFu, q, 1);
            q += __shfl_xor_sync(0xFFFFFFFFu, q, 2);
            if (c4 == 0) {
                int ch = wco * 32 + m * 16 + r4 + 8 * hh;
                redS[wl * 64 + ch] = s;
                redQ[wl * 64 + ch] = q;
            }
        }
    __syncthreads();
    if (tid < 64) {
        double s = (double)redS[tid] + redS[64 + tid];
        double q = (double)redQ[tid] + redQ[64 + tid];
        int slot = bn * gridDim.z + blockIdx.z;
        pS[(size_t)(co0 + tid) * 4096 + slot] = s;
        pQ[(size_t)(co0 + tid) * 4096 + slot] = q;
    }
}

// ---------------- generic conv1d via HMMA, cp.async double-buffered ----------
template <int CIN, int LIN, int COUT, int LOUT, int PAD, int LTILE>
__global__ void __launch_bounds__(128, 2)
conv_mma_k(const uint2* __restrict__ XI,
           const uint2* __restrict__ WI,
           float* __restrict__ Y,
           double* __restrict__ pS, double* __restrict__ pQ) {
    constexpr int RS = 40;
    constexpr int NN = LTILE / 16;
    constexpr int XROWS = LTILE + 2 * PAD;
    constexpr int WTW = 192 * RS;
    constexpr int XTW = XROWS * RS;
    constexpr int NCHUNK = CIN / 32;
    constexpr int XCNT = CDIV(XROWS * 8, 128);
    extern __shared__ unsigned dynsm[];
    __shared__ float redS[2][64], redQ[2][64];
    int bn = blockIdx.x;
    int co0 = blockIdx.y * 64;
    int l0 = blockIdx.z * LTILE;
    int tid = threadIdx.x;
    int lane = tid & 31, wid = tid >> 5;
    int wco = wid & 1, wl = wid >> 1;
    int r4 = lane >> 2, c4 = lane & 3;

    unsigned smbase = (unsigned)__cvta_generic_to_shared(dynsm);
    auto wb = [&](int buf) { return smbase + (unsigned)(buf * (WTW + XTW)) * 4u; };
    auto xb = [&](int buf) { return wb(buf) + (unsigned)WTW * 4u; };

    auto load_chunk = [&](int buf, int ci0) {
        unsigned wbase = wb(buf), xbase = xb(buf);
#pragma unroll
        for (int r = 0; r < 12; r++) {
            int i = r * 128 + tid;
            int row = i >> 3, cw = i & 7;
            int k = row >> 6, co = row & 63;
            const uint2* src = WI + ((size_t)(k * COUT + co0 + co)) * (CIN / 2)
                               + ci0 / 2 + 2 * cw;
            cp16(wbase + (unsigned)(row * RS + 4 * cw) * 4u, src, true);
        }
#pragma unroll
        for (int r = 0; r < XCNT; r++) {
            int i = r * 128 + tid;
            if (i < XROWS * 8) {
                int row = i >> 3, cw = i & 7;
                int gl = l0 - PAD + row;
                bool ok = (gl >= 0 && gl < LIN);
                const uint2* src = ok ? XI + ((size_t)bn * LIN + gl) * (CIN / 2)
                                          + ci0 / 2 + 2 * cw
                                      : XI;
                cp16(xbase + (unsigned)(row * RS + 4 * cw) * 4u, src, ok);
            }
        }
        CP_COMMIT();
    };

    float acc[2][NN][4];
#pragma unroll
    for (int m = 0; m < 2; m++)
#pragma unroll
        for (int n = 0; n < NN; n++)
#pragma unroll
            for (int q = 0; q < 4; q++) acc[m][n][q] = 0.f;

    load_chunk(0, 0);
    for (int c = 0; c < NCHUNK; c++) {
        int cb = c & 1;
        if (c + 1 < NCHUNK) {
            load_chunk((c + 1) & 1, (c + 1) * 32);
            asm volatile("cp.async.wait_group 1;");
        } else {
            asm volatile("cp.async.wait_group 0;");
        }
        __syncthreads();

        const unsigned* Ws = dynsm + cb * (WTW + XTW);
        const unsigned* Xs = Ws + WTW;
#pragma unroll
        for (int k = 0; k < 3; k++) {
#pragma unroll
            for (int h = 0; h < 2; h++) {
                int pw = 2 * (h * 8 + c4);
                unsigned ah[2][4], al[2][4];
#pragma unroll
                for (int m = 0; m < 2; m++) {
                    int row = wco * 32 + m * 16 + r4;
                    int base = (k * 64 + row) * RS + pw;
                    uint2 a00 = *(const uint2*)&Ws[base];
                    uint2 a10 = *(const uint2*)&Ws[base + 8 * RS];
                    uint2 a01 = *(const uint2*)&Ws[base + 8];
                    uint2 a11 = *(const uint2*)&Ws[base + 8 * RS + 8];
                    ah[m][0] = a00.x; ah[m][1] = a10.x; ah[m][2] = a01.x; ah[m][3] = a11.x;
                    al[m][0] = a00.y; al[m][1] = a10.y; al[m][2] = a01.y; al[m][3] = a11.y;
                }
#pragma unroll
                for (int n = 0; n < NN; n++) {
                    int lrow = wl * (NN * 8) + n * 8 + r4 + k;
                    int bb = lrow * RS + pw;
                    uint2 b0 = *(const uint2*)&Xs[bb];
                    uint2 b1 = *(const uint2*)&Xs[bb + 8];
#pragma unroll
                    for (int m = 0; m < 2; m++) {
                        mma16816(acc[m][n], ah[m], b0.x, b1.x);
                        mma16816(acc[m][n], ah[m], b0.y, b1.y);
                        mma16816(acc[m][n], al[m], b0.x, b1.x);
                    }
                }
            }
        }
        __syncthreads();
    }

    float sacc[2][2] = {}, qacc[2][2] = {};
#pragma unroll
    for (int m = 0; m < 2; m++) {
        int co = co0 + wco * 32 + m * 16 + r4;
#pragma unroll
        for (int n = 0; n < NN; n++) {
            int l = l0 + wl * (NN * 8) + n * 8 + 2 * c4;
            if (l < LOUT) {
                float v0 = acc[m][n][0], v2 = acc[m][n][2];
                Y[((size_t)bn * LOUT + l) * COUT + co] = v0;
                Y[((size_t)bn * LOUT + l) * COUT + co + 8] = v2;
                sacc[m][0] += v0; qacc[m][0] += v0 * v0;
                sacc[m][1] += v2; qacc[m][1] += v2 * v2;
            }
            if (l + 1 < LOUT) {
                float v1 = acc[m][n][1], v3 = acc[m][n][3];
                Y[((size_t)bn * LOUT + l + 1) * COUT + co] = v1;
                Y[((size_t)bn * LOUT + l + 1) * COUT + co + 8] = v3;
                sacc[m][0] += v1; qacc[m][0] += v1 * v1;
                sacc[m][1] += v3; qacc[m][1] += v3 * v3;
            }
        }
    }
#pragma unroll
    for (int m = 0; m < 2; m++)
#pragma unroll
        for (int hh = 0; hh < 2; hh++) {
            float s = sacc[m][hh], q = qacc[m][hh];
            s += __shfl_xor_sync(0xFFFFFFFFu, s, 1);
            s += __shfl_xor_sync(0xFFFFFFFFu, s, 2);
            q += __shfl_xor_sync(0xFFFFFFFFu, q, 1);
            q += __shfl_xor_sync(0xFFFFFFFFu, q, 2);
            if (c4 == 0) {
                int ch = wco * 32 + m * 16 + r4 + 8 * hh;
                redS[wl][ch] = s;
                redQ[wl][ch] = q;
            }
        }
    __syncthreads();
    if (tid < 64) {
        double s = (double)redS[0][tid] + redS[1][tid];
        double q = (double)redQ[0][tid] + redQ[1][tid];
        int slot = bn * gridDim.z + blockIdx.z;
        pS[(size_t)(co0 + tid) * 4096 + slot] = s;
        pQ[(size_t)(co0 + tid) * 4096 + slot] = q;
    }
}

// ---------------- BN stats finish ----------------
template <int NS>
__global__ void statsC_k(const double* __restrict__ pS, const double* __restrict__ pQ,
                         float* __restrict__ mean, float* __restrict__ istd,
                         double inv_total) {
    int c = blockIdx.x, tid = threadIdx.x;
    double s = 0.0, q = 0.0;
    for (int i = tid; i < NS; i += 256) {
        s += pS[(size_t)c * 4096 + i];
        q += pQ[(size_t)c * 4096 + i];
    }
    __shared__ double ss[256], qs[256];
    ss[tid] = s; qs[tid] = q;
    __syncthreads();
    for (int o = 128; o > 0; o >>= 1) {
        if (tid < o) { ss[tid] += ss[tid + o]; qs[tid] += qs[tid + o]; }
        __syncthreads();
    }
    if (tid == 0) {
        double m = ss[0] * inv_total;
        double var = qs[0] * inv_total - m * m;
        mean[c] = (float)m;
        istd[c] = rsqrtf((float)var + 1e-5f);
    }
}

// ---------------- fused BN + ReLU + maxpool, 4-way MLP -----------------------
template <int C, int Lout, int Lp>
__global__ void bnpool_k(const float* __restrict__ X, uint2* __restrict__ YI,
                         const float* __restrict__ mean, const float* __restrict__ istd,
                         const float* __restrict__ gam, const float* __restrict__ bet) {
    constexpr int P4 = C / 4;
    constexpr size_t total = (size_t)kB1 * Lp * P4;
    constexpr size_t S = (total + 3) / 4;
    size_t t = (size_t)blockIdx.x * 256 + threadIdx.x;
    if (t >= S) return;
#pragma unroll
    for (int it = 0; it < 4; it++) {
        size_t idx = t + (size_t)it * S;
        if (idx >= total) continue;
        int p4 = idx % P4;
        int j = (idx / P4) % Lp;
        int bn = idx / ((size_t)P4 * Lp);
        int c0 = 4 * p4;
        float sc[4], sh[4], m[4] = {0.f, 0.f, 0.f, 0.f};
#pragma unroll
        for (int e = 0; e < 4; e++) {
            sc[e] = istd[c0 + e] * gam[c0 + e];
            sh[e] = bet[c0 + e] - mean[c0 + e] * sc[e];
        }
        int l0 = 2 * j - 1, l1 = 2 * j;
        if (l0 >= 0) {
            float4 v = *(const float4*)&X[((size_t)bn * Lout + l0) * C + c0];
            float w[4] = {v.x, v.y, v.z, v.w};
#pragma unroll
            for (int e = 0; e < 4; e++) { float a = fmaf(w[e], sc[e], sh[e]); if (a > m[e]) m[e] = a; }
        }
        if (l1 < Lout) {
            float4 v = *(const float4*)&X[((size_t)bn * Lout + l1) * C + c0];
            float w[4] = {v.x, v.y, v.z, v.w};
#pragma unroll
            for (int e = 0; e < 4; e++) { float a = fmaf(w[e], sc[e], sh[e]); if (a > m[e]) m[e] = a; }
        }
        uint2 p01 = pack_hl(m[0], m[1]);
        uint2 p23 = pack_hl(m[2], m[3]);
        ((uint4*)YI)[idx] = make_uint4(p01.x, p01.y, p23.x, p23.y);
    }
}

// ---------------- bnpool stage 3 -> flat pairs, 4-way MLP --------------------
__global__ void bnpool3_k(const float* __restrict__ X,   // [bn][70][256]
                          uint2* __restrict__ YI,        // [bn][4608]
                          const float* __restrict__ mean, const float* __restrict__ istd,
                          const float* __restrict__ gam, const float* __restrict__ bet) {
    constexpr size_t total = (size_t)kB1 * 4608;
    constexpr size_t S = total / 4;
    size_t t = (size_t)blockIdx.x * 256 + threadIdx.x;
    if (t >= S) return;
#pragma unroll
    for (int it = 0; it < 4; it++) {
        size_t idx = t + (size_t)it * S;
        int pr = idx % 4608;
        int bn = idx / 4608;
        float vv[2];
#pragma unroll
        for (int e = 0; e < 2; e++) {
            int el = 2 * pr + e;
            int c = el / 36, l = el - c * 36;
            float sc = istd[c] * gam[c];
            float sh = bet[c] - mean[c] * sc;
            float m = 0.f;
            int l0 = 2 * l - 1, l1 = 2 * l;
            if (l0 >= 0) { float v = fmaf(X[((size_t)bn * 70 + l0) * 256 + c], sc, sh); if (v > m) m = v; }
            if (l1 < 70) { float v = fmaf(X[((size_t)bn * 70 + l1) * 256 + c], sc, sh); if (v > m) m = v; }
            vv[e] = m;
        }
        YI[idx] = pack_hl(vv[0], vv[1]);
    }
}

// ---------------- nf via HMMA: nf = spa @ mapW^T + mb, split to bf16 ---------
__global__ void __launch_bounds__(256) nf_mma_k(const uint2* __restrict__ P3I,
                                                const uint2* __restrict__ MWI,
                                                const float* __restrict__ MB,
                                                uint2* __restrict__ NFI) {
    extern __shared__ unsigned sm[];
    unsigned* spaW = sm;                 // [64][136 words]
    unsigned* mwW  = sm + 64 * 136;      // [128][136 words]
    int bp = blockIdx.x;
    int b = bp / kTC, tc = bp % kTC;
    int tid = threadIdx.x;
    unsigned smb = (unsigned)__cvta_generic_to_shared(sm);
#pragma unroll
    for (int r = 0; r < 8; r++) {
        int i = r * 256 + tid;
        int row = i >> 5, cw = i & 31;
        const uint2* src = P3I + (size_t)(b * kN + row) * 4608 + tc * 64 + 2 * cw;
        cp16(smb + (unsigned)(row * 136 + 4 * cw) * 4u, src, true);
    }
#pragma unroll
    for (int r = 0; r < 16; r++) {
        int i = r * 256 + tid;
        int row = i >> 5, cw = i & 31;
        const uint2* src = MWI + (size_t)row * 64 + 2 * cw;
        cp16(smb + (unsigned)(64 * 136 + row * 136 + 4 * cw) * 4u, src, true);
    }
    CP_COMMIT();
    asm volatile("cp.async.wait_group 0;");
    __syncthreads();

    int lane = tid & 31, wid = tid >> 5;
    int band = wid >> 1, half = wid & 1;
    int r4 = lane >> 2, c4 = lane & 3;
    float acc[8][4] = {};
#pragma unroll
    for (int kk = 0; kk < 8; kk++) {
        int arow = band * 16 + r4;
        uint2 a0 = *(const uint2*)&spaW[arow * 136 + (kk * 8 + c4) * 2];
        uint2 a1 = *(const uint2*)&spaW[(arow + 8) * 136 + (kk * 8 + c4) * 2];
        uint2 a2 = *(const uint2*)&spaW[arow * 136 + (kk * 8 + c4 + 4) * 2];
        uint2 a3 = *(const uint2*)&spaW[(arow + 8) * 136 + (kk * 8 + c4 + 4) * 2];
        unsigned ah[4] = {a0.x, a1.x, a2.x, a3.x};
        unsigned al[4] = {a0.y, a1.y, a2.y, a3.y};
#pragma unroll
        for (int f = 0; f < 8; f++) {
            int nrow = half * 64 + f * 8 + r4;
            uint2 b0 = *(const uint2*)&mwW[nrow * 136 + (kk * 8 + c4) * 2];
            uint2 b1 = *(const uint2*)&mwW[nrow * 136 + (kk * 8 + c4 + 4) * 2];
            mma16816(acc[f], ah, b0.x, b1.x);
            mma16816(acc[f], ah, b0.y, b1.y);
            mma16816(acc[f], al, b0.x, b1.x);
        }
    }
#pragma unroll
    for (int f = 0; f < 8; f++) {
        int col = half * 64 + f * 8 + 2 * c4;
        float m0 = MB[col], m1 = MB[col + 1];
        int row = band * 16 + r4;
        NFI[((size_t)bp * 64 + row) * 64 + col / 2] = pack_hl(acc[f][0] + m0, acc[f][1] + m1);
        NFI[((size_t)bp * 64 + row + 8) * 64 + col / 2] = pack_hl(acc[f][2] + m0, acc[f][3] + m1);
    }
}

// ---------------- adj via HMMA: gram + theta-map + softmax + aggregate -------
__global__ void __launch_bounds__(256) adj_mma_k(const uint2* __restrict__ NFI,
                                                 const uint2* __restrict__ TI,
                                                 const float* __restrict__ TB,
                                                 float* __restrict__ OUT) {
    extern __shared__ unsigned sm[];
    unsigned* nfW = sm;                           // [64][136 words]
    unsigned* thW = sm + 64 * 136;                // [64][136 words]
    float*    Af  = (float*)(sm + 2 * 64 * 136);  // [64][66] fp32
    unsigned* m2W = sm + 2 * 64 * 136 + 64 * 66;  // M2^T bf16 [o:64][72 words]
    unsigned* apW = m2W + 64 * 72;                // A' bf16 [n:64][72 words]
    int bp = blockIdx.x;
    int tid = threadIdx.x;
    unsigned smb = (unsigned)__cvta_generic_to_shared(sm);
#pragma unroll
    for (int r = 0; r < 8; r++) {
        int i = r * 256 + tid;
        int row = i >> 5, cw = i & 31;
        cp16(smb + (unsigned)(row * 136 + 4 * cw) * 4u,
             NFI + (size_t)bp * 4096 + row * 64 + 2 * cw, true);
    }
#pragma unroll
    for (int r = 0; r < 8; r++) {
        int i = r * 256 + tid;
        int row = i >> 5, cw = i & 31;
        cp16(smb + (unsigned)(64 * 136 + row * 136 + 4 * cw) * 4u,
             TI + (size_t)row * 64 + 2 * cw, true);
    }
    CP_COMMIT();
    asm volatile("cp.async.wait_group 0;");
    __syncthreads();

    int lane = tid & 31, wid = tid >> 5;
    int band = wid >> 1, half = wid & 1;
    int r4 = lane >> 2, c4 = lane & 3;

    {   // stage 1: A = nf@nf^T, M2 = nf@theta^T   (K=128)
        float ag[4][4] = {}, am[4][4] = {};
#pragma unroll
        for (int kk = 0; kk < 8; kk++) {
            int arow = band * 16 + r4;
            uint2 a0 = *(const uint2*)&nfW[arow * 136 + (kk * 8 + c4) * 2];
            uint2 a1 = *(const uint2*)&nfW[(arow + 8) * 136 + (kk * 8 + c4) * 2];
            uint2 a2 = *(const uint2*)&nfW[arow * 136 + (kk * 8 + c4 + 4) * 2];
            uint2 a3 = *(const uint2*)&nfW[(arow + 8) * 136 + (kk * 8 + c4 + 4) * 2];
            unsigned ah[4] = {a0.x, a1.x, a2.x, a3.x};
            unsigned al[4] = {a0.y, a1.y, a2.y, a3.y};
#pragma unroll
            for (int f = 0; f < 4; f++) {
                int nrow = half * 32 + f * 8 + r4;
                uint2 g0 = *(const uint2*)&nfW[nrow * 136 + (kk * 8 + c4) * 2];
                uint2 g1 = *(const uint2*)&nfW[nrow * 136 + (kk * 8 + c4 + 4) * 2];
                mma16816(ag[f], ah, g0.x, g1.x);
                mma16816(ag[f], ah, g0.y, g1.y);
                mma16816(ag[f], al, g0.x, g1.x);
                uint2 t0 = *(const uint2*)&thW[nrow * 136 + (kk * 8 + c4) * 2];
                uint2 t1 = *(const uint2*)&thW[nrow * 136 + (kk * 8 + c4 + 4) * 2];
                mma16816(am[f], ah, t0.x, t1.x);
                mma16816(am[f], ah, t0.y, t1.y);
                mma16816(am[f], al, t0.x, t1.x);
            }
        }
        __nv_bfloat16* m2h = (__nv_bfloat16*)m2W;
#pragma unroll
        for (int f = 0; f < 4; f++) {
            int col = half * 32 + f * 8 + 2 * c4;
#pragma unroll
            for (int q = 0; q < 4; q++) {
                int row = band * 16 + r4 + (q >> 1) * 8;
                int cc = col + (q & 1);
                float v = ag[f][q];
                Af[row * 66 + cc] = v;
                float vm = am[f][q];
                __nv_bfloat16 h = __float2bfloat16(vm);
                __nv_bfloat16 l = __float2bfloat16(vm - __bfloat162float(h));
                int wbase = cc * 72 + (row >> 1) * 2;
                m2h[wbase * 2 + (row & 1)] = h;
                m2h[(wbase + 1) * 2 + (row & 1)] = l;
            }
        }
    }
    __syncthreads();
    {   // stage 2: softmax rows of A
        int row = tid >> 2;
        int part = tid & 3;
        float vals[16];
        float mx = -3.4e38f;
#pragma unroll
        for (int jj = 0; jj < 16; jj++) {
            int col = part * 16 + jj;
            float v = Af[row * 66 + col];
            if (col == row) v -= 1e8f;
            v = v > 0.f ? v : 0.01f * v;
            vals[jj] = v;
            mx = fmaxf(mx, v);
        }
        mx = fmaxf(mx, __shfl_xor_sync(0xFFFFFFFFu, mx, 1));
        mx = fmaxf(mx, __shfl_xor_sync(0xFFFFFFFFu, mx, 2));
        float s = 0.f;
#pragma unroll
        for (int jj = 0; jj < 16; jj++) { vals[jj] = expf(vals[jj] - mx); s += vals[jj]; }
        s += __shfl_xor_sync(0xFFFFFFFFu, s, 1);
        s += __shfl_xor_sync(0xFFFFFFFFu, s, 2);
        float inv = 1.f / s;
#pragma unroll
        for (int j = 0; j < 8; j++) {
            int col = part * 16 + 2 * j;
            float v0 = vals[2 * j] * inv;
            float v1 = vals[2 * j + 1] * inv;
            if (col == row) v0 += 1.f;
            if (col + 1 == row) v1 += 1.f;
            *(uint2*)&apW[(row * 36 + part * 8 + j) * 2] = pack_hl(v0, v1);
        }
    }
    __syncthreads();
    {   // stage 3: out = A' @ M2 + tb   (K=64)
        float acc[4][4] = {};
#pragma unroll
        for (int kk = 0; kk < 4; kk++) {
            int arow = band * 16 + r4;
            uint2 a0 = *(const uint2*)&apW[arow * 72 + (kk * 8 + c4) * 2];
            uint2 a1 = *(const uint2*)&apW[(arow + 8) * 72 + (kk * 8 + c4) * 2];
            uint2 a2 = *(const uint2*)&apW[arow * 72 + (kk * 8 + c4 + 4) * 2];
            uint2 a3 = *(const uint2*)&apW[(arow + 8) * 72 + (kk * 8 + c4 + 4) * 2];
            unsigned ah[4] = {a0.x, a1.x, a2.x, a3.x};
            unsigned al[4] = {a0.y, a1.y, a2.y, a3.y};
#pragma unroll
            for (int f = 0; f < 4; f++) {
                int orow = half * 32 + f * 8 + r4;
                uint2 b0 = *(const uint2*)&m2W[orow * 72 + (kk * 8 + c4) * 2];
                uint2 b1 = *(const uint2*)&m2W[orow * 72 + (kk * 8 + c4 + 4) * 2];
                mma16816(acc[f], ah, b0.x, b1.x);
                mma16816(acc[f], ah, b0.y, b1.y);
                mma16816(acc[f], al, b0.x, b1.x);
            }
        }
#pragma unroll
        for (int f = 0; f < 4; f++) {
            int col = half * 32 + f * 8 + 2 * c4;
            float t0 = TB[col], t1 = TB[col + 1];
            int row = band * 16 + r4;
            OUT[((size_t)bp * 64 + row) * 64 + col] = acc[f][0] + t0;
            OUT[((size_t)bp * 64 + row) * 64 + col + 1] = acc[f][1] + t1;
            OUT[((size_t)bp * 64 + row + 8) * 64 + col] = acc[f][2] + t0;
            OUT[((size_t)bp * 64 + row + 8) * 64 + col + 1] = acc[f][3] + t1;
        }
    }
}

// ---------------- final BN stats, two-stage: stage A (256 chunks) ------------
__global__ void statsLA_k(const float* __restrict__ X,   // [M][64]
                          double* __restrict__ pS, double* __restrict__ pQ) {
    constexpr int M = kBP * 64;             // 73728 rows
    constexpr int RPC = M / 256;            // 288 rows per chunk
    int chunk = blockIdx.x;
    int tid = threadIdx.x;
    int c = tid & 63;                       // channel
    int rs = tid >> 6;                      // row-subgroup 0..3
    double q = 0.0, sd = 0.0;
    for (int r = rs; r < RPC; r += 4) {
        float v = X[(size_t)(chunk * RPC + r) * 64 + c];
        sd += v;
        q += (double)v * v;
    }
    __shared__ double ss[256], qs[256];
    ss[tid] = sd; qs[tid] = q;
    __syncthreads();
    if (tid < 128) { ss[tid] += ss[tid + 128]; qs[tid] += qs[tid + 128]; }
    __syncthreads();
    if (tid < 64) {
        pS[(size_t)tid * 4096 + chunk] = ss[tid] + ss[tid + 64];
        pQ[(size_t)tid * 4096 + chunk] = qs[tid] + qs[tid + 64];
    }
}

// ---------------- final: BN + leaky + pair-mean ----------------
__global__ void final_k(const float* __restrict__ Xo,
                        const float* __restrict__ mean, const float* __restrict__ istd,
                        const float* __restrict__ gam, const float* __restrict__ bet,
                        float* __restrict__ Y) {
    int idx = blockIdx.x * 256 + threadIdx.x;
    if (idx >= kBS * 36 * 64 * 64) return;
    int o = idx & 63;
    int n = (idx >> 6) & 63;
    int w = (idx >> 12) % 36;
    int b = idx / (36 * 4096);
    float sc = istd[o] * gam[o];
    float sh = bet[o] - mean[o] * sc;
    float acc = 0.f;
#pragma unroll
    for (int e = 0; e < 2; e++) {
        float v = fmaf(Xo[(((size_t)(b * kTC + 2 * w + e)) * 64 + n) * 64 + o], sc, sh);
        acc += (v > 0.f ? v : 0.01f * v);
    }
    Y[idx] = 0.5f * acc;
}

// ---------------- launch ----------------
extern "C" void kernel_launch(void* const* d_in, const int* in_sizes, int n_in,
                              void* d_out, int out_size) {
    const float* x   = (const float*)d_in[0];
    const float* w1  = (const float*)d_in[1];
    const float* g1  = (const float*)d_in[2];
    const float* b1  = (const float*)d_in[3];
    const float* w2  = (const float*)d_in[4];
    const float* g2  = (const float*)d_in[5];
    const float* b2  = (const float*)d_in[6];
    const float* w3  = (const float*)d_in[7];
    const float* g3  = (const float*)d_in[8];
    const float* b3  = (const float*)d_in[9];
    const float* mw  = (const float*)d_in[10];
    const float* mb  = (const float*)d_in[11];
    const float* tw  = (const float*)d_in[12];
    const float* tbv = (const float*)d_in[13];
    const float* bg  = (const float*)d_in[14];
    const float* bb  = (const float*)d_in[15];
    float* out = (float*)d_out;

    uint2 *xi, *p1i, *p2i, *p3i, *nfi, *w1i, *w2i, *w3i, *mwi, *ti;
    float *c1, *c2, *c3, *oo, *mn, *is;
    double *psS, *psQ;
    cudaGetSymbolAddress((void**)&xi, g_xi);
    cudaGetSymbolAddress((void**)&c1, g_c1);
    cudaGetSymbolAddress((void**)&p1i, g_p1i);
    cudaGetSymbolAddress((void**)&c2, g_c2);
    cudaGetSymbolAddress((void**)&p2i, g_p2i);
    cudaGetSymbolAddress((void**)&c3, g_c3);
    cudaGetSymbolAddress((void**)&p3i, g_p3i);
    cudaGetSymbolAddress((void**)&nfi, g_nfi);
    cudaGetSymbolAddress((void**)&oo, g_oo);
    cudaGetSymbolAddress((void**)&mn, g_mean);
    cudaGetSymbolAddress((void**)&is, g_istd);
    cudaGetSymbolAddress((void**)&psS, g_psS);
    cudaGetSymbolAddress((void**)&psQ, g_psQ);
    cudaGetSymbolAddress((void**)&w1i, g_w1i);
    cudaGetSymbolAddress((void**)&w2i, g_w2i);
    cudaGetSymbolAddress((void**)&w3i, g_w3i);
    cudaGetSymbolAddress((void**)&mwi, g_mwi);
    cudaGetSymbolAddress((void**)&ti, g_ti);

    const int C1_SMEM = (192 * 72 + 2 * 130 * 40) * 4;           // 96896 B
    const int C2_SMEM = 2 * (192 * 40 + 148 * 40) * 4;           // 108800 B
    const int C3_SMEM = 2 * (192 * 40 + 86 * 40) * 4;            // 88960 B
    const int NF_SMEM  = (64 + 128) * 136 * 4;                   // 104448 B
    const int ADJ_SMEM = (2 * 64 * 136 + 64 * 66 + 2 * 64 * 72) * 4;  // 123392 B
    cudaFuncSetAttribute(conv1_mma_k,
                         cudaFuncAttributeMaxDynamicSharedMemorySize, C1_SMEM);
    cudaFuncSetAttribute(conv_mma_k<256, 129, 128, 131, 2, 144>,
                         cudaFuncAttributeMaxDynamicSharedMemorySize, C2_SMEM);
    cudaFuncSetAttribute(conv_mma_k<128, 66, 256, 70, 3, 80>,
                         cudaFuncAttributeMaxDynamicSharedMemorySize, C3_SMEM);
    cudaFuncSetAttribute(nf_mma_k, cudaFuncAttributeMaxDynamicSharedMemorySize, NF_SMEM);
    cudaFuncSetAttribute(adj_mma_k, cudaFuncAttributeMaxDynamicSharedMemorySize, ADJ_SMEM);

    // launch order: conv1 at index 3 (ncu-profiled slot)
    prep_x_k<<<CDIV(kB1 * 256 * 16 / 4, 256), 256>>>(x, xi);                   // 0
    prep_w_k<<<CDIV(3 * 256 * 32, 256), 256>>>(w1, w1i, 256, 64);              // 1
    prep_w_k<<<CDIV(3 * 256 * 64, 256), 256>>>(w3, w3i, 256, 128);             // 2

    conv1_mma_k<<<dim3(kB1, 4, 2), 128, C1_SMEM>>>(xi, w1i, c1, psS, psQ);     // 3
    statsC_k<kB1 * 2><<<256, 256>>>(psS, psQ, mn, is, 1.0 / ((double)kB1 * 256));
    prep_w_k<<<CDIV(3 * 128 * 128, 256), 256>>>(w2, w2i, 128, 256);
    bnpool_k<256, 256, 129><<<CDIV(CDIV(kB1 * 129 * 64, 4), 256), 256>>>(c1, p1i, mn, is, g1, b1);

    conv_mma_k<256, 129, 128, 131, 2, 144>
        <<<dim3(kB1, 2, 1), 128, C2_SMEM>>>(p1i, w2i, c2, psS, psQ);
    statsC_k<kB1><<<128, 256>>>(psS, psQ, mn, is, 1.0 / ((double)kB1 * 131));
    bnpool_k<128, 131, 66><<<CDIV(CDIV(kB1 * 66 * 32, 4), 256), 256>>>(c2, p2i, mn, is, g2, b2);

    conv_mma_k<128, 66, 256, 70, 3, 80>
        <<<dim3(kB1, 4, 1), 128, C3_SMEM>>>(p2i, w3i, c3, psS, psQ);
    statsC_k<kB1><<<256, 256>>>(psS, psQ, mn, is, 1.0 / ((double)kB1 * 70));
    bnpool3_k<<<CDIV(kB1 * 4608 / 4, 256), 256>>>(c3, p3i, mn, is, g3, b3);

    // graph part (HMMA)
    prep_gw_k<<<CDIV(128 * 64, 256), 256>>>(mw, mwi, 128, 128);
    prep_gw_k<<<CDIV(64 * 64, 256), 256>>>(tw, ti, 64, 128);
    nf_mma_k<<<kBP, 256, NF_SMEM>>>(p3i, mwi, mb, nfi);
    adj_mma_k<<<kBP, 256, ADJ_SMEM>>>(nfi, ti, tbv, oo);
    statsLA_k<<<256, 256>>>(oo, psS, psQ);
    statsC_k<256><<<64, 256>>>(psS, psQ, mn, is, 1.0 / ((double)kBP * 64));
    final_k<<<CDIV(kBS * 36 * 64 * 64, 256), 256>>>(oo, mn, is, bg, bb, out);
}